// round 3
// baseline (speedup 1.0000x reference)
#include <cuda_runtime.h>
#include <math.h>
#include <float.h>

#define BB 8
#define NNP 4096
#define SSP 512
#define KKN 32
#define EPSV 1e-5f

// scratch (__device__ globals — no allocation allowed)
__device__ float g_x[BB*SSP*KKN*128];      // x = [pos|pts]  [B,S,K,128]
__device__ float g_dsa[BB*SSP*KKN*256];    // [nei|grp]      [B,S,K,256]
__device__ float g_h[BB*SSP*KKN*256];      // hidden         [B*S*K,256]
__device__ float g_G[BB*SSP*SSP];          // GAM attention
__device__ int   g_knn[BB*SSP*KKN];
__device__ float g_knnd[BB*SSP*KKN];

// ---------------- 1. FPS ----------------
__global__ void __launch_bounds__(512) fps_kernel(const float* __restrict__ xyz,
                                                  const int* __restrict__ start,
                                                  float* __restrict__ centers) {
    extern __shared__ float sh[];
    float *sx = sh, *sy = sh + NNP, *sz = sh + 2*NNP;
    __shared__ float rv[16]; __shared__ int ri[16]; __shared__ int sfar;
    int b = blockIdx.x, tid = threadIdx.x;
    for (int i = tid; i < NNP; i += 512) {
        const float* p = xyz + ((size_t)b*NNP + i)*3;
        sx[i] = p[0]; sy[i] = p[1]; sz[i] = p[2];
    }
    float dist[8];
#pragma unroll
    for (int i = 0; i < 8; i++) dist[i] = 1e10f;
    __syncthreads();
    int far = start[b];
    for (int t = 0; t < SSP; t++) {
        float cx = sx[far], cy = sy[far], cz = sz[far];
        if (tid == 0) {
            float* o = centers + ((size_t)b*SSP + t)*3;
            o[0] = cx; o[1] = cy; o[2] = cz;
        }
        float bv = -1.0f; int bi = 0;
#pragma unroll
        for (int i = 0; i < 8; i++) {
            int p = tid + i*512;
            float dx = sx[p]-cx, dy = sy[p]-cy, dz = sz[p]-cz;
            float d = fminf(dist[i], dx*dx + dy*dy + dz*dz);
            dist[i] = d;
            if (d > bv) { bv = d; bi = p; }
        }
#pragma unroll
        for (int off = 16; off > 0; off >>= 1) {
            float ov = __shfl_down_sync(0xffffffffu, bv, off);
            int   oi = __shfl_down_sync(0xffffffffu, bi, off);
            if (ov > bv || (ov == bv && oi < bi)) { bv = ov; bi = oi; }
        }
        if ((tid & 31) == 0) { rv[tid>>5] = bv; ri[tid>>5] = bi; }
        __syncthreads();
        if (tid == 0) {
            float gv = rv[0]; int gi = ri[0];
#pragma unroll
            for (int w = 1; w < 16; w++)
                if (rv[w] > gv || (rv[w] == gv && ri[w] < gi)) { gv = rv[w]; gi = ri[w]; }
            sfar = gi;
        }
        __syncthreads();
        far = sfar;
    }
}

// ---------------- 2. KNN ----------------
__global__ void __launch_bounds__(128) knn_kernel(const float* __restrict__ xyz,
                                                  const float* __restrict__ centers) {
    __shared__ float sd2[KKN*128];
    __shared__ float swv[4]; __shared__ int swi[4];
    int s = blockIdx.x, b = blockIdx.y, tid = threadIdx.x;
    const float* c = centers + ((size_t)b*SSP + s)*3;
    float cx = c[0], cy = c[1], cz = c[2];
    float cn2 = cx*cx + cy*cy + cz*cz;
    float lv = FLT_MAX; int li = 0x7fffffff; int lslot = 0;
#pragma unroll
    for (int i = 0; i < KKN; i++) {
        int p = tid + i*128;
        const float* pp = xyz + ((size_t)b*NNP + p)*3;
        float px = pp[0], py = pp[1], pz = pp[2];
        float d2 = cn2 + (px*px + py*py + pz*pz) - 2.0f*(cx*px + cy*py + cz*pz);
        sd2[i*128 + tid] = d2;
        if (d2 < lv) { lv = d2; li = p; lslot = i; }
    }
    int lane = tid & 31, warp = tid >> 5;
    int obase = (b*SSP + s)*KKN;
    for (int r = 0; r < KKN; r++) {
        float bv = lv; int bi = li;
#pragma unroll
        for (int off = 16; off > 0; off >>= 1) {
            float ov = __shfl_xor_sync(0xffffffffu, bv, off);
            int   oi = __shfl_xor_sync(0xffffffffu, bi, off);
            if (ov < bv || (ov == bv && oi < bi)) { bv = ov; bi = oi; }
        }
        if (lane == 0) { swv[warp] = bv; swi[warp] = bi; }
        __syncthreads();
        float gv = swv[0]; int gi = swi[0];
#pragma unroll
        for (int w = 1; w < 4; w++)
            if (swv[w] < gv || (swv[w] == gv && swi[w] < gi)) { gv = swv[w]; gi = swi[w]; }
        if (tid == 0) { g_knn[obase + r] = gi; g_knnd[obase + r] = gv; }
        if (gi == li) {
            sd2[lslot*128 + tid] = FLT_MAX;
            lv = FLT_MAX; li = 0x7fffffff; lslot = 0;
#pragma unroll
            for (int i = 0; i < KKN; i++) {
                float d = sd2[i*128 + tid];
                if (d < lv) { lv = d; li = tid + i*128; lslot = i; }
            }
        }
        __syncthreads();
    }
}

// ---------------- 3. group + pos-embed MLP ----------------
__global__ void __launch_bounds__(256) grouppos_kernel(
    const float* __restrict__ xyz, const float* __restrict__ points,
    const float* __restrict__ centers,
    const float* __restrict__ w1, const float* __restrict__ b1, const float* __restrict__ bn1,
    const float* __restrict__ w2, const float* __restrict__ b2, const float* __restrict__ bn2) {
    __shared__ float sw1[320], sw2[2048];
    __shared__ float sA1[32], sC1[32], sA2[64], sC2[64];
    int tid = threadIdx.x;
    for (int i = tid; i < 320; i += 256) sw1[i] = w1[i];
    for (int i = tid; i < 2048; i += 256) sw2[i] = w2[i];
    if (tid < 32) {
        float a = bn1[tid] * rsqrtf(bn1[96+tid] + EPSV);
        sA1[tid] = a; sC1[tid] = a*(b1[tid]-bn1[64+tid]) + bn1[32+tid];
    }
    if (tid < 64) {
        float a = bn2[tid] * rsqrtf(bn2[192+tid] + EPSV);
        sA2[tid] = a; sC2[tid] = a*(b2[tid]-bn2[128+tid]) + bn2[64+tid];
    }
    __syncthreads();
    int gid = blockIdx.x*256 + tid;          // (b*512+s)*32+k
    int b = gid >> 14;
    int idx = g_knn[gid];
    float dd = g_knnd[gid];
    const float* c = centers + (size_t)(gid >> 5)*3;
    float cx = c[0], cy = c[1], cz = c[2];
    const float* pp = xyz + ((size_t)b*NNP + idx)*3;
    float px = pp[0], py = pp[1], pz = pp[2];
    float f[10] = {cx, cy, cz, px, py, pz, px-cx, py-cy, pz-cz, dd};
    float h[32];
#pragma unroll
    for (int cc = 0; cc < 32; cc++) {
        float acc = 0.f;
#pragma unroll
        for (int i = 0; i < 10; i++) acc += f[i]*sw1[i*32+cc];
        h[cc] = fmaxf(acc*sA1[cc] + sC1[cc], 0.f);
    }
    float* xo = g_x + (size_t)gid*128;
#pragma unroll
    for (int cc = 0; cc < 64; cc++) {
        float acc = 0.f;
#pragma unroll
        for (int i = 0; i < 32; i++) acc += h[i]*sw2[i*64+cc];
        xo[cc] = fmaxf(acc*sA2[cc] + sC2[cc], 0.f);
    }
    const float* pr = points + ((size_t)b*NNP + idx)*64;
#pragma unroll
    for (int j = 0; j < 64; j += 4)
        *(float4*)(xo + 64 + j) = *(const float4*)(pr + j);
}

// ---------------- 4. neighbor self-attention -> dsa[:,0:128] ----------------
__global__ void __launch_bounds__(128) nsa_kernel(
    const float* __restrict__ wq, const float* __restrict__ bq,
    const float* __restrict__ wk, const float* __restrict__ bk,
    const float* __restrict__ wv, const float* __restrict__ bv,
    const float* __restrict__ gam) {
    __shared__ float xs[32][128];
    __shared__ float qs[32][16], ks2[32][16];
    __shared__ float at[32][32];
    int g = blockIdx.x, t = threadIdx.x;
    const float* xg = g_x + (size_t)g*4096;
#pragma unroll
    for (int i = 0; i < 8; i++)
        *(float4*)(&xs[0][0] + t*4 + i*512) = *(const float4*)(xg + t*4 + i*512);
    __syncthreads();
    {   // q,k projections: thread -> row r, 4 channels
        int r = t >> 2, c0 = (t & 3)*4;
        float4 aq = *(const float4*)(bq + c0);
        float4 ak = *(const float4*)(bk + c0);
        for (int i = 0; i < 128; i++) {
            float xv = xs[r][i];
            float4 wq4 = *(const float4*)(wq + i*16 + c0);
            float4 wk4 = *(const float4*)(wk + i*16 + c0);
            aq.x += xv*wq4.x; aq.y += xv*wq4.y; aq.z += xv*wq4.z; aq.w += xv*wq4.w;
            ak.x += xv*wk4.x; ak.y += xv*wk4.y; ak.z += xv*wk4.z; ak.w += xv*wk4.w;
        }
        *(float4*)&qs[r][c0] = aq; *(float4*)&ks2[r][c0] = ak;
    }
    __syncthreads();
    {   // scores + softmax: thread -> row r, 8 cols
        int r = t >> 2, j0 = (t & 3)*8;
        float4 q0 = *(float4*)&qs[r][0], q1 = *(float4*)&qs[r][4];
        float4 q2 = *(float4*)&qs[r][8], q3 = *(float4*)&qs[r][12];
        float sc[8];
#pragma unroll
        for (int jj = 0; jj < 8; jj++) {
            int j = j0 + jj;
            float4 k0 = *(float4*)&ks2[j][0], k1 = *(float4*)&ks2[j][4];
            float4 k2 = *(float4*)&ks2[j][8], k3 = *(float4*)&ks2[j][12];
            sc[jj] = q0.x*k0.x + q0.y*k0.y + q0.z*k0.z + q0.w*k0.w
                   + q1.x*k1.x + q1.y*k1.y + q1.z*k1.z + q1.w*k1.w
                   + q2.x*k2.x + q2.y*k2.y + q2.z*k2.z + q2.w*k2.w
                   + q3.x*k3.x + q3.y*k3.y + q3.z*k3.z + q3.w*k3.w;
        }
        float mx = sc[0];
#pragma unroll
        for (int jj = 1; jj < 8; jj++) mx = fmaxf(mx, sc[jj]);
        mx = fmaxf(mx, __shfl_xor_sync(0xffffffffu, mx, 1));
        mx = fmaxf(mx, __shfl_xor_sync(0xffffffffu, mx, 2));
        float sum = 0.f;
#pragma unroll
        for (int jj = 0; jj < 8; jj++) { sc[jj] = expf(sc[jj]-mx); sum += sc[jj]; }
        sum += __shfl_xor_sync(0xffffffffu, sum, 1);
        sum += __shfl_xor_sync(0xffffffffu, sum, 2);
#pragma unroll
        for (int jj = 0; jj < 8; jj++) at[r][j0+jj] = sc[jj]/sum;
    }
    __syncthreads();
    // v projection (thread t = channel d), then nei
    float vreg[32];
    {
        float accv[32];
#pragma unroll
        for (int k = 0; k < 32; k++) accv[k] = 0.f;
        for (int i4 = 0; i4 < 32; i4++) {
            float w0 = wv[(i4*4+0)*128 + t], w1v = wv[(i4*4+1)*128 + t];
            float w2v = wv[(i4*4+2)*128 + t], w3v = wv[(i4*4+3)*128 + t];
#pragma unroll
            for (int k = 0; k < 32; k++) {
                float4 xv = *(float4*)&xs[k][i4*4];
                accv[k] += xv.x*w0 + xv.y*w1v + xv.z*w2v + xv.w*w3v;
            }
        }
        float bvd = bv[t];
#pragma unroll
        for (int k = 0; k < 32; k++) vreg[k] = accv[k] + bvd;
    }
    float accn[32];
#pragma unroll
    for (int k = 0; k < 32; k++) accn[k] = 0.f;
    for (int j4 = 0; j4 < 8; j4++) {
        float v0 = vreg[j4*4+0], v1 = vreg[j4*4+1], v2 = vreg[j4*4+2], v3 = vreg[j4*4+3];
#pragma unroll
        for (int k = 0; k < 32; k++) {
            float4 a4 = *(float4*)&at[k][j4*4];
            accn[k] += a4.x*v0 + a4.y*v1 + a4.z*v2 + a4.w*v3;
        }
    }
    float gm = gam[0];
#pragma unroll
    for (int k = 0; k < 32; k++)
        g_dsa[((size_t)g*32 + k)*256 + t] = gm*accn[k] + xs[k][t];
}

// ---------------- 5. GAM G = F F^T ----------------
__global__ void __launch_bounds__(256) gam1_kernel() {
    __shared__ float As[16][64], Bs[16][64];
    int b = blockIdx.z;
    const float* F = g_x + (size_t)b*SSP*4096;
    int row0 = blockIdx.y*64, col0 = blockIdx.x*64;
    int t = threadIdx.x, tx = t & 15, ty = t >> 4;
    int lr = t >> 2, lk = (t & 3)*4;
    float acc[4][4] = {};
    const float* Arow = F + (size_t)(row0+lr)*4096 + lk;
    const float* Brow = F + (size_t)(col0+lr)*4096 + lk;
    for (int k0 = 0; k0 < 4096; k0 += 16) {
        float4 a = *(const float4*)(Arow + k0);
        float4 c = *(const float4*)(Brow + k0);
        As[lk][lr] = a.x; As[lk+1][lr] = a.y; As[lk+2][lr] = a.z; As[lk+3][lr] = a.w;
        Bs[lk][lr] = c.x; Bs[lk+1][lr] = c.y; Bs[lk+2][lr] = c.z; Bs[lk+3][lr] = c.w;
        __syncthreads();
#pragma unroll
        for (int kk = 0; kk < 16; kk++) {
            float4 av = *(float4*)&As[kk][ty*4];
            float4 bv = *(float4*)&Bs[kk][tx*4];
            float ar[4] = {av.x, av.y, av.z, av.w};
            float br[4] = {bv.x, bv.y, bv.z, bv.w};
#pragma unroll
            for (int i = 0; i < 4; i++)
#pragma unroll
                for (int j = 0; j < 4; j++) acc[i][j] += ar[i]*br[j];
        }
        __syncthreads();
    }
    float* Gp = g_G + (size_t)b*SSP*SSP;
#pragma unroll
    for (int i = 0; i < 4; i++)
        *(float4*)(Gp + (size_t)(row0+ty*4+i)*SSP + col0 + tx*4) = *(float4*)acc[i];
}

// ---------------- 6. softmax over G rows ----------------
__global__ void __launch_bounds__(256) gsoftmax_kernel() {
    __shared__ float red[8];
    int row = blockIdx.x, t = threadIdx.x;
    float* p = g_G + (size_t)row*SSP;
    float a = p[t], b = p[t+256];
    float mx = fmaxf(a, b);
#pragma unroll
    for (int off = 16; off > 0; off >>= 1) mx = fmaxf(mx, __shfl_xor_sync(0xffffffffu, mx, off));
    if ((t & 31) == 0) red[t>>5] = mx;
    __syncthreads();
    mx = red[0];
#pragma unroll
    for (int w = 1; w < 8; w++) mx = fmaxf(mx, red[w]);
    float e1 = expf(a-mx), e2 = expf(b-mx);
    float s = e1 + e2;
#pragma unroll
    for (int off = 16; off > 0; off >>= 1) s += __shfl_xor_sync(0xffffffffu, s, off);
    __syncthreads();
    if ((t & 31) == 0) red[t>>5] = s;
    __syncthreads();
    s = red[0];
#pragma unroll
    for (int w = 1; w < 8; w++) s += red[w];
    p[t] = e1/s; p[t+256] = e2/s;
}

// ---------------- 7. grp = gamma*G@F + x -> dsa[:,128:256] ----------------
__global__ void __launch_bounds__(256) gam2_kernel(const float* __restrict__ gam) {
    __shared__ float As[16][64], Bs[16][64];
    int b = blockIdx.z;
    const float* A = g_G + (size_t)b*SSP*SSP;
    const float* F = g_x + (size_t)b*SSP*4096;
    int row0 = blockIdx.y*64, col0 = blockIdx.x*64;
    int t = threadIdx.x, tx = t & 15, ty = t >> 4;
    int lr = t >> 2, lk = (t & 3)*4;
    int kr = t >> 4, c4 = (t & 15)*4;
    float acc[4][4] = {};
    const float* Arow = A + (size_t)(row0+lr)*SSP + lk;
    for (int k0 = 0; k0 < SSP; k0 += 16) {
        float4 a = *(const float4*)(Arow + k0);
        As[lk][lr] = a.x; As[lk+1][lr] = a.y; As[lk+2][lr] = a.z; As[lk+3][lr] = a.w;
        *(float4*)&Bs[kr][c4] = *(const float4*)(F + (size_t)(k0+kr)*4096 + col0 + c4);
        __syncthreads();
#pragma unroll
        for (int kk = 0; kk < 16; kk++) {
            float4 av = *(float4*)&As[kk][ty*4];
            float4 bv = *(float4*)&Bs[kk][tx*4];
            float ar[4] = {av.x, av.y, av.z, av.w};
            float br[4] = {bv.x, bv.y, bv.z, bv.w};
#pragma unroll
            for (int i = 0; i < 4; i++)
#pragma unroll
                for (int j = 0; j < 4; j++) acc[i][j] += ar[i]*br[j];
        }
        __syncthreads();
    }
    float gm = gam[0];
    int c0 = col0 + tx*4, kidx = c0 >> 7, d = c0 & 127;
#pragma unroll
    for (int i = 0; i < 4; i++) {
        int s = row0 + ty*4 + i;
        const float* xr = F + (size_t)s*4096 + c0;
        float4 o;
        o.x = gm*acc[i][0] + xr[0]; o.y = gm*acc[i][1] + xr[1];
        o.z = gm*acc[i][2] + xr[2]; o.w = gm*acc[i][3] + xr[3];
        *(float4*)(g_dsa + ((size_t)(b*SSP+s)*32 + kidx)*256 + 128 + d) = o;
    }
}

// ---------------- 8. h = relu(bn1(dsa@w1+b1)) ----------------
__global__ void __launch_bounds__(256) head1_kernel(const float* __restrict__ w1,
                                                    const float* __restrict__ b1,
                                                    const float* __restrict__ bn1) {
    __shared__ float As[16][64], Bs[16][64];
    int row0 = blockIdx.y*64, col0 = blockIdx.x*64;
    int t = threadIdx.x, tx = t & 15, ty = t >> 4;
    int lr = t >> 2, lk = (t & 3)*4;
    int kr = t >> 4, c4 = (t & 15)*4;
    float acc[4][4] = {};
    const float* Arow = g_dsa + (size_t)(row0+lr)*256 + lk;
    for (int k0 = 0; k0 < 256; k0 += 16) {
        float4 a = *(const float4*)(Arow + k0);
        As[lk][lr] = a.x; As[lk+1][lr] = a.y; As[lk+2][lr] = a.z; As[lk+3][lr] = a.w;
        *(float4*)&Bs[kr][c4] = *(const float4*)(w1 + (size_t)(k0+kr)*256 + col0 + c4);
        __syncthreads();
#pragma unroll
        for (int kk = 0; kk < 16; kk++) {
            float4 av = *(float4*)&As[kk][ty*4];
            float4 bv = *(float4*)&Bs[kk][tx*4];
            float ar[4] = {av.x, av.y, av.z, av.w};
            float br[4] = {bv.x, bv.y, bv.z, bv.w};
#pragma unroll
            for (int i = 0; i < 4; i++)
#pragma unroll
                for (int j = 0; j < 4; j++) acc[i][j] += ar[i]*br[j];
        }
        __syncthreads();
    }
    float aa[4], cc[4];
#pragma unroll
    for (int j = 0; j < 4; j++) {
        int c = col0 + tx*4 + j;
        float g = bn1[c], be = bn1[256+c], m = bn1[512+c], v = bn1[768+c];
        aa[j] = g*rsqrtf(v + EPSV);
        cc[j] = aa[j]*(b1[c]-m) + be;
    }
#pragma unroll
    for (int i = 0; i < 4; i++) {
        float4 o;
        o.x = fmaxf(acc[i][0]*aa[0]+cc[0], 0.f);
        o.y = fmaxf(acc[i][1]*aa[1]+cc[1], 0.f);
        o.z = fmaxf(acc[i][2]*aa[2]+cc[2], 0.f);
        o.w = fmaxf(acc[i][3]*aa[3]+cc[3], 0.f);
        *(float4*)(g_h + (size_t)(row0+ty*4+i)*256 + col0 + tx*4) = o;
    }
}

// ---------------- 9. fused final: bn2(h@w2+b2) + sc, relu, max over K ----------------
__global__ void __launch_bounds__(128) head2_kernel(
    const float* __restrict__ w2, const float* __restrict__ b2, const float* __restrict__ bn2,
    const float* __restrict__ scw, const float* __restrict__ scb, const float* __restrict__ scbn,
    float* __restrict__ outp) {
    __shared__ float hs[32][256];
    __shared__ float xs2[32][64];
    int g = blockIdx.x, t = threadIdx.x;
    const float* hrow = g_h + (size_t)g*32*256;
#pragma unroll
    for (int i = 0; i < 16; i++)
        *(float4*)(&hs[0][0] + t*4 + i*512) = *(const float4*)(hrow + t*4 + i*512);
    for (int idx = t; idx < 2048; idx += 128)
        xs2[idx>>6][idx&63] = g_x[((size_t)g*32 + (idx>>6))*128 + 64 + (idx&63)];
    __syncthreads();
    float acc[32];
#pragma unroll
    for (int k = 0; k < 32; k++) acc[k] = 0.f;
    for (int i4 = 0; i4 < 64; i4++) {
        float w0 = w2[(i4*4+0)*128+t], w1v = w2[(i4*4+1)*128+t];
        float w2v = w2[(i4*4+2)*128+t], w3v = w2[(i4*4+3)*128+t];
#pragma unroll
        for (int k = 0; k < 32; k++) {
            float4 h4 = *(float4*)&hs[k][i4*4];
            acc[k] += h4.x*w0 + h4.y*w1v + h4.z*w2v + h4.w*w3v;
        }
    }
    float a2 = bn2[t]*rsqrtf(bn2[384+t] + EPSV);
    float c2 = a2*(b2[t]-bn2[256+t]) + bn2[128+t];
#pragma unroll
    for (int k = 0; k < 32; k++) acc[k] = acc[k]*a2 + c2;   // main (no relu)
    float acc2[32];
#pragma unroll
    for (int k = 0; k < 32; k++) acc2[k] = 0.f;
    for (int i4 = 0; i4 < 16; i4++) {
        float w0 = scw[(i4*4+0)*128+t], w1v = scw[(i4*4+1)*128+t];
        float w2v = scw[(i4*4+2)*128+t], w3v = scw[(i4*4+3)*128+t];
#pragma unroll
        for (int k = 0; k < 32; k++) {
            float4 x4 = *(float4*)&xs2[k][i4*4];
            acc2[k] += x4.x*w0 + x4.y*w1v + x4.z*w2v + x4.w*w3v;
        }
    }
    float aS = scbn[t]*rsqrtf(scbn[384+t] + EPSV);
    float cS = aS*(scb[t]-scbn[256+t]) + scbn[128+t];
    float vmax = -FLT_MAX;
#pragma unroll
    for (int k = 0; k < 32; k++) {
        float sc = fmaxf(acc2[k]*aS + cS, 0.f);
        vmax = fmaxf(vmax, fmaxf(acc[k] + sc, 0.f));
    }
    outp[12288 + (size_t)g*128 + t] = vmax;
}

extern "C" void kernel_launch(void* const* d_in, const int* in_sizes, int n_in,
                              void* d_out, int out_size) {
    const float* xyz     = (const float*)d_in[0];
    const float* points  = (const float*)d_in[1];
    const int*   fstart  = (const int*)d_in[2];
    const float* pos_w1  = (const float*)d_in[3];
    const float* pos_b1  = (const float*)d_in[4];
    const float* pos_bn1 = (const float*)d_in[5];
    const float* pos_w2  = (const float*)d_in[6];
    const float* pos_b2  = (const float*)d_in[7];
    const float* pos_bn2 = (const float*)d_in[8];
    const float* nsa_wq  = (const float*)d_in[9];
    const float* nsa_bq  = (const float*)d_in[10];
    const float* nsa_wk  = (const float*)d_in[11];
    const float* nsa_bk  = (const float*)d_in[12];
    const float* nsa_wv  = (const float*)d_in[13];
    const float* nsa_bv  = (const float*)d_in[14];
    const float* nsa_g   = (const float*)d_in[15];
    const float* gam_g   = (const float*)d_in[16];
    const float* cat_w1  = (const float*)d_in[17];
    const float* cat_b1  = (const float*)d_in[18];
    const float* cat_bn1 = (const float*)d_in[19];
    const float* cat_w2  = (const float*)d_in[20];
    const float* cat_b2  = (const float*)d_in[21];
    const float* cat_bn2 = (const float*)d_in[22];
    const float* sc_w    = (const float*)d_in[23];
    const float* sc_b    = (const float*)d_in[24];
    const float* sc_bn   = (const float*)d_in[25];
    float* outp = (float*)d_out;

    static int done = 0;
    if (!done) {
        cudaFuncSetAttribute(fps_kernel, cudaFuncAttributeMaxDynamicSharedMemorySize, 49152);
        done = 1;
    }
    fps_kernel<<<BB, 512, 49152>>>(xyz, fstart, outp);
    knn_kernel<<<dim3(SSP, BB), 128>>>(xyz, outp);
    grouppos_kernel<<<512, 256>>>(xyz, points, outp, pos_w1, pos_b1, pos_bn1,
                                  pos_w2, pos_b2, pos_bn2);
    nsa_kernel<<<BB*SSP, 128>>>(nsa_wq, nsa_bq, nsa_wk, nsa_bk, nsa_wv, nsa_bv, nsa_g);
    gam1_kernel<<<dim3(8, 8, BB), 256>>>();
    gsoftmax_kernel<<<BB*SSP, 256>>>();
    gam2_kernel<<<dim3(64, 8, BB), 256>>>(gam_g);
    head1_kernel<<<dim3(4, 2048), 256>>>(cat_w1, cat_b1, cat_bn1);
    head2_kernel<<<BB*SSP, 128>>>(cat_w2, cat_b2, cat_bn2, sc_w, sc_b, sc_bn, outp);
}

// round 6
// speedup vs baseline: 1.5871x; 1.5871x over previous
#include <cuda_runtime.h>
#include <stdint.h>
#include <math.h>
#include <float.h>

#define BB 8
#define NNP 4096
#define SSP 512
#define KKN 32
#define EPSV 1e-5f
#define PITCH 36

// scratch (__device__ globals — no allocation allowed)
__device__ float g_x[BB*SSP*KKN*128];      // x = [pos|pts]  [B,S,K,128] = [B,S,4096]
__device__ float g_xT[BB*4096*SSP];        // F^T per batch  [B,4096,512]
__device__ float g_dsa[BB*SSP*KKN*256];    // [nei|grp]
__device__ float g_h[BB*SSP*KKN*256];      // hidden
__device__ float g_G[BB*SSP*SSP];          // GAM attention
__device__ float g_main[BB*SSP*KKN*128];   // bn2(h@w2+b2)
__device__ float g_scv[BB*SSP*KKN*128];    // relu(bn(sc))
__device__ float g_w1T[256*256];
__device__ float g_w2T[128*256];
__device__ float g_scwT[128*64];
__device__ int   g_knn[BB*SSP*KKN];
__device__ float g_knnd[BB*SSP*KKN];

// ---------------- tf32 warp-MMA helpers ----------------
__device__ __forceinline__ uint32_t f2tf(float f) {
    uint32_t u; asm("cvt.rna.tf32.f32 %0, %1;" : "=r"(u) : "f"(f)); return u;
}
__device__ __forceinline__ void mma8(float* c, const uint32_t* a, const uint32_t* b) {
    asm volatile("mma.sync.aligned.m16n8k8.row.col.f32.tf32.tf32.f32 "
        "{%0,%1,%2,%3}, {%4,%5,%6,%7}, {%8,%9}, {%0,%1,%2,%3};"
        : "+f"(c[0]), "+f"(c[1]), "+f"(c[2]), "+f"(c[3])
        : "r"(a[0]), "r"(a[1]), "r"(a[2]), "r"(a[3]), "r"(b[0]), "r"(b[1]));
}

// C[128,128] tile of A[M,K](row-major) * B[N,K](row-major, i.e. B^T) ; 256 threads
__device__ __forceinline__ void gemm_core(const float* __restrict__ A, int lda,
                                          const float* __restrict__ B, int ldb,
                                          int K, int row0, int col0,
                                          float (*acc)[8][4],
                                          uint32_t* As, uint32_t* Bs) {
    int t = threadIdx.x, lane = t & 31, wid = t >> 5;
    int wm = wid & 3, wn = wid >> 2;
    int gg = lane >> 2, tg = lane & 3;
    for (int k0 = 0; k0 < K; k0 += 32) {
#pragma unroll
        for (int i = 0; i < 4; i++) {
            int lin = t + i*256;
            int r = lin >> 3, c4 = (lin & 7)*4;
            float4 av = *(const float4*)(A + (size_t)(row0+r)*lda + k0 + c4);
            float4 bv = *(const float4*)(B + (size_t)(col0+r)*ldb + k0 + c4);
            uint32_t* ap = As + r*PITCH + c4;
            ap[0]=f2tf(av.x); ap[1]=f2tf(av.y); ap[2]=f2tf(av.z); ap[3]=f2tf(av.w);
            uint32_t* bp = Bs + r*PITCH + c4;
            bp[0]=f2tf(bv.x); bp[1]=f2tf(bv.y); bp[2]=f2tf(bv.z); bp[3]=f2tf(bv.w);
        }
        __syncthreads();
#pragma unroll
        for (int kk = 0; kk < 32; kk += 8) {
            uint32_t af[2][4], bf[8][2];
#pragma unroll
            for (int mt = 0; mt < 2; mt++) {
                int rb = (wm*32 + mt*16 + gg)*PITCH + kk + tg;
                af[mt][0] = As[rb];
                af[mt][1] = As[rb + 8*PITCH];
                af[mt][2] = As[rb + 4];
                af[mt][3] = As[rb + 8*PITCH + 4];
            }
#pragma unroll
            for (int nt = 0; nt < 8; nt++) {
                int nb = (wn*64 + nt*8 + gg)*PITCH + kk + tg;
                bf[nt][0] = Bs[nb];
                bf[nt][1] = Bs[nb + 4];
            }
#pragma unroll
            for (int mt = 0; mt < 2; mt++)
#pragma unroll
                for (int nt = 0; nt < 8; nt++)
                    mma8(acc[mt][nt], af[mt], bf[nt]);
        }
        __syncthreads();
    }
}

#define EPI_VARS int t_=threadIdx.x, lane_=t_&31, wid_=t_>>5; \
    int wm_=wid_&3, wn_=wid_>>2, eg_=lane_>>2, etg_=lane_&3; (void)t_;

// ---------------- transposes ----------------
__global__ void __launch_bounds__(256) transposeX_kernel() {
    __shared__ float tile[32][33];
    int b = blockIdx.z;
    const float* src = g_x + (size_t)b*SSP*4096;
    float* dst = g_xT + (size_t)b*4096*SSP;
    int r0 = blockIdx.y*32, c0 = blockIdx.x*32;
    int tx = threadIdx.x & 31, ty = threadIdx.x >> 5;
#pragma unroll
    for (int i = 0; i < 32; i += 8)
        tile[ty+i][tx] = src[(size_t)(r0+ty+i)*4096 + c0+tx];
    __syncthreads();
#pragma unroll
    for (int i = 0; i < 32; i += 8)
        dst[(size_t)(c0+ty+i)*SSP + r0+tx] = tile[tx][ty+i];
}
__global__ void __launch_bounds__(256) transposeW_kernel(const float* __restrict__ src,
                                                         int R, int C, int sel) {
    __shared__ float tile[32][33];
    float* dst = sel == 0 ? g_w1T : (sel == 1 ? g_w2T : g_scwT);
    int r0 = blockIdx.y*32, c0 = blockIdx.x*32;
    int tx = threadIdx.x & 31, ty = threadIdx.x >> 5;
#pragma unroll
    for (int i = 0; i < 32; i += 8)
        tile[ty+i][tx] = src[(size_t)(r0+ty+i)*C + c0+tx];
    __syncthreads();
#pragma unroll
    for (int i = 0; i < 32; i += 8)
        dst[(size_t)(c0+ty+i)*R + r0+tx] = tile[tx][ty+i];
}

// ---------------- 1. FPS ----------------
__global__ void __launch_bounds__(512) fps_kernel(const float* __restrict__ xyz,
                                                  const int* __restrict__ start,
                                                  float* __restrict__ centers) {
    __shared__ float sx[NNP], sy[NNP], sz[NNP];
    __shared__ float rv[16]; __shared__ int ri[16]; __shared__ int sfar;
    int b = blockIdx.x, tid = threadIdx.x;
    for (int i = tid; i < NNP; i += 512) {
        const float* p = xyz + ((size_t)b*NNP + i)*3;
        sx[i] = p[0]; sy[i] = p[1]; sz[i] = p[2];
    }
    float dist[8];
#pragma unroll
    for (int i = 0; i < 8; i++) dist[i] = 1e10f;
    __syncthreads();
    int far = start[b];
    for (int t = 0; t < SSP; t++) {
        float cx = sx[far], cy = sy[far], cz = sz[far];
        if (tid == 0) {
            float* o = centers + ((size_t)b*SSP + t)*3;
            o[0] = cx; o[1] = cy; o[2] = cz;
        }
        float bv = -1.0f; int bi = 0;
#pragma unroll
        for (int i = 0; i < 8; i++) {
            int p = tid + i*512;
            float dx = sx[p]-cx, dy = sy[p]-cy, dz = sz[p]-cz;
            float d = fminf(dist[i], dx*dx + dy*dy + dz*dz);
            dist[i] = d;
            if (d > bv) { bv = d; bi = p; }
        }
#pragma unroll
        for (int off = 16; off > 0; off >>= 1) {
            float ov = __shfl_down_sync(0xffffffffu, bv, off);
            int   oi = __shfl_down_sync(0xffffffffu, bi, off);
            if (ov > bv || (ov == bv && oi < bi)) { bv = ov; bi = oi; }
        }
        if ((tid & 31) == 0) { rv[tid>>5] = bv; ri[tid>>5] = bi; }
        __syncthreads();
        if (tid == 0) {
            float gv = rv[0]; int gi = ri[0];
#pragma unroll
            for (int w = 1; w < 16; w++)
                if (rv[w] > gv || (rv[w] == gv && ri[w] < gi)) { gv = rv[w]; gi = ri[w]; }
            sfar = gi;
        }
        __syncthreads();
        far = sfar;
    }
}

// ---------------- 2. KNN ----------------
__global__ void __launch_bounds__(128) knn_kernel(const float* __restrict__ xyz,
                                                  const float* __restrict__ centers) {
    __shared__ float sd2[KKN*128];
    __shared__ float swv[4]; __shared__ int swi[4];
    int s = blockIdx.x, b = blockIdx.y, tid = threadIdx.x;
    const float* c = centers + ((size_t)b*SSP + s)*3;
    float cx = c[0], cy = c[1], cz = c[2];
    float cn2 = cx*cx + cy*cy + cz*cz;
    float lv = FLT_MAX; int li = 0x7fffffff; int lslot = 0;
#pragma unroll
    for (int i = 0; i < KKN; i++) {
        int p = tid + i*128;
        const float* pp = xyz + ((size_t)b*NNP + p)*3;
        float px = pp[0], py = pp[1], pz = pp[2];
        float d2 = cn2 + (px*px + py*py + pz*pz) - 2.0f*(cx*px + cy*py + cz*pz);
        sd2[i*128 + tid] = d2;
        if (d2 < lv) { lv = d2; li = p; lslot = i; }
    }
    int lane = tid & 31, warp = tid >> 5;
    int obase = (b*SSP + s)*KKN;
    for (int r = 0; r < KKN; r++) {
        float bv = lv; int bi = li;
#pragma unroll
        for (int off = 16; off > 0; off >>= 1) {
            float ov = __shfl_xor_sync(0xffffffffu, bv, off);
            int   oi = __shfl_xor_sync(0xffffffffu, bi, off);
            if (ov < bv || (ov == bv && oi < bi)) { bv = ov; bi = oi; }
        }
        if (lane == 0) { swv[warp] = bv; swi[warp] = bi; }
        __syncthreads();
        float gv = swv[0]; int gi = swi[0];
#pragma unroll
        for (int w = 1; w < 4; w++)
            if (swv[w] < gv || (swv[w] == gv && swi[w] < gi)) { gv = swv[w]; gi = swi[w]; }
        if (tid == 0) { g_knn[obase + r] = gi; g_knnd[obase + r] = gv; }
        if (gi == li) {
            sd2[lslot*128 + tid] = FLT_MAX;
            lv = FLT_MAX; li = 0x7fffffff; lslot = 0;
#pragma unroll
            for (int i = 0; i < KKN; i++) {
                float d = sd2[i*128 + tid];
                if (d < lv) { lv = d; li = tid + i*128; lslot = i; }
            }
        }
        __syncthreads();
    }
}

// ---------------- 3. group + pos-embed MLP ----------------
__global__ void __launch_bounds__(256) grouppos_kernel(
    const float* __restrict__ xyz, const float* __restrict__ points,
    const float* __restrict__ centers,
    const float* __restrict__ w1, const float* __restrict__ b1, const float* __restrict__ bn1,
    const float* __restrict__ w2, const float* __restrict__ b2, const float* __restrict__ bn2) {
    __shared__ float sw1[320], sw2[2048];
    __shared__ float sA1[32], sC1[32], sA2[64], sC2[64];
    int tid = threadIdx.x;
    for (int i = tid; i < 320; i += 256) sw1[i] = w1[i];
    for (int i = tid; i < 2048; i += 256) sw2[i] = w2[i];
    if (tid < 32) {
        float a = bn1[tid] * rsqrtf(bn1[96+tid] + EPSV);
        sA1[tid] = a; sC1[tid] = a*(b1[tid]-bn1[64+tid]) + bn1[32+tid];
    }
    if (tid < 64) {
        float a = bn2[tid] * rsqrtf(bn2[192+tid] + EPSV);
        sA2[tid] = a; sC2[tid] = a*(b2[tid]-bn2[128+tid]) + bn2[64+tid];
    }
    __syncthreads();
    int gid = blockIdx.x*256 + tid;
    int b = gid >> 14;
    int idx = g_knn[gid];
    float dd = g_knnd[gid];
    const float* c = centers + (size_t)(gid >> 5)*3;
    float cx = c[0], cy = c[1], cz = c[2];
    const float* pp = xyz + ((size_t)b*NNP + idx)*3;
    float px = pp[0], py = pp[1], pz = pp[2];
    float f[10] = {cx, cy, cz, px, py, pz, px-cx, py-cy, pz-cz, dd};
    float h[32];
#pragma unroll
    for (int cc = 0; cc < 32; cc++) {
        float acc = 0.f;
#pragma unroll
        for (int i = 0; i < 10; i++) acc += f[i]*sw1[i*32+cc];
        h[cc] = fmaxf(acc*sA1[cc] + sC1[cc], 0.f);
    }
    float* xo = g_x + (size_t)gid*128;
#pragma unroll
    for (int cc = 0; cc < 64; cc++) {
        float acc = 0.f;
#pragma unroll
        for (int i = 0; i < 32; i++) acc += h[i]*sw2[i*64+cc];
        xo[cc] = fmaxf(acc*sA2[cc] + sC2[cc], 0.f);
    }
    const float* pr = points + ((size_t)b*NNP + idx)*64;
#pragma unroll
    for (int j = 0; j < 64; j += 4)
        *(float4*)(xo + 64 + j) = *(const float4*)(pr + j);
}

// ---------------- 4. neighbor self-attention -> dsa[:,0:128] ----------------
__global__ void __launch_bounds__(128) nsa_kernel(
    const float* __restrict__ wq, const float* __restrict__ bq,
    const float* __restrict__ wk, const float* __restrict__ bk,
    const float* __restrict__ wv, const float* __restrict__ bv,
    const float* __restrict__ gam) {
    __shared__ float xs[32][128];
    __shared__ float qs[32][16], ks2[32][16];
    __shared__ float at[32][32];
    int g = blockIdx.x, t = threadIdx.x;
    const float* xg = g_x + (size_t)g*4096;
#pragma unroll
    for (int i = 0; i < 8; i++)
        *(float4*)(&xs[0][0] + t*4 + i*512) = *(const float4*)(xg + t*4 + i*512);
    __syncthreads();
    {
        int r = t >> 2, c0 = (t & 3)*4;
        float4 aq = *(const float4*)(bq + c0);
        float4 ak = *(const float4*)(bk + c0);
        for (int i = 0; i < 128; i++) {
            float xv = xs[r][i];
            float4 wq4 = *(const float4*)(wq + i*16 + c0);
            float4 wk4 = *(const float4*)(wk + i*16 + c0);
            aq.x += xv*wq4.x; aq.y += xv*wq4.y; aq.z += xv*wq4.z; aq.w += xv*wq4.w;
            ak.x += xv*wk4.x; ak.y += xv*wk4.y; ak.z += xv*wk4.z; ak.w += xv*wk4.w;
        }
        *(float4*)&qs[r][c0] = aq; *(float4*)&ks2[r][c0] = ak;
    }
    __syncthreads();
    {
        int r = t >> 2, j0 = (t & 3)*8;
        float4 q0 = *(float4*)&qs[r][0], q1 = *(float4*)&qs[r][4];
        float4 q2 = *(float4*)&qs[r][8], q3 = *(float4*)&qs[r][12];
        float sc[8];
#pragma unroll
        for (int jj = 0; jj < 8; jj++) {
            int j = j0 + jj;
            float4 k0 = *(float4*)&ks2[j][0], k1 = *(float4*)&ks2[j][4];
            float4 k2 = *(float4*)&ks2[j][8], k3 = *(float4*)&ks2[j][12];
            sc[jj] = q0.x*k0.x + q0.y*k0.y + q0.z*k0.z + q0.w*k0.w
                   + q1.x*k1.x + q1.y*k1.y + q1.z*k1.z + q1.w*k1.w
                   + q2.x*k2.x + q2.y*k2.y + q2.z*k2.z + q2.w*k2.w
                   + q3.x*k3.x + q3.y*k3.y + q3.z*k3.z + q3.w*k3.w;
        }
        float mx = sc[0];
#pragma unroll
        for (int jj = 1; jj < 8; jj++) mx = fmaxf(mx, sc[jj]);
        mx = fmaxf(mx, __shfl_xor_sync(0xffffffffu, mx, 1));
        mx = fmaxf(mx, __shfl_xor_sync(0xffffffffu, mx, 2));
        float sum = 0.f;
#pragma unroll
        for (int jj = 0; jj < 8; jj++) { sc[jj] = expf(sc[jj]-mx); sum += sc[jj]; }
        sum += __shfl_xor_sync(0xffffffffu, sum, 1);
        sum += __shfl_xor_sync(0xffffffffu, sum, 2);
#pragma unroll
        for (int jj = 0; jj < 8; jj++) at[r][j0+jj] = sc[jj]/sum;
    }
    __syncthreads();
    float vreg[32];
    {
        float accv[32];
#pragma unroll
        for (int k = 0; k < 32; k++) accv[k] = 0.f;
        for (int i4 = 0; i4 < 32; i4++) {
            float w0 = wv[(i4*4+0)*128 + t], w1v = wv[(i4*4+1)*128 + t];
            float w2v = wv[(i4*4+2)*128 + t], w3v = wv[(i4*4+3)*128 + t];
#pragma unroll
            for (int k = 0; k < 32; k++) {
                float4 xv = *(float4*)&xs[k][i4*4];
                accv[k] += xv.x*w0 + xv.y*w1v + xv.z*w2v + xv.w*w3v;
            }
        }
        float bvd = bv[t];
#pragma unroll
        for (int k = 0; k < 32; k++) vreg[k] = accv[k] + bvd;
    }
    float accn[32];
#pragma unroll
    for (int k = 0; k < 32; k++) accn[k] = 0.f;
    for (int j4 = 0; j4 < 8; j4++) {
        float v0 = vreg[j4*4+0], v1 = vreg[j4*4+1], v2 = vreg[j4*4+2], v3 = vreg[j4*4+3];
#pragma unroll
        for (int k = 0; k < 32; k++) {
            float4 a4 = *(float4*)&at[k][j4*4];
            accn[k] += a4.x*v0 + a4.y*v1 + a4.z*v2 + a4.w*v3;
        }
    }
    float gm = gam[0];
#pragma unroll
    for (int k = 0; k < 32; k++)
        g_dsa[((size_t)g*32 + k)*256 + t] = gm*accn[k] + xs[k][t];
}

// ---------------- 5. GAM G = F F^T (tf32 MMA) ----------------
__global__ void __launch_bounds__(256) gam1_mma() {
    __shared__ uint32_t As[128*PITCH], Bs[128*PITCH];
    int b = blockIdx.z;
    const float* F = g_x + (size_t)b*SSP*4096;
    int row0 = blockIdx.y*128, col0 = blockIdx.x*128;
    float acc[2][8][4] = {};
    gemm_core(F, 4096, F, 4096, 4096, row0, col0, acc, As, Bs);
    float* Gp = g_G + (size_t)b*SSP*SSP;
    EPI_VARS
#pragma unroll
    for (int mt = 0; mt < 2; mt++)
#pragma unroll
        for (int nt = 0; nt < 8; nt++) {
            int r = row0 + wm_*32 + mt*16 + eg_;
            int c = col0 + wn_*64 + nt*8 + 2*etg_;
            *(float2*)(Gp + (size_t)r*SSP + c)     = make_float2(acc[mt][nt][0], acc[mt][nt][1]);
            *(float2*)(Gp + (size_t)(r+8)*SSP + c) = make_float2(acc[mt][nt][2], acc[mt][nt][3]);
        }
}

// ---------------- 6. softmax over G rows ----------------
__global__ void __launch_bounds__(256) gsoftmax_kernel() {
    __shared__ float red[8];
    int row = blockIdx.x, t = threadIdx.x;
    float* p = g_G + (size_t)row*SSP;
    float a = p[t], b = p[t+256];
    float mx = fmaxf(a, b);
#pragma unroll
    for (int off = 16; off > 0; off >>= 1) mx = fmaxf(mx, __shfl_xor_sync(0xffffffffu, mx, off));
    if ((t & 31) == 0) red[t>>5] = mx;
    __syncthreads();
    mx = red[0];
#pragma unroll
    for (int w = 1; w < 8; w++) mx = fmaxf(mx, red[w]);
    float e1 = expf(a-mx), e2 = expf(b-mx);
    float s = e1 + e2;
#pragma unroll
    for (int off = 16; off > 0; off >>= 1) s += __shfl_xor_sync(0xffffffffu, s, off);
    __syncthreads();
    if ((t & 31) == 0) red[t>>5] = s;
    __syncthreads();
    s = red[0];
#pragma unroll
    for (int w = 1; w < 8; w++) s += red[w];
    p[t] = e1/s; p[t+256] = e2/s;
}

// ---------------- 7. grp = gamma*G@F + x -> dsa[:,128:256] (tf32 MMA) ----------------
__global__ void __launch_bounds__(256) gam2_mma(const float* __restrict__ gam) {
    __shared__ uint32_t As[128*PITCH], Bs[128*PITCH];
    int b = blockIdx.z;
    const float* A = g_G + (size_t)b*SSP*SSP;
    const float* Bm = g_xT + (size_t)b*4096*SSP;
    int row0 = blockIdx.y*128, col0 = blockIdx.x*128;
    float acc[2][8][4] = {};
    gemm_core(A, SSP, Bm, SSP, SSP, row0, col0, acc, As, Bs);
    float gm = gam[0];
    int kidx = blockIdx.x;   // col0 = kidx*128
    EPI_VARS
#pragma unroll
    for (int mt = 0; mt < 2; mt++)
#pragma unroll
        for (int nt = 0; nt < 8; nt++) {
            int r = row0 + wm_*32 + mt*16 + eg_;
            int c = col0 + wn_*64 + nt*8 + 2*etg_;
            int d = c & 127;
            const float* xr1 = g_x + ((size_t)b*SSP + r)*4096 + c;
            const float* xr2 = g_x + ((size_t)b*SSP + r + 8)*4096 + c;
            float* o1 = g_dsa + ((size_t)((b*SSP + r)*KKN) + kidx)*256 + 128 + d;
            float* o2 = g_dsa + ((size_t)((b*SSP + r + 8)*KKN) + kidx)*256 + 128 + d;
            *(float2*)o1 = make_float2(gm*acc[mt][nt][0] + xr1[0], gm*acc[mt][nt][1] + xr1[1]);
            *(float2*)o2 = make_float2(gm*acc[mt][nt][2] + xr2[0], gm*acc[mt][nt][3] + xr2[1]);
        }
}

// ---------------- 8. h = relu(bn1(dsa@w1+b1)) (tf32 MMA) ----------------
__global__ void __launch_bounds__(256) head1_mma(const float* __restrict__ b1,
                                                 const float* __restrict__ bn1) {
    __shared__ uint32_t As[128*PITCH], Bs[128*PITCH];
    int row0 = blockIdx.y*128, col0 = blockIdx.x*128;
    float acc[2][8][4] = {};
    gemm_core(g_dsa, 256, g_w1T, 256, 256, row0, col0, acc, As, Bs);
    EPI_VARS
#pragma unroll
    for (int mt = 0; mt < 2; mt++)
#pragma unroll
        for (int nt = 0; nt < 8; nt++) {
            int r = row0 + wm_*32 + mt*16 + eg_;
            int c = col0 + wn_*64 + nt*8 + 2*etg_;
            float a0 = bn1[c]*rsqrtf(bn1[768+c] + EPSV);
            float c0v = a0*(b1[c]-bn1[512+c]) + bn1[256+c];
            float a1 = bn1[c+1]*rsqrtf(bn1[768+c+1] + EPSV);
            float c1v = a1*(b1[c+1]-bn1[512+c+1]) + bn1[256+c+1];
            *(float2*)(g_h + (size_t)r*256 + c) = make_float2(
                fmaxf(acc[mt][nt][0]*a0 + c0v, 0.f), fmaxf(acc[mt][nt][1]*a1 + c1v, 0.f));
            *(float2*)(g_h + (size_t)(r+8)*256 + c) = make_float2(
                fmaxf(acc[mt][nt][2]*a0 + c0v, 0.f), fmaxf(acc[mt][nt][3]*a1 + c1v, 0.f));
        }
}

// ---------------- 9. main = bn2(h@w2+b2) (tf32 MMA) ----------------
__global__ void __launch_bounds__(256) head2_mma(const float* __restrict__ b2,
                                                 const float* __restrict__ bn2) {
    __shared__ uint32_t As[128*PITCH], Bs[128*PITCH];
    int row0 = blockIdx.y*128;
    float acc[2][8][4] = {};
    gemm_core(g_h, 256, g_w2T, 256, 256, row0, 0, acc, As, Bs);
    EPI_VARS
#pragma unroll
    for (int mt = 0; mt < 2; mt++)
#pragma unroll
        for (int nt = 0; nt < 8; nt++) {
            int r = row0 + wm_*32 + mt*16 + eg_;
            int c = wn_*64 + nt*8 + 2*etg_;
            float a0 = bn2[c]*rsqrtf(bn2[384+c] + EPSV);
            float c0v = a0*(b2[c]-bn2[256+c]) + bn2[128+c];
            float a1 = bn2[c+1]*rsqrtf(bn2[384+c+1] + EPSV);
            float c1v = a1*(b2[c+1]-bn2[256+c+1]) + bn2[128+c+1];
            *(float2*)(g_main + (size_t)r*128 + c) = make_float2(
                acc[mt][nt][0]*a0 + c0v, acc[mt][nt][1]*a1 + c1v);
            *(float2*)(g_main + (size_t)(r+8)*128 + c) = make_float2(
                acc[mt][nt][2]*a0 + c0v, acc[mt][nt][3]*a1 + c1v);
        }
}

// ---------------- 10. scv = relu(bn(pts@scw+scb)) (tf32 MMA) ----------------
__global__ void __launch_bounds__(256) sc_mma(const float* __restrict__ scb,
                                              const float* __restrict__ scbn) {
    __shared__ uint32_t As[128*PITCH], Bs[128*PITCH];
    int row0 = blockIdx.y*128;
    float acc[2][8][4] = {};
    gemm_core(g_x + 64, 128, g_scwT, 64, 64, row0, 0, acc, As, Bs);
    EPI_VARS
#pragma unroll
    for (int mt = 0; mt < 2; mt++)
#pragma unroll
        for (int nt = 0; nt < 8; nt++) {
            int r = row0 + wm_*32 + mt*16 + eg_;
            int c = wn_*64 + nt*8 + 2*etg_;
            float a0 = scbn[c]*rsqrtf(scbn[384+c] + EPSV);
            float c0v = a0*(scb[c]-scbn[256+c]) + scbn[128+c];
            float a1 = scbn[c+1]*rsqrtf(scbn[384+c+1] + EPSV);
            float c1v = a1*(scb[c+1]-scbn[256+c+1]) + scbn[128+c+1];
            *(float2*)(g_scv + (size_t)r*128 + c) = make_float2(
                fmaxf(acc[mt][nt][0]*a0 + c0v, 0.f), fmaxf(acc[mt][nt][1]*a1 + c1v, 0.f));
            *(float2*)(g_scv + (size_t)(r+8)*128 + c) = make_float2(
                fmaxf(acc[mt][nt][2]*a0 + c0v, 0.f), fmaxf(acc[mt][nt][3]*a1 + c1v, 0.f));
        }
}

// ---------------- 11. out = max_k relu(main + scv) ----------------
__global__ void __launch_bounds__(128) maxfuse_kernel(float* __restrict__ outp) {
    int gq = blockIdx.x, t = threadIdx.x;
    const float* mp = g_main + (size_t)gq*KKN*128 + t;
    const float* sp = g_scv  + (size_t)gq*KKN*128 + t;
    float vmax = -FLT_MAX;
#pragma unroll
    for (int k = 0; k < KKN; k++)
        vmax = fmaxf(vmax, fmaxf(mp[k*128] + sp[k*128], 0.f));
    outp[12288 + (size_t)gq*128 + t] = vmax;
}

extern "C" void kernel_launch(void* const* d_in, const int* in_sizes, int n_in,
                              void* d_out, int out_size) {
    const float* xyz     = (const float*)d_in[0];
    const float* points  = (const float*)d_in[1];
    const int*   fstart  = (const int*)d_in[2];
    const float* pos_w1  = (const float*)d_in[3];
    const float* pos_b1  = (const float*)d_in[4];
    const float* pos_bn1 = (const float*)d_in[5];
    const float* pos_w2  = (const float*)d_in[6];
    const float* pos_b2  = (const float*)d_in[7];
    const float* pos_bn2 = (const float*)d_in[8];
    const float* nsa_wq  = (const float*)d_in[9];
    const float* nsa_bq  = (const float*)d_in[10];
    const float* nsa_wk  = (const float*)d_in[11];
    const float* nsa_bk  = (const float*)d_in[12];
    const float* nsa_wv  = (const float*)d_in[13];
    const float* nsa_bv  = (const float*)d_in[14];
    const float* nsa_g   = (const float*)d_in[15];
    const float* gam_g   = (const float*)d_in[16];
    const float* cat_w1  = (const float*)d_in[17];
    const float* cat_b1  = (const float*)d_in[18];
    const float* cat_bn1 = (const float*)d_in[19];
    const float* cat_w2  = (const float*)d_in[20];
    const float* cat_b2  = (const float*)d_in[21];
    const float* cat_bn2 = (const float*)d_in[22];
    const float* sc_w    = (const float*)d_in[23];
    const float* sc_b    = (const float*)d_in[24];
    const float* sc_bn   = (const float*)d_in[25];
    float* outp = (float*)d_out;

    fps_kernel<<<BB, 512>>>(xyz, fstart, outp);
    knn_kernel<<<dim3(SSP, BB), 128>>>(xyz, outp);
    grouppos_kernel<<<512, 256>>>(xyz, points, outp, pos_w1, pos_b1, pos_bn1,
                                  pos_w2, pos_b2, pos_bn2);
    transposeW_kernel<<<dim3(8, 8), 256>>>(cat_w1, 256, 256, 0);
    transposeW_kernel<<<dim3(4, 8), 256>>>(cat_w2, 256, 128, 1);
    transposeW_kernel<<<dim3(4, 2), 256>>>(sc_w, 64, 128, 2);
    transposeX_kernel<<<dim3(128, 16, BB), 256>>>();
    nsa_kernel<<<BB*SSP, 128>>>(nsa_wq, nsa_bq, nsa_wk, nsa_bk, nsa_wv, nsa_bv, nsa_g);
    gam1_mma<<<dim3(4, 4, BB), 256>>>();
    gsoftmax_kernel<<<BB*SSP, 256>>>();
    gam2_mma<<<dim3(32, 4, BB), 256>>>(gam_g);
    sc_mma<<<dim3(1, 1024), 256>>>(sc_b, sc_bn);
    head1_mma<<<dim3(2, 1024), 256>>>(cat_b1, cat_bn1);
    head2_mma<<<dim3(1, 1024), 256>>>(cat_b2, cat_bn2);
    maxfuse_kernel<<<BB*SSP, 128>>>(outp);
}

// round 7
// speedup vs baseline: 1.9545x; 1.2315x over previous
#include <cuda_runtime.h>
#include <stdint.h>
#include <math.h>
#include <float.h>

#define BB 8
#define NNP 4096
#define SSP 512
#define KKN 32
#define EPSV 1e-5f
#define PITCH 36
#define DBUF (128*PITCH)
#define DYNSM (4*DBUF*4)

// scratch (__device__ globals — no allocation allowed)
__device__ float g_x[BB*SSP*KKN*128];      // x = [pos|pts]  [B,S,K,128] = [B,S,4096]
__device__ float g_xT[BB*4096*SSP];        // F^T per batch
__device__ float g_v[BB*SSP*KKN*128];      // V = x@wv+bv
__device__ float g_dsa[BB*SSP*KKN*256];    // [nei|grp]
__device__ float g_h[BB*SSP*KKN*256];      // hidden
__device__ float g_G[BB*SSP*SSP];          // GAM attention
__device__ float g_scv[BB*SSP*KKN*128];    // relu(bn(sc))
__device__ float g_w1T[256*256];
__device__ float g_w2T[128*256];
__device__ float g_scwT[128*64];
__device__ float g_wvT[128*128];
__device__ int   g_knn[BB*SSP*KKN];
__device__ float g_knnd[BB*SSP*KKN];

// ---------------- tf32 warp-MMA helpers ----------------
__device__ __forceinline__ uint32_t f2tf(float f) {
    uint32_t u; asm("cvt.rna.tf32.f32 %0, %1;" : "=r"(u) : "f"(f)); return u;
}
__device__ __forceinline__ void mma8(float* c, const uint32_t* a, const uint32_t* b) {
    asm volatile("mma.sync.aligned.m16n8k8.row.col.f32.tf32.tf32.f32 "
        "{%0,%1,%2,%3}, {%4,%5,%6,%7}, {%8,%9}, {%0,%1,%2,%3};"
        : "+f"(c[0]), "+f"(c[1]), "+f"(c[2]), "+f"(c[3])
        : "r"(a[0]), "r"(a[1]), "r"(a[2]), "r"(a[3]), "r"(b[0]), "r"(b[1]));
}

// Double-buffered, register-staged pipelined 128x128 tile GEMM.
// C = A[M,K](row-major) * B[N,K](row-major, i.e. B^T); 256 threads.
__device__ __forceinline__ void gemm_core(const float* __restrict__ A, int lda,
                                          const float* __restrict__ B, int ldb,
                                          int K, int row0, int col0,
                                          float (*acc)[8][4],
                                          uint32_t* As, uint32_t* Bs) {
    int t = threadIdx.x, lane = t & 31, wid = t >> 5;
    int wm = wid & 3, wn = wid >> 2;
    int gg = lane >> 2, tg = lane & 3;
    int lr[4], lc[4];
#pragma unroll
    for (int i = 0; i < 4; i++) { int lin = t + i*256; lr[i] = lin >> 3; lc[i] = (lin & 7)*4; }
    const float* Ab = A + (size_t)row0*lda;
    const float* Bb = B + (size_t)col0*ldb;
    float4 avr[4], bvr[4];
#pragma unroll
    for (int i = 0; i < 4; i++) {
        avr[i] = *(const float4*)(Ab + (size_t)lr[i]*lda + lc[i]);
        bvr[i] = *(const float4*)(Bb + (size_t)lr[i]*ldb + lc[i]);
    }
    int nsteps = K >> 5;
    for (int s = 0; s < nsteps; s++) {
        uint32_t* Ac = As + (s & 1)*DBUF;
        uint32_t* Bc = Bs + (s & 1)*DBUF;
#pragma unroll
        for (int i = 0; i < 4; i++) {
            uint32_t* ap = Ac + lr[i]*PITCH + lc[i];
            ap[0]=f2tf(avr[i].x); ap[1]=f2tf(avr[i].y); ap[2]=f2tf(avr[i].z); ap[3]=f2tf(avr[i].w);
            uint32_t* bp = Bc + lr[i]*PITCH + lc[i];
            bp[0]=f2tf(bvr[i].x); bp[1]=f2tf(bvr[i].y); bp[2]=f2tf(bvr[i].z); bp[3]=f2tf(bvr[i].w);
        }
        __syncthreads();
        if (s + 1 < nsteps) {
            int k0 = (s + 1)*32;
#pragma unroll
            for (int i = 0; i < 4; i++) {
                avr[i] = *(const float4*)(Ab + (size_t)lr[i]*lda + k0 + lc[i]);
                bvr[i] = *(const float4*)(Bb + (size_t)lr[i]*ldb + k0 + lc[i]);
            }
        }
#pragma unroll
        for (int kk = 0; kk < 32; kk += 8) {
            uint32_t af[2][4], bf[8][2];
#pragma unroll
            for (int mt = 0; mt < 2; mt++) {
                int rb = (wm*32 + mt*16 + gg)*PITCH + kk + tg;
                af[mt][0] = Ac[rb];
                af[mt][1] = Ac[rb + 8*PITCH];
                af[mt][2] = Ac[rb + 4];
                af[mt][3] = Ac[rb + 8*PITCH + 4];
            }
#pragma unroll
            for (int nt = 0; nt < 8; nt++) {
                int nb = (wn*64 + nt*8 + gg)*PITCH + kk + tg;
                bf[nt][0] = Bc[nb];
                bf[nt][1] = Bc[nb + 4];
            }
#pragma unroll
            for (int mt = 0; mt < 2; mt++)
#pragma unroll
                for (int nt = 0; nt < 8; nt++)
                    mma8(acc[mt][nt], af[mt], bf[nt]);
        }
    }
    __syncthreads();
}

#define EPI_VARS int t_=threadIdx.x, lane_=t_&31, wid_=t_>>5; \
    int wm_=wid_&3, wn_=wid_>>2, eg_=lane_>>2, etg_=lane_&3; (void)t_; (void)lane_;
#define MMA_SMEM extern __shared__ uint32_t smem_u[]; \
    uint32_t* As = smem_u; uint32_t* Bs = smem_u + 2*DBUF;

// ---------------- transposes ----------------
__global__ void __launch_bounds__(256) transposeX_kernel() {
    __shared__ float tile[32][33];
    int b = blockIdx.z;
    const float* src = g_x + (size_t)b*SSP*4096;
    float* dst = g_xT + (size_t)b*4096*SSP;
    int r0 = blockIdx.y*32, c0 = blockIdx.x*32;
    int tx = threadIdx.x & 31, ty = threadIdx.x >> 5;
#pragma unroll
    for (int i = 0; i < 32; i += 8)
        tile[ty+i][tx] = src[(size_t)(r0+ty+i)*4096 + c0+tx];
    __syncthreads();
#pragma unroll
    for (int i = 0; i < 32; i += 8)
        dst[(size_t)(c0+ty+i)*SSP + r0+tx] = tile[tx][ty+i];
}
__global__ void __launch_bounds__(256) transposeW_kernel(const float* __restrict__ src,
                                                         int R, int C, int sel) {
    __shared__ float tile[32][33];
    float* dst = sel == 0 ? g_w1T : (sel == 1 ? g_w2T : (sel == 2 ? g_scwT : g_wvT));
    int r0 = blockIdx.y*32, c0 = blockIdx.x*32;
    int tx = threadIdx.x & 31, ty = threadIdx.x >> 5;
#pragma unroll
    for (int i = 0; i < 32; i += 8)
        tile[ty+i][tx] = src[(size_t)(r0+ty+i)*C + c0+tx];
    __syncthreads();
#pragma unroll
    for (int i = 0; i < 32; i += 8)
        dst[(size_t)(c0+ty+i)*R + r0+tx] = tile[tx][ty+i];
}

// ---------------- 1. FPS ----------------
__global__ void __launch_bounds__(512) fps_kernel(const float* __restrict__ xyz,
                                                  const int* __restrict__ start,
                                                  float* __restrict__ centers) {
    __shared__ float sx[NNP], sy[NNP], sz[NNP];
    __shared__ float rv[16]; __shared__ int ri[16]; __shared__ int sfar;
    int b = blockIdx.x, tid = threadIdx.x;
    for (int i = tid; i < NNP; i += 512) {
        const float* p = xyz + ((size_t)b*NNP + i)*3;
        sx[i] = p[0]; sy[i] = p[1]; sz[i] = p[2];
    }
    float dist[8];
#pragma unroll
    for (int i = 0; i < 8; i++) dist[i] = 1e10f;
    __syncthreads();
    int far = start[b];
    for (int t = 0; t < SSP; t++) {
        float cx = sx[far], cy = sy[far], cz = sz[far];
        if (tid == 0) {
            float* o = centers + ((size_t)b*SSP + t)*3;
            o[0] = cx; o[1] = cy; o[2] = cz;
        }
        float bv = -1.0f; int bi = 0;
#pragma unroll
        for (int i = 0; i < 8; i++) {
            int p = tid + i*512;
            float dx = sx[p]-cx, dy = sy[p]-cy, dz = sz[p]-cz;
            float d = fminf(dist[i], dx*dx + dy*dy + dz*dz);
            dist[i] = d;
            if (d > bv) { bv = d; bi = p; }
        }
#pragma unroll
        for (int off = 16; off > 0; off >>= 1) {
            float ov = __shfl_down_sync(0xffffffffu, bv, off);
            int   oi = __shfl_down_sync(0xffffffffu, bi, off);
            if (ov > bv || (ov == bv && oi < bi)) { bv = ov; bi = oi; }
        }
        if ((tid & 31) == 0) { rv[tid>>5] = bv; ri[tid>>5] = bi; }
        __syncthreads();
        if (tid == 0) {
            float gv = rv[0]; int gi = ri[0];
#pragma unroll
            for (int w = 1; w < 16; w++)
                if (rv[w] > gv || (rv[w] == gv && ri[w] < gi)) { gv = rv[w]; gi = ri[w]; }
            sfar = gi;
        }
        __syncthreads();
        far = sfar;
    }
}

// ---------------- 2. KNN ----------------
__global__ void __launch_bounds__(128) knn_kernel(const float* __restrict__ xyz,
                                                  const float* __restrict__ centers) {
    __shared__ float sd2[KKN*128];
    __shared__ float swv[4]; __shared__ int swi[4];
    int s = blockIdx.x, b = blockIdx.y, tid = threadIdx.x;
    const float* c = centers + ((size_t)b*SSP + s)*3;
    float cx = c[0], cy = c[1], cz = c[2];
    float cn2 = cx*cx + cy*cy + cz*cz;
    float lv = FLT_MAX; int li = 0x7fffffff; int lslot = 0;
#pragma unroll
    for (int i = 0; i < KKN; i++) {
        int p = tid + i*128;
        const float* pp = xyz + ((size_t)b*NNP + p)*3;
        float px = pp[0], py = pp[1], pz = pp[2];
        float d2 = cn2 + (px*px + py*py + pz*pz) - 2.0f*(cx*px + cy*py + cz*pz);
        sd2[i*128 + tid] = d2;
        if (d2 < lv) { lv = d2; li = p; lslot = i; }
    }
    int lane = tid & 31, warp = tid >> 5;
    int obase = (b*SSP + s)*KKN;
    for (int r = 0; r < KKN; r++) {
        float bv = lv; int bi = li;
#pragma unroll
        for (int off = 16; off > 0; off >>= 1) {
            float ov = __shfl_xor_sync(0xffffffffu, bv, off);
            int   oi = __shfl_xor_sync(0xffffffffu, bi, off);
            if (ov < bv || (ov == bv && oi < bi)) { bv = ov; bi = oi; }
        }
        if (lane == 0) { swv[warp] = bv; swi[warp] = bi; }
        __syncthreads();
        float gv = swv[0]; int gi = swi[0];
#pragma unroll
        for (int w = 1; w < 4; w++)
            if (swv[w] < gv || (swv[w] == gv && swi[w] < gi)) { gv = swv[w]; gi = swi[w]; }
        if (tid == 0) { g_knn[obase + r] = gi; g_knnd[obase + r] = gv; }
        if (gi == li) {
            sd2[lslot*128 + tid] = FLT_MAX;
            lv = FLT_MAX; li = 0x7fffffff; lslot = 0;
#pragma unroll
            for (int i = 0; i < KKN; i++) {
                float d = sd2[i*128 + tid];
                if (d < lv) { lv = d; li = tid + i*128; lslot = i; }
            }
        }
        __syncthreads();
    }
}

// ---------------- 3. group + pos-embed MLP ----------------
__global__ void __launch_bounds__(256) grouppos_kernel(
    const float* __restrict__ xyz, const float* __restrict__ points,
    const float* __restrict__ centers,
    const float* __restrict__ w1, const float* __restrict__ b1, const float* __restrict__ bn1,
    const float* __restrict__ w2, const float* __restrict__ b2, const float* __restrict__ bn2) {
    __shared__ float sw1[320], sw2[2048];
    __shared__ float sA1[32], sC1[32], sA2[64], sC2[64];
    int tid = threadIdx.x;
    for (int i = tid; i < 320; i += 256) sw1[i] = w1[i];
    for (int i = tid; i < 2048; i += 256) sw2[i] = w2[i];
    if (tid < 32) {
        float a = bn1[tid] * rsqrtf(bn1[96+tid] + EPSV);
        sA1[tid] = a; sC1[tid] = a*(b1[tid]-bn1[64+tid]) + bn1[32+tid];
    }
    if (tid < 64) {
        float a = bn2[tid] * rsqrtf(bn2[192+tid] + EPSV);
        sA2[tid] = a; sC2[tid] = a*(b2[tid]-bn2[128+tid]) + bn2[64+tid];
    }
    __syncthreads();
    int gid = blockIdx.x*256 + tid;
    int b = gid >> 14;
    int idx = g_knn[gid];
    float dd = g_knnd[gid];
    const float* c = centers + (size_t)(gid >> 5)*3;
    float cx = c[0], cy = c[1], cz = c[2];
    const float* pp = xyz + ((size_t)b*NNP + idx)*3;
    float px = pp[0], py = pp[1], pz = pp[2];
    float f[10] = {cx, cy, cz, px, py, pz, px-cx, py-cy, pz-cz, dd};
    float h[32];
#pragma unroll
    for (int cc = 0; cc < 32; cc++) {
        float acc = 0.f;
#pragma unroll
        for (int i = 0; i < 10; i++) acc += f[i]*sw1[i*32+cc];
        h[cc] = fmaxf(acc*sA1[cc] + sC1[cc], 0.f);
    }
    float* xo = g_x + (size_t)gid*128;
#pragma unroll
    for (int cc = 0; cc < 64; cc++) {
        float acc = 0.f;
#pragma unroll
        for (int i = 0; i < 32; i++) acc += h[i]*sw2[i*64+cc];
        xo[cc] = fmaxf(acc*sA2[cc] + sC2[cc], 0.f);
    }
    const float* pr = points + ((size_t)b*NNP + idx)*64;
#pragma unroll
    for (int j = 0; j < 64; j += 4)
        *(float4*)(xo + 64 + j) = *(const float4*)(pr + j);
}

// ---------------- 4a. V = x@wv + bv (tf32 MMA) ----------------
__global__ void __launch_bounds__(256) vproj_mma(const float* __restrict__ bv) {
    MMA_SMEM
    int row0 = blockIdx.x*128;
    float acc[2][8][4] = {};
    gemm_core(g_x, 128, g_wvT, 128, 128, row0, 0, acc, As, Bs);
    EPI_VARS
#pragma unroll
    for (int mt = 0; mt < 2; mt++)
#pragma unroll
        for (int nt = 0; nt < 8; nt++) {
            int r = row0 + wm_*32 + mt*16 + eg_;
            int c = wn_*64 + nt*8 + 2*etg_;
            float b0 = bv[c], b1 = bv[c+1];
            *(float2*)(g_v + (size_t)r*128 + c)     = make_float2(acc[mt][nt][0]+b0, acc[mt][nt][1]+b1);
            *(float2*)(g_v + (size_t)(r+8)*128 + c) = make_float2(acc[mt][nt][2]+b0, acc[mt][nt][3]+b1);
        }
}

// ---------------- 4b. neighbor self-attention -> dsa[:,0:128] ----------------
__global__ void __launch_bounds__(128) nsa_kernel(
    const float* __restrict__ wq, const float* __restrict__ bq,
    const float* __restrict__ wk, const float* __restrict__ bk,
    const float* __restrict__ gam) {
    __shared__ float xs[32][128];
    __shared__ float qs[32][16], ks2[32][16];
    __shared__ float at[32][32];
    int g = blockIdx.x, t = threadIdx.x;
    const float* xg = g_x + (size_t)g*4096;
#pragma unroll
    for (int i = 0; i < 8; i++)
        *(float4*)(&xs[0][0] + t*4 + i*512) = *(const float4*)(xg + t*4 + i*512);
    __syncthreads();
    {
        int r = t >> 2, c0 = (t & 3)*4;
        float4 aq = *(const float4*)(bq + c0);
        float4 ak = *(const float4*)(bk + c0);
        for (int i = 0; i < 128; i++) {
            float xv = xs[r][i];
            float4 wq4 = *(const float4*)(wq + i*16 + c0);
            float4 wk4 = *(const float4*)(wk + i*16 + c0);
            aq.x += xv*wq4.x; aq.y += xv*wq4.y; aq.z += xv*wq4.z; aq.w += xv*wq4.w;
            ak.x += xv*wk4.x; ak.y += xv*wk4.y; ak.z += xv*wk4.z; ak.w += xv*wk4.w;
        }
        *(float4*)&qs[r][c0] = aq; *(float4*)&ks2[r][c0] = ak;
    }
    __syncthreads();
    {
        int r = t >> 2, j0 = (t & 3)*8;
        float4 q0 = *(float4*)&qs[r][0], q1 = *(float4*)&qs[r][4];
        float4 q2 = *(float4*)&qs[r][8], q3 = *(float4*)&qs[r][12];
        float sc[8];
#pragma unroll
        for (int jj = 0; jj < 8; jj++) {
            int j = j0 + jj;
            float4 k0 = *(float4*)&ks2[j][0], k1 = *(float4*)&ks2[j][4];
            float4 k2 = *(float4*)&ks2[j][8], k3 = *(float4*)&ks2[j][12];
            sc[jj] = q0.x*k0.x + q0.y*k0.y + q0.z*k0.z + q0.w*k0.w
                   + q1.x*k1.x + q1.y*k1.y + q1.z*k1.z + q1.w*k1.w
                   + q2.x*k2.x + q2.y*k2.y + q2.z*k2.z + q2.w*k2.w
                   + q3.x*k3.x + q3.y*k3.y + q3.z*k3.z + q3.w*k3.w;
        }
        float mx = sc[0];
#pragma unroll
        for (int jj = 1; jj < 8; jj++) mx = fmaxf(mx, sc[jj]);
        mx = fmaxf(mx, __shfl_xor_sync(0xffffffffu, mx, 1));
        mx = fmaxf(mx, __shfl_xor_sync(0xffffffffu, mx, 2));
        float sum = 0.f;
#pragma unroll
        for (int jj = 0; jj < 8; jj++) { sc[jj] = expf(sc[jj]-mx); sum += sc[jj]; }
        sum += __shfl_xor_sync(0xffffffffu, sum, 1);
        sum += __shfl_xor_sync(0xffffffffu, sum, 2);
#pragma unroll
        for (int jj = 0; jj < 8; jj++) at[r][j0+jj] = sc[jj]/sum;
    }
    __syncthreads();
    float vreg[32];
#pragma unroll
    for (int k = 0; k < 32; k++)
        vreg[k] = g_v[((size_t)g*32 + k)*128 + t];
    float accn[32];
#pragma unroll
    for (int k = 0; k < 32; k++) accn[k] = 0.f;
    for (int j4 = 0; j4 < 8; j4++) {
        float v0 = vreg[j4*4+0], v1 = vreg[j4*4+1], v2 = vreg[j4*4+2], v3 = vreg[j4*4+3];
#pragma unroll
        for (int k = 0; k < 32; k++) {
            float4 a4 = *(float4*)&at[k][j4*4];
            accn[k] += a4.x*v0 + a4.y*v1 + a4.z*v2 + a4.w*v3;
        }
    }
    float gm = gam[0];
#pragma unroll
    for (int k = 0; k < 32; k++)
        g_dsa[((size_t)g*32 + k)*256 + t] = gm*accn[k] + xs[k][t];
}

// ---------------- 5. GAM G = F F^T (tf32 MMA) ----------------
__global__ void __launch_bounds__(256) gam1_mma() {
    MMA_SMEM
    int b = blockIdx.z;
    const float* F = g_x + (size_t)b*SSP*4096;
    int row0 = blockIdx.y*128, col0 = blockIdx.x*128;
    float acc[2][8][4] = {};
    gemm_core(F, 4096, F, 4096, 4096, row0, col0, acc, As, Bs);
    float* Gp = g_G + (size_t)b*SSP*SSP;
    EPI_VARS
#pragma unroll
    for (int mt = 0; mt < 2; mt++)
#pragma unroll
        for (int nt = 0; nt < 8; nt++) {
            int r = row0 + wm_*32 + mt*16 + eg_;
            int c = col0 + wn_*64 + nt*8 + 2*etg_;
            *(float2*)(Gp + (size_t)r*SSP + c)     = make_float2(acc[mt][nt][0], acc[mt][nt][1]);
            *(float2*)(Gp + (size_t)(r+8)*SSP + c) = make_float2(acc[mt][nt][2], acc[mt][nt][3]);
        }
}

// ---------------- 6. softmax over G rows ----------------
__global__ void __launch_bounds__(256) gsoftmax_kernel() {
    __shared__ float red[8];
    int row = blockIdx.x, t = threadIdx.x;
    float* p = g_G + (size_t)row*SSP;
    float a = p[t], b = p[t+256];
    float mx = fmaxf(a, b);
#pragma unroll
    for (int off = 16; off > 0; off >>= 1) mx = fmaxf(mx, __shfl_xor_sync(0xffffffffu, mx, off));
    if ((t & 31) == 0) red[t>>5] = mx;
    __syncthreads();
    mx = red[0];
#pragma unroll
    for (int w = 1; w < 8; w++) mx = fmaxf(mx, red[w]);
    float e1 = expf(a-mx), e2 = expf(b-mx);
    float s = e1 + e2;
#pragma unroll
    for (int off = 16; off > 0; off >>= 1) s += __shfl_xor_sync(0xffffffffu, s, off);
    __syncthreads();
    if ((t & 31) == 0) red[t>>5] = s;
    __syncthreads();
    s = red[0];
#pragma unroll
    for (int w = 1; w < 8; w++) s += red[w];
    p[t] = e1/s; p[t+256] = e2/s;
}

// ---------------- 7. grp = gamma*G@F + x -> dsa[:,128:256] (tf32 MMA) ----------------
__global__ void __launch_bounds__(256) gam2_mma(const float* __restrict__ gam) {
    MMA_SMEM
    int b = blockIdx.z;
    const float* A = g_G + (size_t)b*SSP*SSP;
    const float* Bm = g_xT + (size_t)b*4096*SSP;
    int row0 = blockIdx.y*128, col0 = blockIdx.x*128;
    float acc[2][8][4] = {};
    gemm_core(A, SSP, Bm, SSP, SSP, row0, col0, acc, As, Bs);
    float gm = gam[0];
    int kidx = blockIdx.x;   // col0 = kidx*128
    EPI_VARS
#pragma unroll
    for (int mt = 0; mt < 2; mt++)
#pragma unroll
        for (int nt = 0; nt < 8; nt++) {
            int r = row0 + wm_*32 + mt*16 + eg_;
            int c = col0 + wn_*64 + nt*8 + 2*etg_;
            int d = c & 127;
            const float* xr1 = g_x + ((size_t)b*SSP + r)*4096 + c;
            const float* xr2 = g_x + ((size_t)b*SSP + r + 8)*4096 + c;
            float* o1 = g_dsa + ((size_t)((b*SSP + r)*KKN) + kidx)*256 + 128 + d;
            float* o2 = g_dsa + ((size_t)((b*SSP + r + 8)*KKN) + kidx)*256 + 128 + d;
            *(float2*)o1 = make_float2(gm*acc[mt][nt][0] + xr1[0], gm*acc[mt][nt][1] + xr1[1]);
            *(float2*)o2 = make_float2(gm*acc[mt][nt][2] + xr2[0], gm*acc[mt][nt][3] + xr2[1]);
        }
}

// ---------------- 8. h = relu(bn1(dsa@w1+b1)) (tf32 MMA) ----------------
__global__ void __launch_bounds__(256) head1_mma(const float* __restrict__ b1,
                                                 const float* __restrict__ bn1) {
    MMA_SMEM
    int row0 = blockIdx.y*128, col0 = blockIdx.x*128;
    float acc[2][8][4] = {};
    gemm_core(g_dsa, 256, g_w1T, 256, 256, row0, col0, acc, As, Bs);
    EPI_VARS
#pragma unroll
    for (int mt = 0; mt < 2; mt++)
#pragma unroll
        for (int nt = 0; nt < 8; nt++) {
            int r = row0 + wm_*32 + mt*16 + eg_;
            int c = col0 + wn_*64 + nt*8 + 2*etg_;
            float a0 = bn1[c]*rsqrtf(bn1[768+c] + EPSV);
            float c0v = a0*(b1[c]-bn1[512+c]) + bn1[256+c];
            float a1 = bn1[c+1]*rsqrtf(bn1[768+c+1] + EPSV);
            float c1v = a1*(b1[c+1]-bn1[512+c+1]) + bn1[256+c+1];
            *(float2*)(g_h + (size_t)r*256 + c) = make_float2(
                fmaxf(acc[mt][nt][0]*a0 + c0v, 0.f), fmaxf(acc[mt][nt][1]*a1 + c1v, 0.f));
            *(float2*)(g_h + (size_t)(r+8)*256 + c) = make_float2(
                fmaxf(acc[mt][nt][2]*a0 + c0v, 0.f), fmaxf(acc[mt][nt][3]*a1 + c1v, 0.f));
        }
}

// ---------------- 9. scv = relu(bn(pts@scw+scb)) (tf32 MMA) ----------------
__global__ void __launch_bounds__(256) sc_mma(const float* __restrict__ scb,
                                              const float* __restrict__ scbn) {
    MMA_SMEM
    int row0 = blockIdx.x*128;
    float acc[2][8][4] = {};
    gemm_core(g_x + 64, 128, g_scwT, 64, 64, row0, 0, acc, As, Bs);
    EPI_VARS
#pragma unroll
    for (int mt = 0; mt < 2; mt++)
#pragma unroll
        for (int nt = 0; nt < 8; nt++) {
            int r = row0 + wm_*32 + mt*16 + eg_;
            int c = wn_*64 + nt*8 + 2*etg_;
            float a0 = scbn[c]*rsqrtf(scbn[384+c] + EPSV);
            float c0v = a0*(scb[c]-scbn[256+c]) + scbn[128+c];
            float a1 = scbn[c+1]*rsqrtf(scbn[384+c+1] + EPSV);
            float c1v = a1*(scb[c+1]-scbn[256+c+1]) + scbn[128+c+1];
            *(float2*)(g_scv + (size_t)r*128 + c) = make_float2(
                fmaxf(acc[mt][nt][0]*a0 + c0v, 0.f), fmaxf(acc[mt][nt][1]*a1 + c1v, 0.f));
            *(float2*)(g_scv + (size_t)(r+8)*128 + c) = make_float2(
                fmaxf(acc[mt][nt][2]*a0 + c0v, 0.f), fmaxf(acc[mt][nt][3]*a1 + c1v, 0.f));
        }
}

// ---------------- 10. fused: bn2(h@w2+b2)+scv, relu, max over K -> out ----------------
__global__ void __launch_bounds__(256) head2max_mma(const float* __restrict__ b2,
                                                    const float* __restrict__ bn2,
                                                    float* __restrict__ outp) {
    MMA_SMEM
    int row0 = blockIdx.x*128;
    float acc[2][8][4] = {};
    gemm_core(g_h, 256, g_w2T, 256, 256, row0, 0, acc, As, Bs);
    EPI_VARS
    float tmax[8][2];
#pragma unroll
    for (int nt = 0; nt < 8; nt++) {
        int c = wn_*64 + nt*8 + 2*etg_;
        float a0 = bn2[c]*rsqrtf(bn2[384+c] + EPSV);
        float c0v = a0*(b2[c]-bn2[256+c]) + bn2[128+c];
        float a1 = bn2[c+1]*rsqrtf(bn2[384+c+1] + EPSV);
        float c1v = a1*(b2[c+1]-bn2[256+c+1]) + bn2[128+c+1];
        float m0 = -FLT_MAX, m1 = -FLT_MAX;
#pragma unroll
        for (int mt = 0; mt < 2; mt++) {
            int r = row0 + wm_*32 + mt*16 + eg_;
            const float* s1 = g_scv + (size_t)r*128 + c;
            const float* s2 = g_scv + (size_t)(r+8)*128 + c;
            m0 = fmaxf(m0, fmaxf(acc[mt][nt][0]*a0 + c0v + s1[0], 0.f));
            m1 = fmaxf(m1, fmaxf(acc[mt][nt][1]*a1 + c1v + s1[1], 0.f));
            m0 = fmaxf(m0, fmaxf(acc[mt][nt][2]*a0 + c0v + s2[0], 0.f));
            m1 = fmaxf(m1, fmaxf(acc[mt][nt][3]*a1 + c1v + s2[1], 0.f));
        }
        tmax[nt][0] = m0; tmax[nt][1] = m1;
    }
    // reduce max over eg (lane bits 2..4)
#pragma unroll
    for (int off = 4; off <= 16; off <<= 1)
#pragma unroll
        for (int nt = 0; nt < 8; nt++) {
            tmax[nt][0] = fmaxf(tmax[nt][0], __shfl_xor_sync(0xffffffffu, tmax[nt][0], off));
            tmax[nt][1] = fmaxf(tmax[nt][1], __shfl_xor_sync(0xffffffffu, tmax[nt][1], off));
        }
    if (eg_ == 0) {
        int gq = blockIdx.x*4 + wm_;
#pragma unroll
        for (int nt = 0; nt < 8; nt++) {
            int c = wn_*64 + nt*8 + 2*etg_;
            outp[12288 + (size_t)gq*128 + c]     = tmax[nt][0];
            outp[12288 + (size_t)gq*128 + c + 1] = tmax[nt][1];
        }
    }
}

extern "C" void kernel_launch(void* const* d_in, const int* in_sizes, int n_in,
                              void* d_out, int out_size) {
    const float* xyz     = (const float*)d_in[0];
    const float* points  = (const float*)d_in[1];
    const int*   fstart  = (const int*)d_in[2];
    const float* pos_w1  = (const float*)d_in[3];
    const float* pos_b1  = (const float*)d_in[4];
    const float* pos_bn1 = (const float*)d_in[5];
    const float* pos_w2  = (const float*)d_in[6];
    const float* pos_b2  = (const float*)d_in[7];
    const float* pos_bn2 = (const float*)d_in[8];
    const float* nsa_wq  = (const float*)d_in[9];
    const float* nsa_bq  = (const float*)d_in[10];
    const float* nsa_wk  = (const float*)d_in[11];
    const float* nsa_bk  = (const float*)d_in[12];
    const float* nsa_wv  = (const float*)d_in[13];
    const float* nsa_bv  = (const float*)d_in[14];
    const float* nsa_g   = (const float*)d_in[15];
    const float* gam_g   = (const float*)d_in[16];
    const float* cat_w1  = (const float*)d_in[17];
    const float* cat_b1  = (const float*)d_in[18];
    const float* cat_bn1 = (const float*)d_in[19];
    const float* cat_w2  = (const float*)d_in[20];
    const float* cat_b2  = (const float*)d_in[21];
    const float* cat_bn2 = (const float*)d_in[22];
    const float* sc_w    = (const float*)d_in[23];
    const float* sc_b    = (const float*)d_in[24];
    const float* sc_bn   = (const float*)d_in[25];
    float* outp = (float*)d_out;

    cudaFuncSetAttribute(vproj_mma,    cudaFuncAttributeMaxDynamicSharedMemorySize, DYNSM);
    cudaFuncSetAttribute(gam1_mma,     cudaFuncAttributeMaxDynamicSharedMemorySize, DYNSM);
    cudaFuncSetAttribute(gam2_mma,     cudaFuncAttributeMaxDynamicSharedMemorySize, DYNSM);
    cudaFuncSetAttribute(head1_mma,    cudaFuncAttributeMaxDynamicSharedMemorySize, DYNSM);
    cudaFuncSetAttribute(sc_mma,       cudaFuncAttributeMaxDynamicSharedMemorySize, DYNSM);
    cudaFuncSetAttribute(head2max_mma, cudaFuncAttributeMaxDynamicSharedMemorySize, DYNSM);

    fps_kernel<<<BB, 512>>>(xyz, fstart, outp);
    knn_kernel<<<dim3(SSP, BB), 128>>>(xyz, outp);
    grouppos_kernel<<<512, 256>>>(xyz, points, outp, pos_w1, pos_b1, pos_bn1,
                                  pos_w2, pos_b2, pos_bn2);
    transposeW_kernel<<<dim3(8, 8), 256>>>(cat_w1, 256, 256, 0);
    transposeW_kernel<<<dim3(4, 8), 256>>>(cat_w2, 256, 128, 1);
    transposeW_kernel<<<dim3(4, 2), 256>>>(sc_w, 64, 128, 2);
    transposeW_kernel<<<dim3(4, 4), 256>>>(nsa_wv, 128, 128, 3);
    transposeX_kernel<<<dim3(128, 16, BB), 256>>>();
    vproj_mma<<<1024, 256, DYNSM>>>(nsa_bv);
    nsa_kernel<<<BB*SSP, 128>>>(nsa_wq, nsa_bq, nsa_wk, nsa_bk, nsa_g);
    gam1_mma<<<dim3(4, 4, BB), 256, DYNSM>>>();
    gsoftmax_kernel<<<BB*SSP, 256>>>();
    gam2_mma<<<dim3(32, 4, BB), 256, DYNSM>>>(gam_g);
    sc_mma<<<1024, 256, DYNSM>>>(sc_b, sc_bn);
    head1_mma<<<dim3(2, 1024), 256, DYNSM>>>(cat_b1, cat_bn1);
    head2max_mma<<<1024, 256, DYNSM>>>(cat_b2, cat_bn2, outp);
}

// round 8
// speedup vs baseline: 2.1602x; 1.1053x over previous
#include <cuda_runtime.h>
#include <stdint.h>
#include <math.h>
#include <float.h>

#define BB 8
#define NNP 4096
#define SSP 512
#define KKN 32
#define EPSV 1e-5f
#define PITCH 36
#define DBUF (128*PITCH)
#define DYNSM (4*DBUF*4)

// scratch (__device__ globals — no allocation allowed)
__device__ float g_x[BB*SSP*KKN*128];      // x = [pos|pts], tf32-rounded
__device__ float g_v[BB*SSP*KKN*128];      // V = x@wv+bv
__device__ float g_dsa[BB*SSP*KKN*256];    // [nei|grp], tf32-rounded
__device__ float g_h[BB*SSP*KKN*256];      // hidden, tf32-rounded
__device__ float g_G[BB*SSP*SSP];          // GAM attention, tf32-rounded after softmax
__device__ float g_scv[BB*SSP*KKN*128];    // relu(bn(sc))
__device__ float g_w1R[256*256];           // tf32-rounded weights (original layouts)
__device__ float g_w2R[256*128];
__device__ float g_wvR[128*128];
__device__ float g_scwR[64*128];
__device__ int   g_knn[BB*SSP*KKN];
__device__ float g_knnd[BB*SSP*KKN];

// ---------------- tf32 helpers ----------------
__device__ __forceinline__ uint32_t f2tf(float f) {
    uint32_t u; asm("cvt.rna.tf32.f32 %0, %1;" : "=r"(u) : "f"(f)); return u;
}
__device__ __forceinline__ float rndtf(float f) { return __uint_as_float(f2tf(f)); }
__device__ __forceinline__ void mma8(float* c, const uint32_t* a, const uint32_t* b) {
    asm volatile("mma.sync.aligned.m16n8k8.row.col.f32.tf32.tf32.f32 "
        "{%0,%1,%2,%3}, {%4,%5,%6,%7}, {%8,%9}, {%0,%1,%2,%3};"
        : "+f"(c[0]), "+f"(c[1]), "+f"(c[2]), "+f"(c[3])
        : "r"(a[0]), "r"(a[1]), "r"(a[2]), "r"(a[3]), "r"(b[0]), "r"(b[1]));
}

#define GEMM_COMPUTE(Ac, Bc) \
    _Pragma("unroll") \
    for (int kk = 0; kk < 32; kk += 8) { \
        uint32_t af[2][4], bf[8][2]; \
        _Pragma("unroll") \
        for (int mt = 0; mt < 2; mt++) { \
            int rb = (wm*32 + mt*16 + gg)*PITCH + kk + tg; \
            af[mt][0] = (Ac)[rb]; \
            af[mt][1] = (Ac)[rb + 8*PITCH]; \
            af[mt][2] = (Ac)[rb + 4]; \
            af[mt][3] = (Ac)[rb + 8*PITCH + 4]; \
        } \
        _Pragma("unroll") \
        for (int nt = 0; nt < 8; nt++) { \
            int nb = (wn*64 + nt*8 + gg)*PITCH + kk + tg; \
            bf[nt][0] = (Bc)[nb]; \
            bf[nt][1] = (Bc)[nb + 4]; \
        } \
        _Pragma("unroll") \
        for (int mt = 0; mt < 2; mt++) \
            _Pragma("unroll") \
            for (int nt = 0; nt < 8; nt++) \
                mma8(acc[mt][nt], af[mt], bf[nt]); \
    }

// C = A[M,K](row-major) * B[N,K](row-major = B^T); inputs pre-rounded to tf32.
__device__ __forceinline__ void gemm_core(const float* __restrict__ A, int lda,
                                          const float* __restrict__ B, int ldb,
                                          int K, int row0, int col0,
                                          float (*acc)[8][4],
                                          uint32_t* As, uint32_t* Bs) {
    int t = threadIdx.x, lane = t & 31, wid = t >> 5;
    int wm = wid & 3, wn = wid >> 2;
    int gg = lane >> 2, tg = lane & 3;
    int lr[4], lc[4];
#pragma unroll
    for (int i = 0; i < 4; i++) { int lin = t + i*256; lr[i] = lin >> 3; lc[i] = (lin & 7)*4; }
    const float* Ab = A + (size_t)row0*lda;
    const float* Bb = B + (size_t)col0*ldb;
    float4 avr[4], bvr[4];
#pragma unroll
    for (int i = 0; i < 4; i++) {
        avr[i] = *(const float4*)(Ab + (size_t)lr[i]*lda + lc[i]);
        bvr[i] = *(const float4*)(Bb + (size_t)lr[i]*ldb + lc[i]);
    }
    int nsteps = K >> 5;
    for (int s = 0; s < nsteps; s++) {
        uint32_t* Ac = As + (s & 1)*DBUF;
        uint32_t* Bc = Bs + (s & 1)*DBUF;
#pragma unroll
        for (int i = 0; i < 4; i++) {
            *(float4*)(Ac + lr[i]*PITCH + lc[i]) = avr[i];
            *(float4*)(Bc + lr[i]*PITCH + lc[i]) = bvr[i];
        }
        __syncthreads();
        if (s + 1 < nsteps) {
            int k0 = (s + 1)*32;
#pragma unroll
            for (int i = 0; i < 4; i++) {
                avr[i] = *(const float4*)(Ab + (size_t)lr[i]*lda + k0 + lc[i]);
                bvr[i] = *(const float4*)(Bb + (size_t)lr[i]*ldb + k0 + lc[i]);
            }
        }
        GEMM_COMPUTE(Ac, Bc)
    }
    __syncthreads();
}

// C = A[M,K](row-major) * Bsrc[K,N](k-major rows); inputs pre-rounded to tf32.
__device__ __forceinline__ void gemm_coreKB(const float* __restrict__ A, int lda,
                                            const float* __restrict__ Bsrc, int ldb,
                                            int K, int row0, int col0,
                                            float (*acc)[8][4],
                                            uint32_t* As, uint32_t* Bs) {
    int t = threadIdx.x, lane = t & 31, wid = t >> 5;
    int wm = wid & 3, wn = wid >> 2;
    int gg = lane >> 2, tg = lane & 3;
    int lr[4], lc[4], bn[4], bk[4];
#pragma unroll
    for (int i = 0; i < 4; i++) {
        int lin = t + i*256;
        lr[i] = lin >> 3; lc[i] = (lin & 7)*4;
        bn[i] = lin & 127; bk[i] = (lin >> 7)*4;
    }
    const float* Ab = A + (size_t)row0*lda;
    float4 avr[4]; float bvr[4][4];
#pragma unroll
    for (int i = 0; i < 4; i++) {
        avr[i] = *(const float4*)(Ab + (size_t)lr[i]*lda + lc[i]);
        const float* bp = Bsrc + (size_t)bk[i]*ldb + col0 + bn[i];
#pragma unroll
        for (int j = 0; j < 4; j++) bvr[i][j] = bp[(size_t)j*ldb];
    }
    int nsteps = K >> 5;
    for (int s = 0; s < nsteps; s++) {
        uint32_t* Ac = As + (s & 1)*DBUF;
        uint32_t* Bc = Bs + (s & 1)*DBUF;
#pragma unroll
        for (int i = 0; i < 4; i++) {
            *(float4*)(Ac + lr[i]*PITCH + lc[i]) = avr[i];
            *(float4*)(Bc + bn[i]*PITCH + bk[i]) =
                make_float4(bvr[i][0], bvr[i][1], bvr[i][2], bvr[i][3]);
        }
        __syncthreads();
        if (s + 1 < nsteps) {
            int k0 = (s + 1)*32;
#pragma unroll
            for (int i = 0; i < 4; i++) {
                avr[i] = *(const float4*)(Ab + (size_t)lr[i]*lda + k0 + lc[i]);
                const float* bp = Bsrc + (size_t)(k0 + bk[i])*ldb + col0 + bn[i];
#pragma unroll
                for (int j = 0; j < 4; j++) bvr[i][j] = bp[(size_t)j*ldb];
            }
        }
        GEMM_COMPUTE(Ac, Bc)
    }
    __syncthreads();
}

#define EPI_VARS int t_=threadIdx.x, lane_=t_&31, wid_=t_>>5; \
    int wm_=wid_&3, wn_=wid_>>2, eg_=lane_>>2, etg_=lane_&3; (void)t_; (void)lane_;
#define MMA_SMEM extern __shared__ uint32_t smem_u[]; \
    uint32_t* As = smem_u; uint32_t* Bs = smem_u + 2*DBUF;

// ---------------- 0. round weights to tf32 (original layouts) ----------------
__global__ void __launch_bounds__(256) prep_round(const float* __restrict__ w1,
                                                  const float* __restrict__ w2,
                                                  const float* __restrict__ wv,
                                                  const float* __restrict__ scw) {
    int t = blockIdx.x*256 + threadIdx.x;
    if (t < 65536) g_w1R[t] = rndtf(w1[t]);
    else if (t < 98304) g_w2R[t-65536] = rndtf(w2[t-65536]);
    else if (t < 114688) g_wvR[t-98304] = rndtf(wv[t-98304]);
    else if (t < 122880) g_scwR[t-114688] = rndtf(scw[t-114688]);
}

// ---------------- 1. FPS ----------------
__global__ void __launch_bounds__(512) fps_kernel(const float* __restrict__ xyz,
                                                  const int* __restrict__ start,
                                                  float* __restrict__ centers) {
    __shared__ float sx[NNP], sy[NNP], sz[NNP];
    __shared__ float rv[16]; __shared__ int ri[16]; __shared__ int sfar;
    int b = blockIdx.x, tid = threadIdx.x;
    for (int i = tid; i < NNP; i += 512) {
        const float* p = xyz + ((size_t)b*NNP + i)*3;
        sx[i] = p[0]; sy[i] = p[1]; sz[i] = p[2];
    }
    float dist[8];
#pragma unroll
    for (int i = 0; i < 8; i++) dist[i] = 1e10f;
    __syncthreads();
    int far = start[b];
    for (int t = 0; t < SSP; t++) {
        float cx = sx[far], cy = sy[far], cz = sz[far];
        if (tid == 0) {
            float* o = centers + ((size_t)b*SSP + t)*3;
            o[0] = cx; o[1] = cy; o[2] = cz;
        }
        float bv = -1.0f; int bi = 0;
#pragma unroll
        for (int i = 0; i < 8; i++) {
            int p = tid + i*512;
            float dx = sx[p]-cx, dy = sy[p]-cy, dz = sz[p]-cz;
            float d = fminf(dist[i], dx*dx + dy*dy + dz*dz);
            dist[i] = d;
            if (d > bv) { bv = d; bi = p; }
        }
#pragma unroll
        for (int off = 16; off > 0; off >>= 1) {
            float ov = __shfl_down_sync(0xffffffffu, bv, off);
            int   oi = __shfl_down_sync(0xffffffffu, bi, off);
            if (ov > bv || (ov == bv && oi < bi)) { bv = ov; bi = oi; }
        }
        if ((tid & 31) == 0) { rv[tid>>5] = bv; ri[tid>>5] = bi; }
        __syncthreads();
        if (tid < 32) {
            float gv = (tid < 16) ? rv[tid] : -3.0f;
            int   gi = (tid < 16) ? ri[tid] : 0x7fffffff;
#pragma unroll
            for (int off = 8; off > 0; off >>= 1) {
                float ov = __shfl_down_sync(0xffffffffu, gv, off);
                int   oi = __shfl_down_sync(0xffffffffu, gi, off);
                if (ov > gv || (ov == gv && oi < gi)) { gv = ov; gi = oi; }
            }
            if (tid == 0) sfar = gi;
        }
        __syncthreads();
        far = sfar;
    }
}

// ---------------- 2. KNN ----------------
__global__ void __launch_bounds__(128) knn_kernel(const float* __restrict__ xyz,
                                                  const float* __restrict__ centers) {
    __shared__ float sd2[KKN*128];
    __shared__ float swv[4]; __shared__ int swi[4];
    int s = blockIdx.x, b = blockIdx.y, tid = threadIdx.x;
    const float* c = centers + ((size_t)b*SSP + s)*3;
    float cx = c[0], cy = c[1], cz = c[2];
    float cn2 = cx*cx + cy*cy + cz*cz;
    float lv = FLT_MAX; int li = 0x7fffffff; int lslot = 0;
#pragma unroll
    for (int i = 0; i < KKN; i++) {
        int p = tid + i*128;
        const float* pp = xyz + ((size_t)b*NNP + p)*3;
        float px = pp[0], py = pp[1], pz = pp[2];
        float d2 = cn2 + (px*px + py*py + pz*pz) - 2.0f*(cx*px + cy*py + cz*pz);
        sd2[i*128 + tid] = d2;
        if (d2 < lv) { lv = d2; li = p; lslot = i; }
    }
    int lane = tid & 31, warp = tid >> 5;
    int obase = (b*SSP + s)*KKN;
    for (int r = 0; r < KKN; r++) {
        float bv = lv; int bi = li;
#pragma unroll
        for (int off = 16; off > 0; off >>= 1) {
            float ov = __shfl_xor_sync(0xffffffffu, bv, off);
            int   oi = __shfl_xor_sync(0xffffffffu, bi, off);
            if (ov < bv || (ov == bv && oi < bi)) { bv = ov; bi = oi; }
        }
        if (lane == 0) { swv[warp] = bv; swi[warp] = bi; }
        __syncthreads();
        float gv = swv[0]; int gi = swi[0];
#pragma unroll
        for (int w = 1; w < 4; w++)
            if (swv[w] < gv || (swv[w] == gv && swi[w] < gi)) { gv = swv[w]; gi = swi[w]; }
        if (tid == 0) { g_knn[obase + r] = gi; g_knnd[obase + r] = gv; }
        if (gi == li) {
            sd2[lslot*128 + tid] = FLT_MAX;
            lv = FLT_MAX; li = 0x7fffffff; lslot = 0;
#pragma unroll
            for (int i = 0; i < KKN; i++) {
                float d = sd2[i*128 + tid];
                if (d < lv) { lv = d; li = tid + i*128; lslot = i; }
            }
        }
        __syncthreads();
    }
}

// ---------------- 3. group + pos-embed MLP (writes tf32-rounded x) ----------------
__global__ void __launch_bounds__(256) grouppos_kernel(
    const float* __restrict__ xyz, const float* __restrict__ points,
    const float* __restrict__ centers,
    const float* __restrict__ w1, const float* __restrict__ b1, const float* __restrict__ bn1,
    const float* __restrict__ w2, const float* __restrict__ b2, const float* __restrict__ bn2) {
    __shared__ float sw1[320], sw2[2048];
    __shared__ float sA1[32], sC1[32], sA2[64], sC2[64];
    int tid = threadIdx.x;
    for (int i = tid; i < 320; i += 256) sw1[i] = w1[i];
    for (int i = tid; i < 2048; i += 256) sw2[i] = w2[i];
    if (tid < 32) {
        float a = bn1[tid] * rsqrtf(bn1[96+tid] + EPSV);
        sA1[tid] = a; sC1[tid] = a*(b1[tid]-bn1[64+tid]) + bn1[32+tid];
    }
    if (tid < 64) {
        float a = bn2[tid] * rsqrtf(bn2[192+tid] + EPSV);
        sA2[tid] = a; sC2[tid] = a*(b2[tid]-bn2[128+tid]) + bn2[64+tid];
    }
    __syncthreads();
    int gid = blockIdx.x*256 + tid;
    int b = gid >> 14;
    int idx = g_knn[gid];
    float dd = g_knnd[gid];
    const float* c = centers + (size_t)(gid >> 5)*3;
    float cx = c[0], cy = c[1], cz = c[2];
    const float* pp = xyz + ((size_t)b*NNP + idx)*3;
    float px = pp[0], py = pp[1], pz = pp[2];
    float f[10] = {cx, cy, cz, px, py, pz, px-cx, py-cy, pz-cz, dd};
    float h[32];
#pragma unroll
    for (int cc = 0; cc < 32; cc++) {
        float acc = 0.f;
#pragma unroll
        for (int i = 0; i < 10; i++) acc += f[i]*sw1[i*32+cc];
        h[cc] = fmaxf(acc*sA1[cc] + sC1[cc], 0.f);
    }
    float* xo = g_x + (size_t)gid*128;
#pragma unroll
    for (int cc = 0; cc < 64; cc++) {
        float acc = 0.f;
#pragma unroll
        for (int i = 0; i < 32; i++) acc += h[i]*sw2[i*64+cc];
        xo[cc] = rndtf(fmaxf(acc*sA2[cc] + sC2[cc], 0.f));
    }
    const float* pr = points + ((size_t)b*NNP + idx)*64;
#pragma unroll
    for (int j = 0; j < 64; j += 4) {
        float4 v = *(const float4*)(pr + j);
        v.x = rndtf(v.x); v.y = rndtf(v.y); v.z = rndtf(v.z); v.w = rndtf(v.w);
        *(float4*)(xo + 64 + j) = v;
    }
}

// ---------------- 4a. V = x@wv + bv (tf32 MMA) ----------------
__global__ void __launch_bounds__(256) vproj_mma(const float* __restrict__ bv) {
    MMA_SMEM
    int row0 = blockIdx.x*128;
    float acc[2][8][4] = {};
    gemm_coreKB(g_x, 128, g_wvR, 128, 128, row0, 0, acc, As, Bs);
    EPI_VARS
#pragma unroll
    for (int mt = 0; mt < 2; mt++)
#pragma unroll
        for (int nt = 0; nt < 8; nt++) {
            int r = row0 + wm_*32 + mt*16 + eg_;
            int c = wn_*64 + nt*8 + 2*etg_;
            float b0 = bv[c], b1 = bv[c+1];
            *(float2*)(g_v + (size_t)r*128 + c)     = make_float2(acc[mt][nt][0]+b0, acc[mt][nt][1]+b1);
            *(float2*)(g_v + (size_t)(r+8)*128 + c) = make_float2(acc[mt][nt][2]+b0, acc[mt][nt][3]+b1);
        }
}

// ---------------- 4b. neighbor self-attention -> dsa[:,0:128] ----------------
__global__ void __launch_bounds__(128) nsa_kernel(
    const float* __restrict__ wq, const float* __restrict__ bq,
    const float* __restrict__ wk, const float* __restrict__ bk,
    const float* __restrict__ gam) {
    __shared__ float xs[32][128];
    __shared__ float qs[32][16], ks2[32][16];
    __shared__ float at[32][32];
    int g = blockIdx.x, t = threadIdx.x;
    const float* xg = g_x + (size_t)g*4096;
#pragma unroll
    for (int i = 0; i < 8; i++)
        *(float4*)(&xs[0][0] + t*4 + i*512) = *(const float4*)(xg + t*4 + i*512);
    __syncthreads();
    {
        int r = t >> 2, c0 = (t & 3)*4;
        float4 aq = *(const float4*)(bq + c0);
        float4 ak = *(const float4*)(bk + c0);
        for (int i = 0; i < 128; i++) {
            float xv = xs[r][i];
            float4 wq4 = *(const float4*)(wq + i*16 + c0);
            float4 wk4 = *(const float4*)(wk + i*16 + c0);
            aq.x += xv*wq4.x; aq.y += xv*wq4.y; aq.z += xv*wq4.z; aq.w += xv*wq4.w;
            ak.x += xv*wk4.x; ak.y += xv*wk4.y; ak.z += xv*wk4.z; ak.w += xv*wk4.w;
        }
        *(float4*)&qs[r][c0] = aq; *(float4*)&ks2[r][c0] = ak;
    }
    __syncthreads();
    {
        int r = t >> 2, j0 = (t & 3)*8;
        float4 q0 = *(float4*)&qs[r][0], q1 = *(float4*)&qs[r][4];
        float4 q2 = *(float4*)&qs[r][8], q3 = *(float4*)&qs[r][12];
        float sc[8];
#pragma unroll
        for (int jj = 0; jj < 8; jj++) {
            int j = j0 + jj;
            float4 k0 = *(float4*)&ks2[j][0], k1 = *(float4*)&ks2[j][4];
            float4 k2 = *(float4*)&ks2[j][8], k3 = *(float4*)&ks2[j][12];
            sc[jj] = q0.x*k0.x + q0.y*k0.y + q0.z*k0.z + q0.w*k0.w
                   + q1.x*k1.x + q1.y*k1.y + q1.z*k1.z + q1.w*k1.w
                   + q2.x*k2.x + q2.y*k2.y + q2.z*k2.z + q2.w*k2.w
                   + q3.x*k3.x + q3.y*k3.y + q3.z*k3.z + q3.w*k3.w;
        }
        float mx = sc[0];
#pragma unroll
        for (int jj = 1; jj < 8; jj++) mx = fmaxf(mx, sc[jj]);
        mx = fmaxf(mx, __shfl_xor_sync(0xffffffffu, mx, 1));
        mx = fmaxf(mx, __shfl_xor_sync(0xffffffffu, mx, 2));
        float sum = 0.f;
#pragma unroll
        for (int jj = 0; jj < 8; jj++) { sc[jj] = expf(sc[jj]-mx); sum += sc[jj]; }
        sum += __shfl_xor_sync(0xffffffffu, sum, 1);
        sum += __shfl_xor_sync(0xffffffffu, sum, 2);
#pragma unroll
        for (int jj = 0; jj < 8; jj++) at[r][j0+jj] = sc[jj]/sum;
    }
    __syncthreads();
    float vreg[32];
#pragma unroll
    for (int k = 0; k < 32; k++)
        vreg[k] = g_v[((size_t)g*32 + k)*128 + t];
    float accn[32];
#pragma unroll
    for (int k = 0; k < 32; k++) accn[k] = 0.f;
    for (int j4 = 0; j4 < 8; j4++) {
        float v0 = vreg[j4*4+0], v1 = vreg[j4*4+1], v2 = vreg[j4*4+2], v3 = vreg[j4*4+3];
#pragma unroll
        for (int k = 0; k < 32; k++) {
            float4 a4 = *(float4*)&at[k][j4*4];
            accn[k] += a4.x*v0 + a4.y*v1 + a4.z*v2 + a4.w*v3;
        }
    }
    float gm = gam[0];
#pragma unroll
    for (int k = 0; k < 32; k++)
        g_dsa[((size_t)g*32 + k)*256 + t] = rndtf(gm*accn[k] + xs[k][t]);
}

// ---------------- 5. GAM G = F F^T (tf32 MMA) ----------------
__global__ void __launch_bounds__(256) gam1_mma() {
    MMA_SMEM
    int b = blockIdx.z;
    const float* F = g_x + (size_t)b*SSP*4096;
    int row0 = blockIdx.y*128, col0 = blockIdx.x*128;
    float acc[2][8][4] = {};
    gemm_core(F, 4096, F, 4096, 4096, row0, col0, acc, As, Bs);
    float* Gp = g_G + (size_t)b*SSP*SSP;
    EPI_VARS
#pragma unroll
    for (int mt = 0; mt < 2; mt++)
#pragma unroll
        for (int nt = 0; nt < 8; nt++) {
            int r = row0 + wm_*32 + mt*16 + eg_;
            int c = col0 + wn_*64 + nt*8 + 2*etg_;
            *(float2*)(Gp + (size_t)r*SSP + c)     = make_float2(acc[mt][nt][0], acc[mt][nt][1]);
            *(float2*)(Gp + (size_t)(r+8)*SSP + c) = make_float2(acc[mt][nt][2], acc[mt][nt][3]);
        }
}

// ---------------- 6. softmax over G rows (writes tf32-rounded) ----------------
__global__ void __launch_bounds__(256) gsoftmax_kernel() {
    __shared__ float red[8];
    int row = blockIdx.x, t = threadIdx.x;
    float* p = g_G + (size_t)row*SSP;
    float a = p[t], b = p[t+256];
    float mx = fmaxf(a, b);
#pragma unroll
    for (int off = 16; off > 0; off >>= 1) mx = fmaxf(mx, __shfl_xor_sync(0xffffffffu, mx, off));
    if ((t & 31) == 0) red[t>>5] = mx;
    __syncthreads();
    mx = red[0];
#pragma unroll
    for (int w = 1; w < 8; w++) mx = fmaxf(mx, red[w]);
    float e1 = expf(a-mx), e2 = expf(b-mx);
    float s = e1 + e2;
#pragma unroll
    for (int off = 16; off > 0; off >>= 1) s += __shfl_xor_sync(0xffffffffu, s, off);
    __syncthreads();
    if ((t & 31) == 0) red[t>>5] = s;
    __syncthreads();
    s = red[0];
#pragma unroll
    for (int w = 1; w < 8; w++) s += red[w];
    p[t] = rndtf(e1/s); p[t+256] = rndtf(e2/s);
}

// ---------------- 7. grp = gamma*G@F + x -> dsa[:,128:256] (tf32 MMA) ----------------
__global__ void __launch_bounds__(256) gam2_mma(const float* __restrict__ gam) {
    MMA_SMEM
    int b = blockIdx.z;
    const float* A = g_G + (size_t)b*SSP*SSP;
    const float* F = g_x + (size_t)b*SSP*4096;
    int row0 = blockIdx.y*128, col0 = blockIdx.x*128;
    float acc[2][8][4] = {};
    gemm_coreKB(A, SSP, F, 4096, SSP, row0, col0, acc, As, Bs);
    float gm = gam[0];
    int kidx = blockIdx.x;   // col0 = kidx*128
    EPI_VARS
#pragma unroll
    for (int mt = 0; mt < 2; mt++)
#pragma unroll
        for (int nt = 0; nt < 8; nt++) {
            int r = row0 + wm_*32 + mt*16 + eg_;
            int c = col0 + wn_*64 + nt*8 + 2*etg_;
            int d = c & 127;
            const float* xr1 = g_x + ((size_t)b*SSP + r)*4096 + c;
            const float* xr2 = g_x + ((size_t)b*SSP + r + 8)*4096 + c;
            float* o1 = g_dsa + ((size_t)((b*SSP + r)*KKN) + kidx)*256 + 128 + d;
            float* o2 = g_dsa + ((size_t)((b*SSP + r + 8)*KKN) + kidx)*256 + 128 + d;
            *(float2*)o1 = make_float2(rndtf(gm*acc[mt][nt][0] + xr1[0]),
                                       rndtf(gm*acc[mt][nt][1] + xr1[1]));
            *(float2*)o2 = make_float2(rndtf(gm*acc[mt][nt][2] + xr2[0]),
                                       rndtf(gm*acc[mt][nt][3] + xr2[1]));
        }
}

// ---------------- 8. h = relu(bn1(dsa@w1+b1)) (tf32 MMA) ----------------
__global__ void __launch_bounds__(256) head1_mma(const float* __restrict__ b1,
                                                 const float* __restrict__ bn1) {
    MMA_SMEM
    int row0 = blockIdx.y*128, col0 = blockIdx.x*128;
    float acc[2][8][4] = {};
    gemm_coreKB(g_dsa, 256, g_w1R, 256, 256, row0, col0, acc, As, Bs);
    EPI_VARS
#pragma unroll
    for (int mt = 0; mt < 2; mt++)
#pragma unroll
        for (int nt = 0; nt < 8; nt++) {
            int r = row0 + wm_*32 + mt*16 + eg_;
            int c = col0 + wn_*64 + nt*8 + 2*etg_;
            float a0 = bn1[c]*rsqrtf(bn1[768+c] + EPSV);
            float c0v = a0*(b1[c]-bn1[512+c]) + bn1[256+c];
            float a1 = bn1[c+1]*rsqrtf(bn1[768+c+1] + EPSV);
            float c1v = a1*(b1[c+1]-bn1[512+c+1]) + bn1[256+c+1];
            *(float2*)(g_h + (size_t)r*256 + c) = make_float2(
                rndtf(fmaxf(acc[mt][nt][0]*a0 + c0v, 0.f)),
                rndtf(fmaxf(acc[mt][nt][1]*a1 + c1v, 0.f)));
            *(float2*)(g_h + (size_t)(r+8)*256 + c) = make_float2(
                rndtf(fmaxf(acc[mt][nt][2]*a0 + c0v, 0.f)),
                rndtf(fmaxf(acc[mt][nt][3]*a1 + c1v, 0.f)));
        }
}

// ---------------- 9. scv = relu(bn(pts@scw+scb)) (tf32 MMA) ----------------
__global__ void __launch_bounds__(256) sc_mma(const float* __restrict__ scb,
                                              const float* __restrict__ scbn) {
    MMA_SMEM
    int row0 = blockIdx.x*128;
    float acc[2][8][4] = {};
    gemm_coreKB(g_x + 64, 128, g_scwR, 128, 64, row0, 0, acc, As, Bs);
    EPI_VARS
#pragma unroll
    for (int mt = 0; mt < 2; mt++)
#pragma unroll
        for (int nt = 0; nt < 8; nt++) {
            int r = row0 + wm_*32 + mt*16 + eg_;
            int c = wn_*64 + nt*8 + 2*etg_;
            float a0 = scbn[c]*rsqrtf(scbn[384+c] + EPSV);
            float c0v = a0*(scb[c]-scbn[256+c]) + scbn[128+c];
            float a1 = scbn[c+1]*rsqrtf(scbn[384+c+1] + EPSV);
            float c1v = a1*(scb[c+1]-scbn[256+c+1]) + scbn[128+c+1];
            *(float2*)(g_scv + (size_t)r*128 + c) = make_float2(
                fmaxf(acc[mt][nt][0]*a0 + c0v, 0.f), fmaxf(acc[mt][nt][1]*a1 + c1v, 0.f));
            *(float2*)(g_scv + (size_t)(r+8)*128 + c) = make_float2(
                fmaxf(acc[mt][nt][2]*a0 + c0v, 0.f), fmaxf(acc[mt][nt][3]*a1 + c1v, 0.f));
        }
}

// ---------------- 10. fused: bn2(h@w2+b2)+scv, relu, max over K -> out ----------------
__global__ void __launch_bounds__(256) head2max_mma(const float* __restrict__ b2,
                                                    const float* __restrict__ bn2,
                                                    float* __restrict__ outp) {
    MMA_SMEM
    int row0 = blockIdx.x*128;
    float acc[2][8][4] = {};
    gemm_coreKB(g_h, 256, g_w2R, 128, 256, row0, 0, acc, As, Bs);
    EPI_VARS
    float tmax[8][2];
#pragma unroll
    for (int nt = 0; nt < 8; nt++) {
        int c = wn_*64 + nt*8 + 2*etg_;
        float a0 = bn2[c]*rsqrtf(bn2[384+c] + EPSV);
        float c0v = a0*(b2[c]-bn2[256+c]) + bn2[128+c];
        float a1 = bn2[c+1]*rsqrtf(bn2[384+c+1] + EPSV);
        float c1v = a1*(b2[c+1]-bn2[256+c+1]) + bn2[128+c+1];
        float m0 = -FLT_MAX, m1 = -FLT_MAX;
#pragma unroll
        for (int mt = 0; mt < 2; mt++) {
            int r = row0 + wm_*32 + mt*16 + eg_;
            const float* s1 = g_scv + (size_t)r*128 + c;
            const float* s2 = g_scv + (size_t)(r+8)*128 + c;
            m0 = fmaxf(m0, fmaxf(acc[mt][nt][0]*a0 + c0v + s1[0], 0.f));
            m1 = fmaxf(m1, fmaxf(acc[mt][nt][1]*a1 + c1v + s1[1], 0.f));
            m0 = fmaxf(m0, fmaxf(acc[mt][nt][2]*a0 + c0v + s2[0], 0.f));
            m1 = fmaxf(m1, fmaxf(acc[mt][nt][3]*a1 + c1v + s2[1], 0.f));
        }
        tmax[nt][0] = m0; tmax[nt][1] = m1;
    }
#pragma unroll
    for (int off = 4; off <= 16; off <<= 1)
#pragma unroll
        for (int nt = 0; nt < 8; nt++) {
            tmax[nt][0] = fmaxf(tmax[nt][0], __shfl_xor_sync(0xffffffffu, tmax[nt][0], off));
            tmax[nt][1] = fmaxf(tmax[nt][1], __shfl_xor_sync(0xffffffffu, tmax[nt][1], off));
        }
    if (eg_ == 0) {
        int gq = blockIdx.x*4 + wm_;
#pragma unroll
        for (int nt = 0; nt < 8; nt++) {
            int c = wn_*64 + nt*8 + 2*etg_;
            outp[12288 + (size_t)gq*128 + c]     = tmax[nt][0];
            outp[12288 + (size_t)gq*128 + c + 1] = tmax[nt][1];
        }
    }
}

extern "C" void kernel_launch(void* const* d_in, const int* in_sizes, int n_in,
                              void* d_out, int out_size) {
    const float* xyz     = (const float*)d_in[0];
    const float* points  = (const float*)d_in[1];
    const int*   fstart  = (const int*)d_in[2];
    const float* pos_w1  = (const float*)d_in[3];
    const float* pos_b1  = (const float*)d_in[4];
    const float* pos_bn1 = (const float*)d_in[5];
    const float* pos_w2  = (const float*)d_in[6];
    const float* pos_b2  = (const float*)d_in[7];
    const float* pos_bn2 = (const float*)d_in[8];
    const float* nsa_wq  = (const float*)d_in[9];
    const float* nsa_bq  = (const float*)d_in[10];
    const float* nsa_wk  = (const float*)d_in[11];
    const float* nsa_bk  = (const float*)d_in[12];
    const float* nsa_wv  = (const float*)d_in[13];
    const float* nsa_bv  = (const float*)d_in[14];
    const float* nsa_g   = (const float*)d_in[15];
    const float* gam_g   = (const float*)d_in[16];
    const float* cat_w1  = (const float*)d_in[17];
    const float* cat_b1  = (const float*)d_in[18];
    const float* cat_bn1 = (const float*)d_in[19];
    const float* cat_w2  = (const float*)d_in[20];
    const float* cat_b2  = (const float*)d_in[21];
    const float* cat_bn2 = (const float*)d_in[22];
    const float* sc_w    = (const float*)d_in[23];
    const float* sc_b    = (const float*)d_in[24];
    const float* sc_bn   = (const float*)d_in[25];
    float* outp = (float*)d_out;

    cudaFuncSetAttribute(vproj_mma,    cudaFuncAttributeMaxDynamicSharedMemorySize, DYNSM);
    cudaFuncSetAttribute(gam1_mma,     cudaFuncAttributeMaxDynamicSharedMemorySize, DYNSM);
    cudaFuncSetAttribute(gam2_mma,     cudaFuncAttributeMaxDynamicSharedMemorySize, DYNSM);
    cudaFuncSetAttribute(head1_mma,    cudaFuncAttributeMaxDynamicSharedMemorySize, DYNSM);
    cudaFuncSetAttribute(sc_mma,       cudaFuncAttributeMaxDynamicSharedMemorySize, DYNSM);
    cudaFuncSetAttribute(head2max_mma, cudaFuncAttributeMaxDynamicSharedMemorySize, DYNSM);

    fps_kernel<<<BB, 512>>>(xyz, fstart, outp);
    prep_round<<<480, 256>>>(cat_w1, cat_w2, nsa_wv, sc_w);
    knn_kernel<<<dim3(SSP, BB), 128>>>(xyz, outp);
    grouppos_kernel<<<512, 256>>>(xyz, points, outp, pos_w1, pos_b1, pos_bn1,
                                  pos_w2, pos_b2, pos_bn2);
    vproj_mma<<<1024, 256, DYNSM>>>(nsa_bv);
    nsa_kernel<<<BB*SSP, 128>>>(nsa_wq, nsa_bq, nsa_wk, nsa_bk, nsa_g);
    gam1_mma<<<dim3(4, 4, BB), 256, DYNSM>>>();
    gsoftmax_kernel<<<BB*SSP, 256>>>();
    gam2_mma<<<dim3(32, 4, BB), 256, DYNSM>>>(gam_g);
    sc_mma<<<1024, 256, DYNSM>>>(sc_b, sc_bn);
    head1_mma<<<dim3(2, 1024), 256, DYNSM>>>(cat_b1, cat_bn1);
    head2max_mma<<<1024, 256, DYNSM>>>(cat_b2, cat_bn2, outp);
}

// round 9
// speedup vs baseline: 2.2450x; 1.0393x over previous
#include <cuda_runtime.h>
#include <stdint.h>
#include <math.h>
#include <float.h>

#define BB 8
#define NNP 4096
#define SSP 512
#define KKN 32
#define EPSV 1e-5f
#define PITCH 36
#define DBUF (128*PITCH)
#define DYNSM (4*DBUF*4)

// scratch (__device__ globals — no allocation allowed)
__device__ float g_x[BB*SSP*KKN*128];      // x = [pos|pts], tf32-rounded
__device__ float g_v[BB*SSP*KKN*128];      // V = x@wv+bv
__device__ float g_dsa[BB*SSP*KKN*256];    // [nei|grp], tf32-rounded
__device__ float g_h[BB*SSP*KKN*256];      // hidden, tf32-rounded
__device__ float g_G[BB*SSP*SSP];          // GAM logits (K-half 0), then softmax result
__device__ float g_G2[BB*SSP*SSP];         // GAM logits (K-half 1)
__device__ float g_scv[BB*SSP*KKN*128];    // relu(bn(sc))
__device__ float g_w1R[256*256];           // tf32-rounded weights (original layouts)
__device__ float g_w2R[256*128];
__device__ float g_wvR[128*128];
__device__ float g_scwR[64*128];
__device__ int   g_knn[BB*SSP*KKN];
__device__ float g_knnd[BB*SSP*KKN];

// ---------------- tf32 helpers ----------------
__device__ __forceinline__ uint32_t f2tf(float f) {
    uint32_t u; asm("cvt.rna.tf32.f32 %0, %1;" : "=r"(u) : "f"(f)); return u;
}
__device__ __forceinline__ float rndtf(float f) { return __uint_as_float(f2tf(f)); }
__device__ __forceinline__ void mma8(float* c, const uint32_t* a, const uint32_t* b) {
    asm volatile("mma.sync.aligned.m16n8k8.row.col.f32.tf32.tf32.f32 "
        "{%0,%1,%2,%3}, {%4,%5,%6,%7}, {%8,%9}, {%0,%1,%2,%3};"
        : "+f"(c[0]), "+f"(c[1]), "+f"(c[2]), "+f"(c[3])
        : "r"(a[0]), "r"(a[1]), "r"(a[2]), "r"(a[3]), "r"(b[0]), "r"(b[1]));
}

#define GEMM_COMPUTE(Ac, Bc) \
    _Pragma("unroll") \
    for (int kk = 0; kk < 32; kk += 8) { \
        uint32_t af[2][4], bf[8][2]; \
        _Pragma("unroll") \
        for (int mt = 0; mt < 2; mt++) { \
            int rb = (wm*32 + mt*16 + gg)*PITCH + kk + tg; \
            af[mt][0] = (Ac)[rb]; \
            af[mt][1] = (Ac)[rb + 8*PITCH]; \
            af[mt][2] = (Ac)[rb + 4]; \
            af[mt][3] = (Ac)[rb + 8*PITCH + 4]; \
        } \
        _Pragma("unroll") \
        for (int nt = 0; nt < 8; nt++) { \
            int nb = (wn*64 + nt*8 + gg)*PITCH + kk + tg; \
            bf[nt][0] = (Bc)[nb]; \
            bf[nt][1] = (Bc)[nb + 4]; \
        } \
        _Pragma("unroll") \
        for (int mt = 0; mt < 2; mt++) \
            _Pragma("unroll") \
            for (int nt = 0; nt < 8; nt++) \
                mma8(acc[mt][nt], af[mt], bf[nt]); \
    }

// C = A[M,K](row-major) * B[N,K](row-major = B^T); inputs pre-rounded to tf32.
__device__ __forceinline__ void gemm_core(const float* __restrict__ A, int lda,
                                          const float* __restrict__ B, int ldb,
                                          int K, int row0, int col0,
                                          float (*acc)[8][4],
                                          uint32_t* As, uint32_t* Bs) {
    int t = threadIdx.x, lane = t & 31, wid = t >> 5;
    int wm = wid & 3, wn = wid >> 2;
    int gg = lane >> 2, tg = lane & 3;
    int lr[4], lc[4];
#pragma unroll
    for (int i = 0; i < 4; i++) { int lin = t + i*256; lr[i] = lin >> 3; lc[i] = (lin & 7)*4; }
    const float* Ab = A + (size_t)row0*lda;
    const float* Bb = B + (size_t)col0*ldb;
    float4 avr[4], bvr[4];
#pragma unroll
    for (int i = 0; i < 4; i++) {
        avr[i] = *(const float4*)(Ab + (size_t)lr[i]*lda + lc[i]);
        bvr[i] = *(const float4*)(Bb + (size_t)lr[i]*ldb + lc[i]);
    }
    int nsteps = K >> 5;
    for (int s = 0; s < nsteps; s++) {
        uint32_t* Ac = As + (s & 1)*DBUF;
        uint32_t* Bc = Bs + (s & 1)*DBUF;
#pragma unroll
        for (int i = 0; i < 4; i++) {
            *(float4*)(Ac + lr[i]*PITCH + lc[i]) = avr[i];
            *(float4*)(Bc + lr[i]*PITCH + lc[i]) = bvr[i];
        }
        __syncthreads();
        if (s + 1 < nsteps) {
            int k0 = (s + 1)*32;
#pragma unroll
            for (int i = 0; i < 4; i++) {
                avr[i] = *(const float4*)(Ab + (size_t)lr[i]*lda + k0 + lc[i]);
                bvr[i] = *(const float4*)(Bb + (size_t)lr[i]*ldb + k0 + lc[i]);
            }
        }
        GEMM_COMPUTE(Ac, Bc)
    }
    __syncthreads();
}

// C = A[M,K](row-major) * Bsrc[K,N](k-major rows); inputs pre-rounded to tf32.
__device__ __forceinline__ void gemm_coreKB(const float* __restrict__ A, int lda,
                                            const float* __restrict__ Bsrc, int ldb,
                                            int K, int row0, int col0,
                                            float (*acc)[8][4],
                                            uint32_t* As, uint32_t* Bs) {
    int t = threadIdx.x, lane = t & 31, wid = t >> 5;
    int wm = wid & 3, wn = wid >> 2;
    int gg = lane >> 2, tg = lane & 3;
    int lr[4], lc[4], bn[4], bk[4];
#pragma unroll
    for (int i = 0; i < 4; i++) {
        int lin = t + i*256;
        lr[i] = lin >> 3; lc[i] = (lin & 7)*4;
        bn[i] = lin & 127; bk[i] = (lin >> 7)*4;
    }
    const float* Ab = A + (size_t)row0*lda;
    float4 avr[4]; float bvr[4][4];
#pragma unroll
    for (int i = 0; i < 4; i++) {
        avr[i] = *(const float4*)(Ab + (size_t)lr[i]*lda + lc[i]);
        const float* bp = Bsrc + (size_t)bk[i]*ldb + col0 + bn[i];
#pragma unroll
        for (int j = 0; j < 4; j++) bvr[i][j] = bp[(size_t)j*ldb];
    }
    int nsteps = K >> 5;
    for (int s = 0; s < nsteps; s++) {
        uint32_t* Ac = As + (s & 1)*DBUF;
        uint32_t* Bc = Bs + (s & 1)*DBUF;
#pragma unroll
        for (int i = 0; i < 4; i++) {
            *(float4*)(Ac + lr[i]*PITCH + lc[i]) = avr[i];
            *(float4*)(Bc + bn[i]*PITCH + bk[i]) =
                make_float4(bvr[i][0], bvr[i][1], bvr[i][2], bvr[i][3]);
        }
        __syncthreads();
        if (s + 1 < nsteps) {
            int k0 = (s + 1)*32;
#pragma unroll
            for (int i = 0; i < 4; i++) {
                avr[i] = *(const float4*)(Ab + (size_t)lr[i]*lda + k0 + lc[i]);
                const float* bp = Bsrc + (size_t)(k0 + bk[i])*ldb + col0 + bn[i];
#pragma unroll
                for (int j = 0; j < 4; j++) bvr[i][j] = bp[(size_t)j*ldb];
            }
        }
        GEMM_COMPUTE(Ac, Bc)
    }
    __syncthreads();
}

#define EPI_VARS int t_=threadIdx.x, lane_=t_&31, wid_=t_>>5; \
    int wm_=wid_&3, wn_=wid_>>2, eg_=lane_>>2, etg_=lane_&3; (void)t_; (void)lane_;
#define MMA_SMEM extern __shared__ uint32_t smem_u[]; \
    uint32_t* As = smem_u; uint32_t* Bs = smem_u + 2*DBUF;

// ---------------- 0. round weights to tf32 (original layouts) ----------------
__global__ void __launch_bounds__(256) prep_round(const float* __restrict__ w1,
                                                  const float* __restrict__ w2,
                                                  const float* __restrict__ wv,
                                                  const float* __restrict__ scw) {
    int t = blockIdx.x*256 + threadIdx.x;
    if (t < 65536) g_w1R[t] = rndtf(w1[t]);
    else if (t < 98304) g_w2R[t-65536] = rndtf(w2[t-65536]);
    else if (t < 114688) g_wvR[t-98304] = rndtf(wv[t-98304]);
    else if (t < 122880) g_scwR[t-114688] = rndtf(scw[t-114688]);
}

// ---------------- 1. FPS ----------------
__global__ void __launch_bounds__(512) fps_kernel(const float* __restrict__ xyz,
                                                  const int* __restrict__ start,
                                                  float* __restrict__ centers) {
    __shared__ float sx[NNP], sy[NNP], sz[NNP];
    __shared__ float rv[16]; __shared__ int ri[16]; __shared__ int sfar;
    int b = blockIdx.x, tid = threadIdx.x;
    for (int i = tid; i < NNP; i += 512) {
        const float* p = xyz + ((size_t)b*NNP + i)*3;
        sx[i] = p[0]; sy[i] = p[1]; sz[i] = p[2];
    }
    float dist[8];
#pragma unroll
    for (int i = 0; i < 8; i++) dist[i] = 1e10f;
    __syncthreads();
    int far = start[b];
    for (int t = 0; t < SSP; t++) {
        float cx = sx[far], cy = sy[far], cz = sz[far];
        if (tid == 0) {
            float* o = centers + ((size_t)b*SSP + t)*3;
            o[0] = cx; o[1] = cy; o[2] = cz;
        }
        float bv = -1.0f; int bi = 0;
#pragma unroll
        for (int i = 0; i < 8; i++) {
            int p = tid + i*512;
            float dx = sx[p]-cx, dy = sy[p]-cy, dz = sz[p]-cz;
            float d = fminf(dist[i], dx*dx + dy*dy + dz*dz);
            dist[i] = d;
            if (d > bv) { bv = d; bi = p; }
        }
#pragma unroll
        for (int off = 16; off > 0; off >>= 1) {
            float ov = __shfl_down_sync(0xffffffffu, bv, off);
            int   oi = __shfl_down_sync(0xffffffffu, bi, off);
            if (ov > bv || (ov == bv && oi < bi)) { bv = ov; bi = oi; }
        }
        if ((tid & 31) == 0) { rv[tid>>5] = bv; ri[tid>>5] = bi; }
        __syncthreads();
        if (tid < 32) {
            float gv = (tid < 16) ? rv[tid] : -3.0f;
            int   gi = (tid < 16) ? ri[tid] : 0x7fffffff;
#pragma unroll
            for (int off = 8; off > 0; off >>= 1) {
                float ov = __shfl_down_sync(0xffffffffu, gv, off);
                int   oi = __shfl_down_sync(0xffffffffu, gi, off);
                if (ov > gv || (ov == gv && oi < gi)) { gv = ov; gi = oi; }
            }
            if (tid == 0) sfar = gi;
        }
        __syncthreads();
        far = sfar;
    }
}

// ---------------- 2. KNN ----------------
__global__ void __launch_bounds__(128) knn_kernel(const float* __restrict__ xyz,
                                                  const float* __restrict__ centers) {
    __shared__ float sd2[KKN*128];
    __shared__ float swv[4]; __shared__ int swi[4];
    int s = blockIdx.x, b = blockIdx.y, tid = threadIdx.x;
    const float* c = centers + ((size_t)b*SSP + s)*3;
    float cx = c[0], cy = c[1], cz = c[2];
    float cn2 = cx*cx + cy*cy + cz*cz;
    float lv = FLT_MAX; int li = 0x7fffffff; int lslot = 0;
#pragma unroll
    for (int i = 0; i < KKN; i++) {
        int p = tid + i*128;
        const float* pp = xyz + ((size_t)b*NNP + p)*3;
        float px = pp[0], py = pp[1], pz = pp[2];
        float d2 = cn2 + (px*px + py*py + pz*pz) - 2.0f*(cx*px + cy*py + cz*pz);
        sd2[i*128 + tid] = d2;
        if (d2 < lv) { lv = d2; li = p; lslot = i; }
    }
    int lane = tid & 31, warp = tid >> 5;
    int obase = (b*SSP + s)*KKN;
    for (int r = 0; r < KKN; r++) {
        float bv = lv; int bi = li;
#pragma unroll
        for (int off = 16; off > 0; off >>= 1) {
            float ov = __shfl_xor_sync(0xffffffffu, bv, off);
            int   oi = __shfl_xor_sync(0xffffffffu, bi, off);
            if (ov < bv || (ov == bv && oi < bi)) { bv = ov; bi = oi; }
        }
        if (lane == 0) { swv[warp] = bv; swi[warp] = bi; }
        __syncthreads();
        float gv = swv[0]; int gi = swi[0];
#pragma unroll
        for (int w = 1; w < 4; w++)
            if (swv[w] < gv || (swv[w] == gv && swi[w] < gi)) { gv = swv[w]; gi = swi[w]; }
        if (tid == 0) { g_knn[obase + r] = gi; g_knnd[obase + r] = gv; }
        if (gi == li) {
            sd2[lslot*128 + tid] = FLT_MAX;
            lv = FLT_MAX; li = 0x7fffffff; lslot = 0;
#pragma unroll
            for (int i = 0; i < KKN; i++) {
                float d = sd2[i*128 + tid];
                if (d < lv) { lv = d; li = tid + i*128; lslot = i; }
            }
        }
        __syncthreads();
    }
}

// ---------------- 3. group + pos-embed MLP (writes tf32-rounded x) ----------------
__global__ void __launch_bounds__(256) grouppos_kernel(
    const float* __restrict__ xyz, const float* __restrict__ points,
    const float* __restrict__ centers,
    const float* __restrict__ w1, const float* __restrict__ b1, const float* __restrict__ bn1,
    const float* __restrict__ w2, const float* __restrict__ b2, const float* __restrict__ bn2) {
    __shared__ float sw1[320], sw2[2048];
    __shared__ float sA1[32], sC1[32], sA2[64], sC2[64];
    int tid = threadIdx.x;
    for (int i = tid; i < 320; i += 256) sw1[i] = w1[i];
    for (int i = tid; i < 2048; i += 256) sw2[i] = w2[i];
    if (tid < 32) {
        float a = bn1[tid] * rsqrtf(bn1[96+tid] + EPSV);
        sA1[tid] = a; sC1[tid] = a*(b1[tid]-bn1[64+tid]) + bn1[32+tid];
    }
    if (tid < 64) {
        float a = bn2[tid] * rsqrtf(bn2[192+tid] + EPSV);
        sA2[tid] = a; sC2[tid] = a*(b2[tid]-bn2[128+tid]) + bn2[64+tid];
    }
    __syncthreads();
    int gid = blockIdx.x*256 + tid;
    int b = gid >> 14;
    int idx = g_knn[gid];
    float dd = g_knnd[gid];
    const float* c = centers + (size_t)(gid >> 5)*3;
    float cx = c[0], cy = c[1], cz = c[2];
    const float* pp = xyz + ((size_t)b*NNP + idx)*3;
    float px = pp[0], py = pp[1], pz = pp[2];
    float f[10] = {cx, cy, cz, px, py, pz, px-cx, py-cy, pz-cz, dd};
    float h[32];
#pragma unroll
    for (int cc = 0; cc < 32; cc++) {
        float acc = 0.f;
#pragma unroll
        for (int i = 0; i < 10; i++) acc += f[i]*sw1[i*32+cc];
        h[cc] = fmaxf(acc*sA1[cc] + sC1[cc], 0.f);
    }
    float* xo = g_x + (size_t)gid*128;
#pragma unroll
    for (int cc = 0; cc < 64; cc++) {
        float acc = 0.f;
#pragma unroll
        for (int i = 0; i < 32; i++) acc += h[i]*sw2[i*64+cc];
        xo[cc] = rndtf(fmaxf(acc*sA2[cc] + sC2[cc], 0.f));
    }
    const float* pr = points + ((size_t)b*NNP + idx)*64;
#pragma unroll
    for (int j = 0; j < 64; j += 4) {
        float4 v = *(const float4*)(pr + j);
        v.x = rndtf(v.x); v.y = rndtf(v.y); v.z = rndtf(v.z); v.w = rndtf(v.w);
        *(float4*)(xo + 64 + j) = v;
    }
}

// ---------------- 4a. V = x@wv + bv (tf32 MMA) ----------------
__global__ void __launch_bounds__(256) vproj_mma(const float* __restrict__ bv) {
    MMA_SMEM
    int row0 = blockIdx.x*128;
    float acc[2][8][4] = {};
    gemm_coreKB(g_x, 128, g_wvR, 128, 128, row0, 0, acc, As, Bs);
    EPI_VARS
#pragma unroll
    for (int mt = 0; mt < 2; mt++)
#pragma unroll
        for (int nt = 0; nt < 8; nt++) {
            int r = row0 + wm_*32 + mt*16 + eg_;
            int c = wn_*64 + nt*8 + 2*etg_;
            float b0 = bv[c], b1 = bv[c+1];
            *(float2*)(g_v + (size_t)r*128 + c)     = make_float2(acc[mt][nt][0]+b0, acc[mt][nt][1]+b1);
            *(float2*)(g_v + (size_t)(r+8)*128 + c) = make_float2(acc[mt][nt][2]+b0, acc[mt][nt][3]+b1);
        }
}

// ---------------- 4b. neighbor self-attention -> dsa[:,0:128] ----------------
__global__ void __launch_bounds__(128) nsa_kernel(
    const float* __restrict__ wq, const float* __restrict__ bq,
    const float* __restrict__ wk, const float* __restrict__ bk,
    const float* __restrict__ gam) {
    __shared__ float xs[32][128];
    __shared__ float swq[128][16], swk[128][16];
    __shared__ float qs[32][16], ks2[32][16];
    __shared__ float at[32][32];
    int g = blockIdx.x, t = threadIdx.x;
    const float* xg = g_x + (size_t)g*4096;
#pragma unroll
    for (int i = 0; i < 8; i++)
        *(float4*)(&xs[0][0] + t*4 + i*512) = *(const float4*)(xg + t*4 + i*512);
#pragma unroll
    for (int i = 0; i < 4; i++) {
        *(float4*)(&swq[0][0] + t*4 + i*512) = *(const float4*)(wq + t*4 + i*512);
        *(float4*)(&swk[0][0] + t*4 + i*512) = *(const float4*)(wk + t*4 + i*512);
    }
    __syncthreads();
    {
        int r = t >> 2, c0 = (t & 3)*4;
        float4 aq = *(const float4*)(bq + c0);
        float4 ak = *(const float4*)(bk + c0);
        for (int i = 0; i < 128; i++) {
            float xv = xs[r][i];
            float4 wq4 = *(float4*)&swq[i][c0];
            float4 wk4 = *(float4*)&swk[i][c0];
            aq.x += xv*wq4.x; aq.y += xv*wq4.y; aq.z += xv*wq4.z; aq.w += xv*wq4.w;
            ak.x += xv*wk4.x; ak.y += xv*wk4.y; ak.z += xv*wk4.z; ak.w += xv*wk4.w;
        }
        *(float4*)&qs[r][c0] = aq; *(float4*)&ks2[r][c0] = ak;
    }
    __syncthreads();
    {
        int r = t >> 2, j0 = (t & 3)*8;
        float4 q0 = *(float4*)&qs[r][0], q1 = *(float4*)&qs[r][4];
        float4 q2 = *(float4*)&qs[r][8], q3 = *(float4*)&qs[r][12];
        float sc[8];
#pragma unroll
        for (int jj = 0; jj < 8; jj++) {
            int j = j0 + jj;
            float4 k0 = *(float4*)&ks2[j][0], k1 = *(float4*)&ks2[j][4];
            float4 k2 = *(float4*)&ks2[j][8], k3 = *(float4*)&ks2[j][12];
            sc[jj] = q0.x*k0.x + q0.y*k0.y + q0.z*k0.z + q0.w*k0.w
                   + q1.x*k1.x + q1.y*k1.y + q1.z*k1.z + q1.w*k1.w
                   + q2.x*k2.x + q2.y*k2.y + q2.z*k2.z + q2.w*k2.w
                   + q3.x*k3.x + q3.y*k3.y + q3.z*k3.z + q3.w*k3.w;
        }
        float mx = sc[0];
#pragma unroll
        for (int jj = 1; jj < 8; jj++) mx = fmaxf(mx, sc[jj]);
        mx = fmaxf(mx, __shfl_xor_sync(0xffffffffu, mx, 1));
        mx = fmaxf(mx, __shfl_xor_sync(0xffffffffu, mx, 2));
        float sum = 0.f;
#pragma unroll
        for (int jj = 0; jj < 8; jj++) { sc[jj] = expf(sc[jj]-mx); sum += sc[jj]; }
        sum += __shfl_xor_sync(0xffffffffu, sum, 1);
        sum += __shfl_xor_sync(0xffffffffu, sum, 2);
#pragma unroll
        for (int jj = 0; jj < 8; jj++) at[r][j0+jj] = sc[jj]/sum;
    }
    __syncthreads();
    float vreg[32];
#pragma unroll
    for (int k = 0; k < 32; k++)
        vreg[k] = g_v[((size_t)g*32 + k)*128 + t];
    float accn[32];
#pragma unroll
    for (int k = 0; k < 32; k++) accn[k] = 0.f;
    for (int j4 = 0; j4 < 8; j4++) {
        float v0 = vreg[j4*4+0], v1 = vreg[j4*4+1], v2 = vreg[j4*4+2], v3 = vreg[j4*4+3];
#pragma unroll
        for (int k = 0; k < 32; k++) {
            float4 a4 = *(float4*)&at[k][j4*4];
            accn[k] += a4.x*v0 + a4.y*v1 + a4.z*v2 + a4.w*v3;
        }
    }
    float gm = gam[0];
#pragma unroll
    for (int k = 0; k < 32; k++)
        g_dsa[((size_t)g*32 + k)*256 + t] = rndtf(gm*accn[k] + xs[k][t]);
}

// ---------------- 5. GAM G = F F^T (tf32 MMA, symmetric + K-split) ----------------
// grid (20, 1, 8): bx%10 -> lower-triangle tile, bx/10 -> K half.
__global__ void __launch_bounds__(256) gam1_mma() {
    MMA_SMEM
    int bx = blockIdx.x;
    int half = bx / 10, ti = bx % 10;
    int trow = (ti >= 6) ? 3 : (ti >= 3) ? 2 : (ti >= 1) ? 1 : 0;
    int tcol = ti - trow*(trow+1)/2;
    int row0 = trow*128, col0 = tcol*128;
    int b = blockIdx.z;
    const float* F = g_x + (size_t)b*SSP*4096 + half*2048;
    float acc[2][8][4] = {};
    gemm_core(F, 4096, F, 4096, 2048, row0, col0, acc, As, Bs);
    float* Gp = (half ? g_G2 : g_G) + (size_t)b*SSP*SSP;
    bool mir = (row0 != col0);
    EPI_VARS
#pragma unroll
    for (int mt = 0; mt < 2; mt++)
#pragma unroll
        for (int nt = 0; nt < 8; nt++) {
            int r = row0 + wm_*32 + mt*16 + eg_;
            int c = col0 + wn_*64 + nt*8 + 2*etg_;
            float c0 = acc[mt][nt][0], c1 = acc[mt][nt][1];
            float c2 = acc[mt][nt][2], c3 = acc[mt][nt][3];
            *(float2*)(Gp + (size_t)r*SSP + c)     = make_float2(c0, c1);
            *(float2*)(Gp + (size_t)(r+8)*SSP + c) = make_float2(c2, c3);
            if (mir) {
                Gp[(size_t)c*SSP + r]         = c0;
                Gp[(size_t)(c+1)*SSP + r]     = c1;
                Gp[(size_t)c*SSP + r + 8]     = c2;
                Gp[(size_t)(c+1)*SSP + r + 8] = c3;
            }
        }
}

// ---------------- 6. softmax over (G + G2) rows (writes tf32-rounded to g_G) ----------------
__global__ void __launch_bounds__(256) gsoftmax_kernel() {
    __shared__ float red[8];
    int row = blockIdx.x, t = threadIdx.x;
    float* p  = g_G  + (size_t)row*SSP;
    float* p2 = g_G2 + (size_t)row*SSP;
    float a = p[t] + p2[t], b = p[t+256] + p2[t+256];
    float mx = fmaxf(a, b);
#pragma unroll
    for (int off = 16; off > 0; off >>= 1) mx = fmaxf(mx, __shfl_xor_sync(0xffffffffu, mx, off));
    if ((t & 31) == 0) red[t>>5] = mx;
    __syncthreads();
    mx = red[0];
#pragma unroll
    for (int w = 1; w < 8; w++) mx = fmaxf(mx, red[w]);
    float e1 = expf(a-mx), e2 = expf(b-mx);
    float s = e1 + e2;
#pragma unroll
    for (int off = 16; off > 0; off >>= 1) s += __shfl_xor_sync(0xffffffffu, s, off);
    __syncthreads();
    if ((t & 31) == 0) red[t>>5] = s;
    __syncthreads();
    s = red[0];
#pragma unroll
    for (int w = 1; w < 8; w++) s += red[w];
    p[t] = rndtf(e1/s); p[t+256] = rndtf(e2/s);
}

// ---------------- 7. grp = gamma*G@F + x -> dsa[:,128:256] (tf32 MMA) ----------------
__global__ void __launch_bounds__(256) gam2_mma(const float* __restrict__ gam) {
    MMA_SMEM
    int b = blockIdx.z;
    const float* A = g_G + (size_t)b*SSP*SSP;
    const float* F = g_x + (size_t)b*SSP*4096;
    int row0 = blockIdx.y*128, col0 = blockIdx.x*128;
    float acc[2][8][4] = {};
    gemm_coreKB(A, SSP, F, 4096, SSP, row0, col0, acc, As, Bs);
    float gm = gam[0];
    int kidx = blockIdx.x;   // col0 = kidx*128
    EPI_VARS
#pragma unroll
    for (int mt = 0; mt < 2; mt++)
#pragma unroll
        for (int nt = 0; nt < 8; nt++) {
            int r = row0 + wm_*32 + mt*16 + eg_;
            int c = col0 + wn_*64 + nt*8 + 2*etg_;
            int d = c & 127;
            const float* xr1 = g_x + ((size_t)b*SSP + r)*4096 + c;
            const float* xr2 = g_x + ((size_t)b*SSP + r + 8)*4096 + c;
            float* o1 = g_dsa + ((size_t)((b*SSP + r)*KKN) + kidx)*256 + 128 + d;
            float* o2 = g_dsa + ((size_t)((b*SSP + r + 8)*KKN) + kidx)*256 + 128 + d;
            *(float2*)o1 = make_float2(rndtf(gm*acc[mt][nt][0] + xr1[0]),
                                       rndtf(gm*acc[mt][nt][1] + xr1[1]));
            *(float2*)o2 = make_float2(rndtf(gm*acc[mt][nt][2] + xr2[0]),
                                       rndtf(gm*acc[mt][nt][3] + xr2[1]));
        }
}

// ---------------- 8. h = relu(bn1(dsa@w1+b1)) (tf32 MMA) ----------------
__global__ void __launch_bounds__(256) head1_mma(const float* __restrict__ b1,
                                                 const float* __restrict__ bn1) {
    MMA_SMEM
    int row0 = blockIdx.y*128, col0 = blockIdx.x*128;
    float acc[2][8][4] = {};
    gemm_coreKB(g_dsa, 256, g_w1R, 256, 256, row0, col0, acc, As, Bs);
    EPI_VARS
#pragma unroll
    for (int mt = 0; mt < 2; mt++)
#pragma unroll
        for (int nt = 0; nt < 8; nt++) {
            int r = row0 + wm_*32 + mt*16 + eg_;
            int c = col0 + wn_*64 + nt*8 + 2*etg_;
            float a0 = bn1[c]*rsqrtf(bn1[768+c] + EPSV);
            float c0v = a0*(b1[c]-bn1[512+c]) + bn1[256+c];
            float a1 = bn1[c+1]*rsqrtf(bn1[768+c+1] + EPSV);
            float c1v = a1*(b1[c+1]-bn1[512+c+1]) + bn1[256+c+1];
            *(float2*)(g_h + (size_t)r*256 + c) = make_float2(
                rndtf(fmaxf(acc[mt][nt][0]*a0 + c0v, 0.f)),
                rndtf(fmaxf(acc[mt][nt][1]*a1 + c1v, 0.f)));
            *(float2*)(g_h + (size_t)(r+8)*256 + c) = make_float2(
                rndtf(fmaxf(acc[mt][nt][2]*a0 + c0v, 0.f)),
                rndtf(fmaxf(acc[mt][nt][3]*a1 + c1v, 0.f)));
        }
}

// ---------------- 9. scv = relu(bn(pts@scw+scb)) (tf32 MMA) ----------------
__global__ void __launch_bounds__(256) sc_mma(const float* __restrict__ scb,
                                              const float* __restrict__ scbn) {
    MMA_SMEM
    int row0 = blockIdx.x*128;
    float acc[2][8][4] = {};
    gemm_coreKB(g_x + 64, 128, g_scwR, 128, 64, row0, 0, acc, As, Bs);
    EPI_VARS
#pragma unroll
    for (int mt = 0; mt < 2; mt++)
#pragma unroll
        for (int nt = 0; nt < 8; nt++) {
            int r = row0 + wm_*32 + mt*16 + eg_;
            int c = wn_*64 + nt*8 + 2*etg_;
            float a0 = scbn[c]*rsqrtf(scbn[384+c] + EPSV);
            float c0v = a0*(scb[c]-scbn[256+c]) + scbn[128+c];
            float a1 = scbn[c+1]*rsqrtf(scbn[384+c+1] + EPSV);
            float c1v = a1*(scb[c+1]-scbn[256+c+1]) + scbn[128+c+1];
            *(float2*)(g_scv + (size_t)r*128 + c) = make_float2(
                fmaxf(acc[mt][nt][0]*a0 + c0v, 0.f), fmaxf(acc[mt][nt][1]*a1 + c1v, 0.f));
            *(float2*)(g_scv + (size_t)(r+8)*128 + c) = make_float2(
                fmaxf(acc[mt][nt][2]*a0 + c0v, 0.f), fmaxf(acc[mt][nt][3]*a1 + c1v, 0.f));
        }
}

// ---------------- 10. fused: bn2(h@w2+b2)+scv, relu, max over K -> out ----------------
__global__ void __launch_bounds__(256) head2max_mma(const float* __restrict__ b2,
                                                    const float* __restrict__ bn2,
                                                    float* __restrict__ outp) {
    MMA_SMEM
    int row0 = blockIdx.x*128;
    float acc[2][8][4] = {};
    gemm_coreKB(g_h, 256, g_w2R, 128, 256, row0, 0, acc, As, Bs);
    EPI_VARS
    float tmax[8][2];
#pragma unroll
    for (int nt = 0; nt < 8; nt++) {
        int c = wn_*64 + nt*8 + 2*etg_;
        float a0 = bn2[c]*rsqrtf(bn2[384+c] + EPSV);
        float c0v = a0*(b2[c]-bn2[256+c]) + bn2[128+c];
        float a1 = bn2[c+1]*rsqrtf(bn2[384+c+1] + EPSV);
        float c1v = a1*(b2[c+1]-bn2[256+c+1]) + bn2[128+c+1];
        float m0 = -FLT_MAX, m1 = -FLT_MAX;
#pragma unroll
        for (int mt = 0; mt < 2; mt++) {
            int r = row0 + wm_*32 + mt*16 + eg_;
            const float* s1 = g_scv + (size_t)r*128 + c;
            const float* s2 = g_scv + (size_t)(r+8)*128 + c;
            m0 = fmaxf(m0, fmaxf(acc[mt][nt][0]*a0 + c0v + s1[0], 0.f));
            m1 = fmaxf(m1, fmaxf(acc[mt][nt][1]*a1 + c1v + s1[1], 0.f));
            m0 = fmaxf(m0, fmaxf(acc[mt][nt][2]*a0 + c0v + s2[0], 0.f));
            m1 = fmaxf(m1, fmaxf(acc[mt][nt][3]*a1 + c1v + s2[1], 0.f));
        }
        tmax[nt][0] = m0; tmax[nt][1] = m1;
    }
#pragma unroll
    for (int off = 4; off <= 16; off <<= 1)
#pragma unroll
        for (int nt = 0; nt < 8; nt++) {
            tmax[nt][0] = fmaxf(tmax[nt][0], __shfl_xor_sync(0xffffffffu, tmax[nt][0], off));
            tmax[nt][1] = fmaxf(tmax[nt][1], __shfl_xor_sync(0xffffffffu, tmax[nt][1], off));
        }
    if (eg_ == 0) {
        int gq = blockIdx.x*4 + wm_;
#pragma unroll
        for (int nt = 0; nt < 8; nt++) {
            int c = wn_*64 + nt*8 + 2*etg_;
            outp[12288 + (size_t)gq*128 + c]     = tmax[nt][0];
            outp[12288 + (size_t)gq*128 + c + 1] = tmax[nt][1];
        }
    }
}

extern "C" void kernel_launch(void* const* d_in, const int* in_sizes, int n_in,
                              void* d_out, int out_size) {
    const float* xyz     = (const float*)d_in[0];
    const float* points  = (const float*)d_in[1];
    const int*   fstart  = (const int*)d_in[2];
    const float* pos_w1  = (const float*)d_in[3];
    const float* pos_b1  = (const float*)d_in[4];
    const float* pos_bn1 = (const float*)d_in[5];
    const float* pos_w2  = (const float*)d_in[6];
    const float* pos_b2  = (const float*)d_in[7];
    const float* pos_bn2 = (const float*)d_in[8];
    const float* nsa_wq  = (const float*)d_in[9];
    const float* nsa_bq  = (const float*)d_in[10];
    const float* nsa_wk  = (const float*)d_in[11];
    const float* nsa_bk  = (const float*)d_in[12];
    const float* nsa_wv  = (const float*)d_in[13];
    const float* nsa_bv  = (const float*)d_in[14];
    const float* nsa_g   = (const float*)d_in[15];
    const float* gam_g   = (const float*)d_in[16];
    const float* cat_w1  = (const float*)d_in[17];
    const float* cat_b1  = (const float*)d_in[18];
    const float* cat_bn1 = (const float*)d_in[19];
    const float* cat_w2  = (const float*)d_in[20];
    const float* cat_b2  = (const float*)d_in[21];
    const float* cat_bn2 = (const float*)d_in[22];
    const float* sc_w    = (const float*)d_in[23];
    const float* sc_b    = (const float*)d_in[24];
    const float* sc_bn   = (const float*)d_in[25];
    float* outp = (float*)d_out;

    cudaFuncSetAttribute(vproj_mma,    cudaFuncAttributeMaxDynamicSharedMemorySize, DYNSM);
    cudaFuncSetAttribute(gam1_mma,     cudaFuncAttributeMaxDynamicSharedMemorySize, DYNSM);
    cudaFuncSetAttribute(gam2_mma,     cudaFuncAttributeMaxDynamicSharedMemorySize, DYNSM);
    cudaFuncSetAttribute(head1_mma,    cudaFuncAttributeMaxDynamicSharedMemorySize, DYNSM);
    cudaFuncSetAttribute(sc_mma,       cudaFuncAttributeMaxDynamicSharedMemorySize, DYNSM);
    cudaFuncSetAttribute(head2max_mma, cudaFuncAttributeMaxDynamicSharedMemorySize, DYNSM);

    fps_kernel<<<BB, 512>>>(xyz, fstart, outp);
    prep_round<<<480, 256>>>(cat_w1, cat_w2, nsa_wv, sc_w);
    knn_kernel<<<dim3(SSP, BB), 128>>>(xyz, outp);
    grouppos_kernel<<<512, 256>>>(xyz, points, outp, pos_w1, pos_b1, pos_bn1,
                                  pos_w2, pos_b2, pos_bn2);
    vproj_mma<<<1024, 256, DYNSM>>>(nsa_bv);
    nsa_kernel<<<BB*SSP, 128>>>(nsa_wq, nsa_bq, nsa_wk, nsa_bk, nsa_g);
    gam1_mma<<<dim3(20, 1, BB), 256, DYNSM>>>();
    gsoftmax_kernel<<<BB*SSP, 256>>>();
    gam2_mma<<<dim3(32, 4, BB), 256, DYNSM>>>(gam_g);
    sc_mma<<<1024, 256, DYNSM>>>(sc_b, sc_bn);
    head1_mma<<<dim3(2, 1024), 256, DYNSM>>>(cat_b1, cat_bn1);
    head2max_mma<<<1024, 256, DYNSM>>>(cat_b2, cat_bn2, outp);
}

// round 11
// speedup vs baseline: 2.3598x; 1.0511x over previous
#include <cuda_runtime.h>
#include <stdint.h>
#include <math.h>
#include <float.h>

#define BB 8
#define NNP 4096
#define SSP 512
#define KKN 32
#define EPSV 1e-5f
#define PITCH 36
#define DBUF (128*PITCH)
#define DYNSM (4*DBUF*4)

// scratch (__device__ globals — no allocation allowed)
__device__ float g_x[BB*SSP*KKN*128];      // x = [pos|pts], tf32-rounded
__device__ float g_v[BB*SSP*KKN*128];      // V = x@wv+bv
__device__ float g_dsa[BB*SSP*KKN*256];    // [nei|grp], tf32-rounded
__device__ float g_h[BB*SSP*KKN*256];      // hidden, tf32-rounded
__device__ float g_G[BB*SSP*SSP];          // GAM logits (K-half 0), then softmax result
__device__ float g_G2[BB*SSP*SSP];         // GAM logits (K-half 1)
__device__ float g_scv[BB*SSP*KKN*128];    // relu(bn(sc))
__device__ float g_w1R[256*256];           // tf32-rounded weights (original layouts)
__device__ float g_w2R[256*128];
__device__ float g_wvR[128*128];
__device__ float g_scwR[64*128];
__device__ int   g_knn[BB*SSP*KKN];
__device__ float g_knnd[BB*SSP*KKN];

// ---------------- tf32 helpers ----------------
__device__ __forceinline__ uint32_t f2tf(float f) {
    uint32_t u; asm("cvt.rna.tf32.f32 %0, %1;" : "=r"(u) : "f"(f)); return u;
}
__device__ __forceinline__ float rndtf(float f) { return __uint_as_float(f2tf(f)); }
__device__ __forceinline__ void mma8(float* c, const uint32_t* a, const uint32_t* b) {
    asm volatile("mma.sync.aligned.m16n8k8.row.col.f32.tf32.tf32.f32 "
        "{%0,%1,%2,%3}, {%4,%5,%6,%7}, {%8,%9}, {%0,%1,%2,%3};"
        : "+f"(c[0]), "+f"(c[1]), "+f"(c[2]), "+f"(c[3])
        : "r"(a[0]), "r"(a[1]), "r"(a[2]), "r"(a[3]), "r"(b[0]), "r"(b[1]));
}

#define GEMM_COMPUTE(Ac, Bc) \
    _Pragma("unroll") \
    for (int kk = 0; kk < 32; kk += 8) { \
        uint32_t af[2][4], bf[8][2]; \
        _Pragma("unroll") \
        for (int mt = 0; mt < 2; mt++) { \
            int rb = (wm*32 + mt*16 + gg)*PITCH + kk + tg; \
            af[mt][0] = (Ac)[rb]; \
            af[mt][1] = (Ac)[rb + 8*PITCH]; \
            af[mt][2] = (Ac)[rb + 4]; \
            af[mt][3] = (Ac)[rb + 8*PITCH + 4]; \
        } \
        _Pragma("unroll") \
        for (int nt = 0; nt < 8; nt++) { \
            int nb = (wn*64 + nt*8 + gg)*PITCH + kk + tg; \
            bf[nt][0] = (Bc)[nb]; \
            bf[nt][1] = (Bc)[nb + 4]; \
        } \
        _Pragma("unroll") \
        for (int mt = 0; mt < 2; mt++) \
            _Pragma("unroll") \
            for (int nt = 0; nt < 8; nt++) \
                mma8(acc[mt][nt], af[mt], bf[nt]); \
    }

// C = A[M,K](row-major) * B[N,K](row-major = B^T); inputs pre-rounded to tf32.
__device__ __forceinline__ void gemm_core(const float* __restrict__ A, int lda,
                                          const float* __restrict__ B, int ldb,
                                          int K, int row0, int col0,
                                          float (*acc)[8][4],
                                          uint32_t* As, uint32_t* Bs) {
    int t = threadIdx.x, lane = t & 31, wid = t >> 5;
    int wm = wid & 3, wn = wid >> 2;
    int gg = lane >> 2, tg = lane & 3;
    int lr[4], lc[4];
#pragma unroll
    for (int i = 0; i < 4; i++) { int lin = t + i*256; lr[i] = lin >> 3; lc[i] = (lin & 7)*4; }
    const float* Ab = A + (size_t)row0*lda;
    const float* Bb = B + (size_t)col0*ldb;
    float4 avr[4], bvr[4];
#pragma unroll
    for (int i = 0; i < 4; i++) {
        avr[i] = *(const float4*)(Ab + (size_t)lr[i]*lda + lc[i]);
        bvr[i] = *(const float4*)(Bb + (size_t)lr[i]*ldb + lc[i]);
    }
    int nsteps = K >> 5;
    for (int s = 0; s < nsteps; s++) {
        uint32_t* Ac = As + (s & 1)*DBUF;
        uint32_t* Bc = Bs + (s & 1)*DBUF;
#pragma unroll
        for (int i = 0; i < 4; i++) {
            *(float4*)(Ac + lr[i]*PITCH + lc[i]) = avr[i];
            *(float4*)(Bc + lr[i]*PITCH + lc[i]) = bvr[i];
        }
        __syncthreads();
        if (s + 1 < nsteps) {
            int k0 = (s + 1)*32;
#pragma unroll
            for (int i = 0; i < 4; i++) {
                avr[i] = *(const float4*)(Ab + (size_t)lr[i]*lda + k0 + lc[i]);
                bvr[i] = *(const float4*)(Bb + (size_t)lr[i]*ldb + k0 + lc[i]);
            }
        }
        GEMM_COMPUTE(Ac, Bc)
    }
    __syncthreads();
}

// C = A[M,K](row-major) * Bsrc[K,N](k-major rows); inputs pre-rounded to tf32.
__device__ __forceinline__ void gemm_coreKB(const float* __restrict__ A, int lda,
                                            const float* __restrict__ Bsrc, int ldb,
                                            int K, int row0, int col0,
                                            float (*acc)[8][4],
                                            uint32_t* As, uint32_t* Bs) {
    int t = threadIdx.x, lane = t & 31, wid = t >> 5;
    int wm = wid & 3, wn = wid >> 2;
    int gg = lane >> 2, tg = lane & 3;
    int lr[4], lc[4], bn[4], bk[4];
#pragma unroll
    for (int i = 0; i < 4; i++) {
        int lin = t + i*256;
        lr[i] = lin >> 3; lc[i] = (lin & 7)*4;
        bn[i] = lin & 127; bk[i] = (lin >> 7)*4;
    }
    const float* Ab = A + (size_t)row0*lda;
    float4 avr[4]; float bvr[4][4];
#pragma unroll
    for (int i = 0; i < 4; i++) {
        avr[i] = *(const float4*)(Ab + (size_t)lr[i]*lda + lc[i]);
        const float* bp = Bsrc + (size_t)bk[i]*ldb + col0 + bn[i];
#pragma unroll
        for (int j = 0; j < 4; j++) bvr[i][j] = bp[(size_t)j*ldb];
    }
    int nsteps = K >> 5;
    for (int s = 0; s < nsteps; s++) {
        uint32_t* Ac = As + (s & 1)*DBUF;
        uint32_t* Bc = Bs + (s & 1)*DBUF;
#pragma unroll
        for (int i = 0; i < 4; i++) {
            *(float4*)(Ac + lr[i]*PITCH + lc[i]) = avr[i];
            *(float4*)(Bc + bn[i]*PITCH + bk[i]) =
                make_float4(bvr[i][0], bvr[i][1], bvr[i][2], bvr[i][3]);
        }
        __syncthreads();
        if (s + 1 < nsteps) {
            int k0 = (s + 1)*32;
#pragma unroll
            for (int i = 0; i < 4; i++) {
                avr[i] = *(const float4*)(Ab + (size_t)lr[i]*lda + k0 + lc[i]);
                const float* bp = Bsrc + (size_t)(k0 + bk[i])*ldb + col0 + bn[i];
#pragma unroll
                for (int j = 0; j < 4; j++) bvr[i][j] = bp[(size_t)j*ldb];
            }
        }
        GEMM_COMPUTE(Ac, Bc)
    }
    __syncthreads();
}

#define EPI_VARS int t_=threadIdx.x, lane_=t_&31, wid_=t_>>5; \
    int wm_=wid_&3, wn_=wid_>>2, eg_=lane_>>2, etg_=lane_&3; (void)t_; (void)lane_;
#define MMA_SMEM extern __shared__ uint32_t smem_u[]; \
    uint32_t* As = smem_u; uint32_t* Bs = smem_u + 2*DBUF;

// ---------------- 0. round weights to tf32 (original layouts) ----------------
__global__ void __launch_bounds__(256) prep_round(const float* __restrict__ w1,
                                                  const float* __restrict__ w2,
                                                  const float* __restrict__ wv,
                                                  const float* __restrict__ scw) {
    int t = blockIdx.x*256 + threadIdx.x;
    if (t < 65536) g_w1R[t] = rndtf(w1[t]);
    else if (t < 98304) g_w2R[t-65536] = rndtf(w2[t-65536]);
    else if (t < 114688) g_wvR[t-98304] = rndtf(wv[t-98304]);
    else if (t < 122880) g_scwR[t-114688] = rndtf(scw[t-114688]);
}

// ---------------- 1. FPS ----------------
__global__ void __launch_bounds__(512) fps_kernel(const float* __restrict__ xyz,
                                                  const int* __restrict__ start,
                                                  float* __restrict__ centers) {
    __shared__ float sx[NNP], sy[NNP], sz[NNP];
    __shared__ float rv[16]; __shared__ int ri[16]; __shared__ int sfar;
    int b = blockIdx.x, tid = threadIdx.x;
    for (int i = tid; i < NNP; i += 512) {
        const float* p = xyz + ((size_t)b*NNP + i)*3;
        sx[i] = p[0]; sy[i] = p[1]; sz[i] = p[2];
    }
    float dist[8];
#pragma unroll
    for (int i = 0; i < 8; i++) dist[i] = 1e10f;
    __syncthreads();
    int far = start[b];
    for (int t = 0; t < SSP; t++) {
        float cx = sx[far], cy = sy[far], cz = sz[far];
        if (tid == 0) {
            float* o = centers + ((size_t)b*SSP + t)*3;
            o[0] = cx; o[1] = cy; o[2] = cz;
        }
        float bv = -1.0f; int bi = 0;
#pragma unroll
        for (int i = 0; i < 8; i++) {
            int p = tid + i*512;
            float dx = sx[p]-cx, dy = sy[p]-cy, dz = sz[p]-cz;
            float d = fminf(dist[i], dx*dx + dy*dy + dz*dz);
            dist[i] = d;
            if (d > bv) { bv = d; bi = p; }
        }
#pragma unroll
        for (int off = 16; off > 0; off >>= 1) {
            float ov = __shfl_down_sync(0xffffffffu, bv, off);
            int   oi = __shfl_down_sync(0xffffffffu, bi, off);
            if (ov > bv || (ov == bv && oi < bi)) { bv = ov; bi = oi; }
        }
        if ((tid & 31) == 0) { rv[tid>>5] = bv; ri[tid>>5] = bi; }
        __syncthreads();
        if (tid < 32) {
            float gv = (tid < 16) ? rv[tid] : -3.0f;
            int   gi = (tid < 16) ? ri[tid] : 0x7fffffff;
#pragma unroll
            for (int off = 8; off > 0; off >>= 1) {
                float ov = __shfl_down_sync(0xffffffffu, gv, off);
                int   oi = __shfl_down_sync(0xffffffffu, gi, off);
                if (ov > gv || (ov == gv && oi < gi)) { gv = ov; gi = oi; }
            }
            if (tid == 0) sfar = gi;
        }
        __syncthreads();
        far = sfar;
    }
}

// ---------------- 2. KNN ----------------
__global__ void __launch_bounds__(128) knn_kernel(const float* __restrict__ xyz,
                                                  const float* __restrict__ centers) {
    __shared__ float sd2[KKN*128];
    __shared__ float swv[4]; __shared__ int swi[4];
    int s = blockIdx.x, b = blockIdx.y, tid = threadIdx.x;
    const float* c = centers + ((size_t)b*SSP + s)*3;
    float cx = c[0], cy = c[1], cz = c[2];
    float cn2 = cx*cx + cy*cy + cz*cz;
    float lv = FLT_MAX; int li = 0x7fffffff; int lslot = 0;
#pragma unroll
    for (int i = 0; i < KKN; i++) {
        int p = tid + i*128;
        const float* pp = xyz + ((size_t)b*NNP + p)*3;
        float px = pp[0], py = pp[1], pz = pp[2];
        float d2 = cn2 + (px*px + py*py + pz*pz) - 2.0f*(cx*px + cy*py + cz*pz);
        sd2[i*128 + tid] = d2;
        if (d2 < lv) { lv = d2; li = p; lslot = i; }
    }
    int lane = tid & 31, warp = tid >> 5;
    int obase = (b*SSP + s)*KKN;
    for (int r = 0; r < KKN; r++) {
        float bv = lv; int bi = li;
#pragma unroll
        for (int off = 16; off > 0; off >>= 1) {
            float ov = __shfl_xor_sync(0xffffffffu, bv, off);
            int   oi = __shfl_xor_sync(0xffffffffu, bi, off);
            if (ov < bv || (ov == bv && oi < bi)) { bv = ov; bi = oi; }
        }
        if (lane == 0) { swv[warp] = bv; swi[warp] = bi; }
        __syncthreads();
        float gv = swv[0]; int gi = swi[0];
#pragma unroll
        for (int w = 1; w < 4; w++)
            if (swv[w] < gv || (swv[w] == gv && swi[w] < gi)) { gv = swv[w]; gi = swi[w]; }
        if (tid == 0) { g_knn[obase + r] = gi; g_knnd[obase + r] = gv; }
        if (gi == li) {
            sd2[lslot*128 + tid] = FLT_MAX;
            lv = FLT_MAX; li = 0x7fffffff; lslot = 0;
#pragma unroll
            for (int i = 0; i < KKN; i++) {
                float d = sd2[i*128 + tid];
                if (d < lv) { lv = d; li = tid + i*128; lslot = i; }
            }
        }
        __syncthreads();
    }
}

// ---------------- 3. group + pos-embed MLP (writes tf32-rounded x) ----------------
__global__ void __launch_bounds__(256) grouppos_kernel(
    const float* __restrict__ xyz, const float* __restrict__ points,
    const float* __restrict__ centers,
    const float* __restrict__ w1, const float* __restrict__ b1, const float* __restrict__ bn1,
    const float* __restrict__ w2, const float* __restrict__ b2, const float* __restrict__ bn2) {
    __shared__ float sw1[320], sw2[2048];
    __shared__ float sA1[32], sC1[32], sA2[64], sC2[64];
    int tid = threadIdx.x;
    for (int i = tid; i < 320; i += 256) sw1[i] = w1[i];
    for (int i = tid; i < 2048; i += 256) sw2[i] = w2[i];
    if (tid < 32) {
        float a = bn1[tid] * rsqrtf(bn1[96+tid] + EPSV);
        sA1[tid] = a; sC1[tid] = a*(b1[tid]-bn1[64+tid]) + bn1[32+tid];
    }
    if (tid < 64) {
        float a = bn2[tid] * rsqrtf(bn2[192+tid] + EPSV);
        sA2[tid] = a; sC2[tid] = a*(b2[tid]-bn2[128+tid]) + bn2[64+tid];
    }
    __syncthreads();
    int gid = blockIdx.x*256 + tid;
    int b = gid >> 14;
    int idx = g_knn[gid];
    float dd = g_knnd[gid];
    const float* c = centers + (size_t)(gid >> 5)*3;
    float cx = c[0], cy = c[1], cz = c[2];
    const float* pp = xyz + ((size_t)b*NNP + idx)*3;
    float px = pp[0], py = pp[1], pz = pp[2];
    float f[10] = {cx, cy, cz, px, py, pz, px-cx, py-cy, pz-cz, dd};
    float h[32];
#pragma unroll
    for (int cc = 0; cc < 32; cc++) {
        float acc = 0.f;
#pragma unroll
        for (int i = 0; i < 10; i++) acc += f[i]*sw1[i*32+cc];
        h[cc] = fmaxf(acc*sA1[cc] + sC1[cc], 0.f);
    }
    float* xo = g_x + (size_t)gid*128;
#pragma unroll
    for (int cc = 0; cc < 64; cc++) {
        float acc = 0.f;
#pragma unroll
        for (int i = 0; i < 32; i++) acc += h[i]*sw2[i*64+cc];
        xo[cc] = rndtf(fmaxf(acc*sA2[cc] + sC2[cc], 0.f));
    }
    const float* pr = points + ((size_t)b*NNP + idx)*64;
#pragma unroll
    for (int j = 0; j < 64; j += 4) {
        float4 v = *(const float4*)(pr + j);
        v.x = rndtf(v.x); v.y = rndtf(v.y); v.z = rndtf(v.z); v.w = rndtf(v.w);
        *(float4*)(xo + 64 + j) = v;
    }
}

// ---------------- 4a. V = x@wv + bv (tf32 MMA) ----------------
__global__ void __launch_bounds__(256) vproj_mma(const float* __restrict__ bv) {
    MMA_SMEM
    int row0 = blockIdx.x*128;
    float acc[2][8][4] = {};
    gemm_coreKB(g_x, 128, g_wvR, 128, 128, row0, 0, acc, As, Bs);
    EPI_VARS
#pragma unroll
    for (int mt = 0; mt < 2; mt++)
#pragma unroll
        for (int nt = 0; nt < 8; nt++) {
            int r = row0 + wm_*32 + mt*16 + eg_;
            int c = wn_*64 + nt*8 + 2*etg_;
            float b0 = bv[c], b1 = bv[c+1];
            *(float2*)(g_v + (size_t)r*128 + c)     = make_float2(acc[mt][nt][0]+b0, acc[mt][nt][1]+b1);
            *(float2*)(g_v + (size_t)(r+8)*128 + c) = make_float2(acc[mt][nt][2]+b0, acc[mt][nt][3]+b1);
        }
}

// ---------------- 4b. neighbor self-attention -> dsa[:,0:128] ----------------
__global__ void __launch_bounds__(128) nsa_kernel(
    const float* __restrict__ wq, const float* __restrict__ bq,
    const float* __restrict__ wk, const float* __restrict__ bk,
    const float* __restrict__ gam) {
    __shared__ float xs[32][128];
    __shared__ float swq[128][16], swk[128][16];
    __shared__ float qs[32][16], ks2[32][16];
    __shared__ float at[32][32];
    int g = blockIdx.x, t = threadIdx.x;
    const float* xg = g_x + (size_t)g*4096;
#pragma unroll
    for (int i = 0; i < 8; i++)
        *(float4*)(&xs[0][0] + t*4 + i*512) = *(const float4*)(xg + t*4 + i*512);
#pragma unroll
    for (int i = 0; i < 4; i++) {
        *(float4*)(&swq[0][0] + t*4 + i*512) = *(const float4*)(wq + t*4 + i*512);
        *(float4*)(&swk[0][0] + t*4 + i*512) = *(const float4*)(wk + t*4 + i*512);
    }
    __syncthreads();
    {
        int r = t >> 2, c0 = (t & 3)*4;
        float4 aq = *(const float4*)(bq + c0);
        float4 ak = *(const float4*)(bk + c0);
        for (int i = 0; i < 128; i++) {
            float xv = xs[r][i];
            float4 wq4 = *(float4*)&swq[i][c0];
            float4 wk4 = *(float4*)&swk[i][c0];
            aq.x += xv*wq4.x; aq.y += xv*wq4.y; aq.z += xv*wq4.z; aq.w += xv*wq4.w;
            ak.x += xv*wk4.x; ak.y += xv*wk4.y; ak.z += xv*wk4.z; ak.w += xv*wk4.w;
        }
        *(float4*)&qs[r][c0] = aq; *(float4*)&ks2[r][c0] = ak;
    }
    __syncthreads();
    {
        int r = t >> 2, j0 = (t & 3)*8;
        float4 q0 = *(float4*)&qs[r][0], q1 = *(float4*)&qs[r][4];
        float4 q2 = *(float4*)&qs[r][8], q3 = *(float4*)&qs[r][12];
        float sc[8];
#pragma unroll
        for (int jj = 0; jj < 8; jj++) {
            int j = j0 + jj;
            float4 k0 = *(float4*)&ks2[j][0], k1 = *(float4*)&ks2[j][4];
            float4 k2 = *(float4*)&ks2[j][8], k3 = *(float4*)&ks2[j][12];
            sc[jj] = q0.x*k0.x + q0.y*k0.y + q0.z*k0.z + q0.w*k0.w
                   + q1.x*k1.x + q1.y*k1.y + q1.z*k1.z + q1.w*k1.w
                   + q2.x*k2.x + q2.y*k2.y + q2.z*k2.z + q2.w*k2.w
                   + q3.x*k3.x + q3.y*k3.y + q3.z*k3.z + q3.w*k3.w;
        }
        float mx = sc[0];
#pragma unroll
        for (int jj = 1; jj < 8; jj++) mx = fmaxf(mx, sc[jj]);
        mx = fmaxf(mx, __shfl_xor_sync(0xffffffffu, mx, 1));
        mx = fmaxf(mx, __shfl_xor_sync(0xffffffffu, mx, 2));
        float sum = 0.f;
#pragma unroll
        for (int jj = 0; jj < 8; jj++) { sc[jj] = expf(sc[jj]-mx); sum += sc[jj]; }
        sum += __shfl_xor_sync(0xffffffffu, sum, 1);
        sum += __shfl_xor_sync(0xffffffffu, sum, 2);
#pragma unroll
        for (int jj = 0; jj < 8; jj++) at[r][j0+jj] = sc[jj]/sum;
    }
    __syncthreads();
    float vreg[32];
#pragma unroll
    for (int k = 0; k < 32; k++)
        vreg[k] = g_v[((size_t)g*32 + k)*128 + t];
    float accn[32];
#pragma unroll
    for (int k = 0; k < 32; k++) accn[k] = 0.f;
    for (int j4 = 0; j4 < 8; j4++) {
        float v0 = vreg[j4*4+0], v1 = vreg[j4*4+1], v2 = vreg[j4*4+2], v3 = vreg[j4*4+3];
#pragma unroll
        for (int k = 0; k < 32; k++) {
            float4 a4 = *(float4*)&at[k][j4*4];
            accn[k] += a4.x*v0 + a4.y*v1 + a4.z*v2 + a4.w*v3;
        }
    }
    float gm = gam[0];
#pragma unroll
    for (int k = 0; k < 32; k++)
        g_dsa[((size_t)g*32 + k)*256 + t] = rndtf(gm*accn[k] + xs[k][t]);
}

// ---------------- 5. GAM G = F F^T (tf32 MMA, symmetric + K-split) ----------------
__global__ void __launch_bounds__(256) gam1_mma() {
    MMA_SMEM
    int bx = blockIdx.x;
    int half = bx / 10, ti = bx % 10;
    int trow = (ti >= 6) ? 3 : (ti >= 3) ? 2 : (ti >= 1) ? 1 : 0;
    int tcol = ti - trow*(trow+1)/2;
    int row0 = trow*128, col0 = tcol*128;
    int b = blockIdx.z;
    const float* F = g_x + (size_t)b*SSP*4096 + half*2048;
    float acc[2][8][4] = {};
    gemm_core(F, 4096, F, 4096, 2048, row0, col0, acc, As, Bs);
    float* Gp = (half ? g_G2 : g_G) + (size_t)b*SSP*SSP;
    bool mir = (row0 != col0);
    EPI_VARS
#pragma unroll
    for (int mt = 0; mt < 2; mt++)
#pragma unroll
        for (int nt = 0; nt < 8; nt++) {
            int r = row0 + wm_*32 + mt*16 + eg_;
            int c = col0 + wn_*64 + nt*8 + 2*etg_;
            float c0 = acc[mt][nt][0], c1 = acc[mt][nt][1];
            float c2 = acc[mt][nt][2], c3 = acc[mt][nt][3];
            *(float2*)(Gp + (size_t)r*SSP + c)     = make_float2(c0, c1);
            *(float2*)(Gp + (size_t)(r+8)*SSP + c) = make_float2(c2, c3);
            if (mir) {
                Gp[(size_t)c*SSP + r]         = c0;
                Gp[(size_t)(c+1)*SSP + r]     = c1;
                Gp[(size_t)c*SSP + r + 8]     = c2;
                Gp[(size_t)(c+1)*SSP + r + 8] = c3;
            }
        }
}

// ---------------- 6. softmax over (G + G2) rows (writes tf32-rounded to g_G) ----------------
__global__ void __launch_bounds__(256) gsoftmax_kernel() {
    __shared__ float red[8];
    int row = blockIdx.x, t = threadIdx.x;
    float* p  = g_G  + (size_t)row*SSP;
    float* p2 = g_G2 + (size_t)row*SSP;
    float a = p[t] + p2[t], b = p[t+256] + p2[t+256];
    float mx = fmaxf(a, b);
#pragma unroll
    for (int off = 16; off > 0; off >>= 1) mx = fmaxf(mx, __shfl_xor_sync(0xffffffffu, mx, off));
    if ((t & 31) == 0) red[t>>5] = mx;
    __syncthreads();
    mx = red[0];
#pragma unroll
    for (int w = 1; w < 8; w++) mx = fmaxf(mx, red[w]);
    float e1 = expf(a-mx), e2 = expf(b-mx);
    float s = e1 + e2;
#pragma unroll
    for (int off = 16; off > 0; off >>= 1) s += __shfl_xor_sync(0xffffffffu, s, off);
    __syncthreads();
    if ((t & 31) == 0) red[t>>5] = s;
    __syncthreads();
    s = red[0];
#pragma unroll
    for (int w = 1; w < 8; w++) s += red[w];
    p[t] = rndtf(e1/s); p[t+256] = rndtf(e2/s);
}

// ---------------- 7. grp = gamma*G@F + x -> dsa[:,128:256] (tf32 MMA) ----------------
__global__ void __launch_bounds__(256) gam2_mma(const float* __restrict__ gam) {
    MMA_SMEM
    int b = blockIdx.z;
    const float* A = g_G + (size_t)b*SSP*SSP;
    const float* F = g_x + (size_t)b*SSP*4096;
    int row0 = blockIdx.y*128, col0 = blockIdx.x*128;
    float acc[2][8][4] = {};
    gemm_coreKB(A, SSP, F, 4096, SSP, row0, col0, acc, As, Bs);
    float gm = gam[0];
    int kidx = blockIdx.x;   // col0 = kidx*128
    EPI_VARS
#pragma unroll
    for (int mt = 0; mt < 2; mt++)
#pragma unroll
        for (int nt = 0; nt < 8; nt++) {
            int r = row0 + wm_*32 + mt*16 + eg_;
            int c = col0 + wn_*64 + nt*8 + 2*etg_;
            int d = c & 127;
            const float* xr1 = g_x + ((size_t)b*SSP + r)*4096 + c;
            const float* xr2 = g_x + ((size_t)b*SSP + r + 8)*4096 + c;
            float* o1 = g_dsa + ((size_t)((b*SSP + r)*KKN) + kidx)*256 + 128 + d;
            float* o2 = g_dsa + ((size_t)((b*SSP + r + 8)*KKN) + kidx)*256 + 128 + d;
            *(float2*)o1 = make_float2(rndtf(gm*acc[mt][nt][0] + xr1[0]),
                                       rndtf(gm*acc[mt][nt][1] + xr1[1]));
            *(float2*)o2 = make_float2(rndtf(gm*acc[mt][nt][2] + xr2[0]),
                                       rndtf(gm*acc[mt][nt][3] + xr2[1]));
        }
}

// ---------------- 8. h = relu(bn1(dsa@w1+b1)) (tf32 MMA) ----------------
__global__ void __launch_bounds__(256) head1_mma(const float* __restrict__ b1,
                                                 const float* __restrict__ bn1) {
    MMA_SMEM
    int row0 = blockIdx.y*128, col0 = blockIdx.x*128;
    float acc[2][8][4] = {};
    gemm_coreKB(g_dsa, 256, g_w1R, 256, 256, row0, col0, acc, As, Bs);
    EPI_VARS
#pragma unroll
    for (int mt = 0; mt < 2; mt++)
#pragma unroll
        for (int nt = 0; nt < 8; nt++) {
            int r = row0 + wm_*32 + mt*16 + eg_;
            int c = col0 + wn_*64 + nt*8 + 2*etg_;
            float a0 = bn1[c]*rsqrtf(bn1[768+c] + EPSV);
            float c0v = a0*(b1[c]-bn1[512+c]) + bn1[256+c];
            float a1 = bn1[c+1]*rsqrtf(bn1[768+c+1] + EPSV);
            float c1v = a1*(b1[c+1]-bn1[512+c+1]) + bn1[256+c+1];
            *(float2*)(g_h + (size_t)r*256 + c) = make_float2(
                rndtf(fmaxf(acc[mt][nt][0]*a0 + c0v, 0.f)),
                rndtf(fmaxf(acc[mt][nt][1]*a1 + c1v, 0.f)));
            *(float2*)(g_h + (size_t)(r+8)*256 + c) = make_float2(
                rndtf(fmaxf(acc[mt][nt][2]*a0 + c0v, 0.f)),
                rndtf(fmaxf(acc[mt][nt][3]*a1 + c1v, 0.f)));
        }
}

// ---------------- 9. scv = relu(bn(pts@scw+scb)) (tf32 MMA) ----------------
__global__ void __launch_bounds__(256) sc_mma(const float* __restrict__ scb,
                                              const float* __restrict__ scbn) {
    MMA_SMEM
    int row0 = blockIdx.x*128;
    float acc[2][8][4] = {};
    gemm_coreKB(g_x + 64, 128, g_scwR, 128, 64, row0, 0, acc, As, Bs);
    EPI_VARS
#pragma unroll
    for (int mt = 0; mt < 2; mt++)
#pragma unroll
        for (int nt = 0; nt < 8; nt++) {
            int r = row0 + wm_*32 + mt*16 + eg_;
            int c = wn_*64 + nt*8 + 2*etg_;
            float a0 = scbn[c]*rsqrtf(scbn[384+c] + EPSV);
            float c0v = a0*(scb[c]-scbn[256+c]) + scbn[128+c];
            float a1 = scbn[c+1]*rsqrtf(scbn[384+c+1] + EPSV);
            float c1v = a1*(scb[c+1]-scbn[256+c+1]) + scbn[128+c+1];
            *(float2*)(g_scv + (size_t)r*128 + c) = make_float2(
                fmaxf(acc[mt][nt][0]*a0 + c0v, 0.f), fmaxf(acc[mt][nt][1]*a1 + c1v, 0.f));
            *(float2*)(g_scv + (size_t)(r+8)*128 + c) = make_float2(
                fmaxf(acc[mt][nt][2]*a0 + c0v, 0.f), fmaxf(acc[mt][nt][3]*a1 + c1v, 0.f));
        }
}

// ---------------- 10. fused: bn2(h@w2+b2)+scv, relu, max over K -> out ----------------
__global__ void __launch_bounds__(256) head2max_mma(const float* __restrict__ b2,
                                                    const float* __restrict__ bn2,
                                                    float* __restrict__ outp) {
    MMA_SMEM
    int row0 = blockIdx.x*128;
    float acc[2][8][4] = {};
    gemm_coreKB(g_h, 256, g_w2R, 128, 256, row0, 0, acc, As, Bs);
    EPI_VARS
    float tmax[8][2];
#pragma unroll
    for (int nt = 0; nt < 8; nt++) {
        int c = wn_*64 + nt*8 + 2*etg_;
        float a0 = bn2[c]*rsqrtf(bn2[384+c] + EPSV);
        float c0v = a0*(b2[c]-bn2[256+c]) + bn2[128+c];
        float a1 = bn2[c+1]*rsqrtf(bn2[384+c+1] + EPSV);
        float c1v = a1*(b2[c+1]-bn2[256+c+1]) + bn2[128+c+1];
        float m0 = -FLT_MAX, m1 = -FLT_MAX;
#pragma unroll
        for (int mt = 0; mt < 2; mt++) {
            int r = row0 + wm_*32 + mt*16 + eg_;
            const float* s1 = g_scv + (size_t)r*128 + c;
            const float* s2 = g_scv + (size_t)(r+8)*128 + c;
            m0 = fmaxf(m0, fmaxf(acc[mt][nt][0]*a0 + c0v + s1[0], 0.f));
            m1 = fmaxf(m1, fmaxf(acc[mt][nt][1]*a1 + c1v + s1[1], 0.f));
            m0 = fmaxf(m0, fmaxf(acc[mt][nt][2]*a0 + c0v + s2[0], 0.f));
            m1 = fmaxf(m1, fmaxf(acc[mt][nt][3]*a1 + c1v + s2[1], 0.f));
        }
        tmax[nt][0] = m0; tmax[nt][1] = m1;
    }
#pragma unroll
    for (int off = 4; off <= 16; off <<= 1)
#pragma unroll
        for (int nt = 0; nt < 8; nt++) {
            tmax[nt][0] = fmaxf(tmax[nt][0], __shfl_xor_sync(0xffffffffu, tmax[nt][0], off));
            tmax[nt][1] = fmaxf(tmax[nt][1], __shfl_xor_sync(0xffffffffu, tmax[nt][1], off));
        }
    if (eg_ == 0) {
        int gq = blockIdx.x*4 + wm_;
#pragma unroll
        for (int nt = 0; nt < 8; nt++) {
            int c = wn_*64 + nt*8 + 2*etg_;
            outp[12288 + (size_t)gq*128 + c]     = tmax[nt][0];
            outp[12288 + (size_t)gq*128 + c + 1] = tmax[nt][1];
        }
    }
}

extern "C" void kernel_launch(void* const* d_in, const int* in_sizes, int n_in,
                              void* d_out, int out_size) {
    const float* xyz     = (const float*)d_in[0];
    const float* points  = (const float*)d_in[1];
    const int*   fstart  = (const int*)d_in[2];
    const float* pos_w1  = (const float*)d_in[3];
    const float* pos_b1  = (const float*)d_in[4];
    const float* pos_bn1 = (const float*)d_in[5];
    const float* pos_w2  = (const float*)d_in[6];
    const float* pos_b2  = (const float*)d_in[7];
    const float* pos_bn2 = (const float*)d_in[8];
    const float* nsa_wq  = (const float*)d_in[9];
    const float* nsa_bq  = (const float*)d_in[10];
    const float* nsa_wk  = (const float*)d_in[11];
    const float* nsa_bk  = (const float*)d_in[12];
    const float* nsa_wv  = (const float*)d_in[13];
    const float* nsa_bv  = (const float*)d_in[14];
    const float* nsa_g   = (const float*)d_in[15];
    const float* gam_g   = (const float*)d_in[16];
    const float* cat_w1  = (const float*)d_in[17];
    const float* cat_b1  = (const float*)d_in[18];
    const float* cat_bn1 = (const float*)d_in[19];
    const float* cat_w2  = (const float*)d_in[20];
    const float* cat_b2  = (const float*)d_in[21];
    const float* cat_bn2 = (const float*)d_in[22];
    const float* sc_w    = (const float*)d_in[23];
    const float* sc_b    = (const float*)d_in[24];
    const float* sc_bn   = (const float*)d_in[25];
    float* outp = (float*)d_out;

    // One-time setup on the first (correctness) call — BEFORE graph capture.
    // Streams/events persist for the process; the captured work is identical
    // on every call (deterministic), and no create/destroy happens during capture.
    static cudaStream_t sA = nullptr, sB = nullptr;
    static cudaEvent_t eGrp = nullptr, eA = nullptr, eB = nullptr;
    if (sA == nullptr) {
        cudaStreamCreateWithFlags(&sA, cudaStreamNonBlocking);
        cudaStreamCreateWithFlags(&sB, cudaStreamNonBlocking);
        cudaEventCreateWithFlags(&eGrp, cudaEventDisableTiming);
        cudaEventCreateWithFlags(&eA,   cudaEventDisableTiming);
        cudaEventCreateWithFlags(&eB,   cudaEventDisableTiming);
        cudaFuncSetAttribute(vproj_mma,    cudaFuncAttributeMaxDynamicSharedMemorySize, DYNSM);
        cudaFuncSetAttribute(gam1_mma,     cudaFuncAttributeMaxDynamicSharedMemorySize, DYNSM);
        cudaFuncSetAttribute(gam2_mma,     cudaFuncAttributeMaxDynamicSharedMemorySize, DYNSM);
        cudaFuncSetAttribute(head1_mma,    cudaFuncAttributeMaxDynamicSharedMemorySize, DYNSM);
        cudaFuncSetAttribute(sc_mma,       cudaFuncAttributeMaxDynamicSharedMemorySize, DYNSM);
        cudaFuncSetAttribute(head2max_mma, cudaFuncAttributeMaxDynamicSharedMemorySize, DYNSM);
    }

    // trunk: prep -> fps -> knn -> grouppos
    prep_round<<<480, 256>>>(cat_w1, cat_w2, nsa_wv, sc_w);
    fps_kernel<<<BB, 512>>>(xyz, fstart, outp);
    knn_kernel<<<dim3(SSP, BB), 128>>>(xyz, outp);
    grouppos_kernel<<<512, 256>>>(xyz, points, outp, pos_w1, pos_b1, pos_bn1,
                                  pos_w2, pos_b2, pos_bn2);
    cudaEventRecord(eGrp, 0);

    // branch A: vproj -> nsa (writes dsa[:,0:128])
    cudaStreamWaitEvent(sA, eGrp, 0);
    vproj_mma<<<1024, 256, DYNSM, sA>>>(nsa_bv);
    nsa_kernel<<<BB*SSP, 128, 0, sA>>>(nsa_wq, nsa_bq, nsa_wk, nsa_bk, nsa_g);
    cudaEventRecord(eA, sA);

    // branch B: shortcut GEMM
    cudaStreamWaitEvent(sB, eGrp, 0);
    sc_mma<<<1024, 256, DYNSM, sB>>>(sc_b, sc_bn);
    cudaEventRecord(eB, sB);

    // trunk continues: GAM chain (writes dsa[:,128:256])
    gam1_mma<<<dim3(20, 1, BB), 256, DYNSM>>>();
    gsoftmax_kernel<<<BB*SSP, 256>>>();
    gam2_mma<<<dim3(32, 4, BB), 256, DYNSM>>>(gam_g);

    // join A -> head1; join B -> head2
    cudaStreamWaitEvent(0, eA, 0);
    head1_mma<<<dim3(2, 1024), 256, DYNSM>>>(cat_b1, cat_bn1);
    cudaStreamWaitEvent(0, eB, 0);
    head2max_mma<<<1024, 256, DYNSM>>>(cat_b2, cat_bn2, outp);
}